// round 1
// baseline (speedup 1.0000x reference)
#include <cuda_runtime.h>
#include <cuda_bf16.h>
#include <math.h>

// ---------------------------------------------------------------------------
// Problem constants
// ---------------------------------------------------------------------------
#define ND   20000
#define NF   50000
#define EE   400000
#define HIDN 128
#define NH   8
#define HDIM 16
#define NLYR 2
#define OUTC 32

// ---------------------------------------------------------------------------
// Scratch pool (static device memory; no allocations anywhere)
// ---------------------------------------------------------------------------
constexpr size_t ND128 = (size_t)ND * HIDN;
constexpr size_t NF128 = (size_t)NF * HIDN;

constexpr size_t OFF_XD   = 0;
constexpr size_t OFF_XF   = OFF_XD  + ND128;
constexpr size_t OFF_KD   = OFF_XF  + NF128;
constexpr size_t OFF_QD   = OFF_KD  + ND128;
constexpr size_t OFF_VD   = OFF_QD  + ND128;
constexpr size_t OFF_KF   = OFF_VD  + ND128;
constexpr size_t OFF_QF   = OFF_KF  + NF128;
constexpr size_t OFF_VF   = OFF_QF  + NF128;
constexpr size_t OFF_KTD  = OFF_VF  + NF128;
constexpr size_t OFF_VTD  = OFF_KTD + ND128;
constexpr size_t OFF_KTF  = OFF_VTD + ND128;
constexpr size_t OFF_VTF  = OFF_KTF + NF128;
constexpr size_t OFF_AGGD = OFF_VTF + NF128;
constexpr size_t OFF_AGGF = OFF_AGGD + ND128;
constexpr size_t OFF_TMPD = OFF_AGGF + NF128;
constexpr size_t OFF_TMPF = OFF_TMPD + ND128;
constexpr size_t OFF_LOG  = OFF_TMPF + NF128;            // E*H edge scratch
constexpr size_t OFF_MX   = OFF_LOG + (size_t)EE * NH;   // NF*H (covers ND too)
constexpr size_t OFF_SM   = OFF_MX  + (size_t)NF * NH;
constexpr size_t POOL_SZ  = OFF_SM  + (size_t)NF * NH;

__device__ __align__(256) float g_pool[POOL_SZ];

// ---------------------------------------------------------------------------
// Helpers
// ---------------------------------------------------------------------------
__device__ __forceinline__ unsigned fenc(float f) {
    unsigned u = __float_as_uint(f);
    return (u & 0x80000000u) ? ~u : (u | 0x80000000u);
}
__device__ __forceinline__ float fdec(unsigned u) {
    return __uint_as_float((u & 0x80000000u) ? (u ^ 0x80000000u) : ~u);
}

// ---------------------------------------------------------------------------
// GEMM: C[N,128] = act(A[N,128] @ W[128,128] + bias)
// block = 256 thr, tile 64 rows x 128 cols, BK = 16, 8x4 register tile
// ---------------------------------------------------------------------------
template <int ACT>  // 0 = none, 1 = relu
__global__ void gemm128(const float* __restrict__ A, const float* __restrict__ W,
                        const float* __restrict__ bias, float* __restrict__ C, int N) {
    __shared__ float As[16][68];   // [k][row], padded vs bank conflicts
    __shared__ float Ws[16][128];  // [k][col]

    const int row0 = blockIdx.x * 64;
    const int tid  = threadIdx.x;
    const int tx   = tid & 31;   // col group: cols tx*4 .. tx*4+3
    const int ty   = tid >> 5;   // row group: rows ty*8 .. ty*8+7

    float acc[8][4];
#pragma unroll
    for (int r = 0; r < 8; r++)
#pragma unroll
        for (int c = 0; c < 4; c++) acc[r][c] = 0.f;

    for (int k0 = 0; k0 < 128; k0 += 16) {
        // A tile (64 rows x 16 k), stored transposed
        for (int i = tid; i < 64 * 16; i += 256) {
            int r = i >> 4, kk = i & 15;
            int gr = row0 + r;
            As[kk][r] = (gr < N) ? A[(size_t)gr * 128 + k0 + kk] : 0.f;
        }
        // W tile (16 k x 128 cols)
        for (int i = tid; i < 16 * 128; i += 256) {
            int kk = i >> 7, c = i & 127;
            Ws[kk][c] = W[(k0 + kk) * 128 + c];
        }
        __syncthreads();
#pragma unroll
        for (int kk = 0; kk < 16; kk++) {
            float a[8], w[4];
#pragma unroll
            for (int r = 0; r < 8; r++) a[r] = As[kk][ty * 8 + r];
#pragma unroll
            for (int c = 0; c < 4; c++) w[c] = Ws[kk][tx * 4 + c];
#pragma unroll
            for (int r = 0; r < 8; r++)
#pragma unroll
                for (int c = 0; c < 4; c++) acc[r][c] += a[r] * w[c];
        }
        __syncthreads();
    }

#pragma unroll
    for (int r = 0; r < 8; r++) {
        int gr = row0 + ty * 8 + r;
        if (gr < N) {
#pragma unroll
            for (int c = 0; c < 4; c++) {
                float v = acc[r][c] + bias[tx * 4 + c];
                if (ACT == 1) v = fmaxf(v, 0.f);
                C[(size_t)gr * 128 + tx * 4 + c] = v;
            }
        }
    }
}

// ---------------------------------------------------------------------------
// Relation transform: kt[n,h,:] = k[n,h,:] @ a[h]  (D x D), same for v/m
// one thread per (n, h, e) output element
// ---------------------------------------------------------------------------
__global__ void rel_transform(const float* __restrict__ k, const float* __restrict__ v,
                              const float* __restrict__ a, const float* __restrict__ m,
                              float* __restrict__ kt, float* __restrict__ vt, int N) {
    size_t idx = (size_t)blockIdx.x * blockDim.x + threadIdx.x;
    if (idx >= (size_t)N * HIDN) return;
    int he = (int)(idx & 127);
    int h = he >> 4, e = he & 15;
    size_t nb = idx & ~(size_t)127;  // n*128
    const float* krow = k + nb + h * 16;
    const float* vrow = v + nb + h * 16;
    const float* arow = a + h * 256 + e;  // a[h][d][e], d-stride 16
    const float* mrow = m + h * 256 + e;
    float sk = 0.f, sv = 0.f;
#pragma unroll
    for (int d = 0; d < 16; d++) {
        sk += krow[d] * arow[d * 16];
        sv += vrow[d] * mrow[d * 16];
    }
    kt[idx] = sk;
    vt[idx] = sv;
}

// ---------------------------------------------------------------------------
// Edge pass 1: logits + segment max (thread per (edge, head))
// ---------------------------------------------------------------------------
__global__ void edge_logit(const int* __restrict__ src, const int* __restrict__ dst,
                           const float* __restrict__ q, const float* __restrict__ kt,
                           const float* __restrict__ p, float* __restrict__ logit,
                           unsigned* __restrict__ mx) {
    size_t idx = (size_t)blockIdx.x * blockDim.x + threadIdx.x;
    if (idx >= (size_t)EE * NH) return;
    int e = (int)(idx >> 3), h = (int)(idx & 7);
    int s = src[e], d = dst[e];
    const float4* qr = (const float4*)(q + (size_t)d * 128 + h * 16);
    const float4* kr = (const float4*)(kt + (size_t)s * 128 + h * 16);
    float sum = 0.f;
#pragma unroll
    for (int i = 0; i < 4; i++) {
        float4 aa = qr[i], bb = kr[i];
        sum += aa.x * bb.x + aa.y * bb.y + aa.z * bb.z + aa.w * bb.w;
    }
    float lg = sum * p[h] * 0.25f;  // p_rel / sqrt(D), D=16
    logit[idx] = lg;
    atomicMax(&mx[d * NH + h], fenc(lg));
}

// ---------------------------------------------------------------------------
// Edge pass 2: exp(logit - max), segment sum (in-place over logit buffer)
// ---------------------------------------------------------------------------
__global__ void edge_exp(const int* __restrict__ dst, float* __restrict__ logit,
                         const unsigned* __restrict__ mx, float* __restrict__ sm) {
    size_t idx = (size_t)blockIdx.x * blockDim.x + threadIdx.x;
    if (idx >= (size_t)EE * NH) return;
    int e = (int)(idx >> 3), h = (int)(idx & 7);
    int d = dst[e];
    float m = fdec(mx[d * NH + h]);
    float ex = __expf(logit[idx] - m);
    logit[idx] = ex;
    atomicAdd(&sm[d * NH + h], ex);
}

// ---------------------------------------------------------------------------
// Edge pass 3: alpha-weighted scatter of vt into agg (vectorized red.global)
// ---------------------------------------------------------------------------
__global__ void edge_agg(const int* __restrict__ src, const int* __restrict__ dst,
                         const float* __restrict__ ex, const float* __restrict__ sm,
                         const float* __restrict__ vt, float* __restrict__ agg) {
    size_t idx = (size_t)blockIdx.x * blockDim.x + threadIdx.x;
    if (idx >= (size_t)EE * NH) return;
    int e = (int)(idx >> 3), h = (int)(idx & 7);
    int s = src[e], d = dst[e];
    float alpha = ex[idx] / (sm[d * NH + h] + 1e-16f);
    const float4* vr = (const float4*)(vt + (size_t)s * 128 + h * 16);
    float* out = agg + (size_t)d * 128 + h * 16;
#pragma unroll
    for (int i = 0; i < 4; i++) {
        float4 vv = vr[i];
        asm volatile("red.global.add.v4.f32 [%0], {%1,%2,%3,%4};"
                     :: "l"(out + i * 4),
                        "f"(vv.x * alpha), "f"(vv.y * alpha),
                        "f"(vv.z * alpha), "f"(vv.w * alpha)
                     : "memory");
    }
}

// ---------------------------------------------------------------------------
// Exact GELU in place
// ---------------------------------------------------------------------------
__global__ void gelu_ip(float* __restrict__ x, size_t n) {
    size_t idx = (size_t)blockIdx.x * blockDim.x + threadIdx.x;
    if (idx >= n) return;
    float v = x[idx];
    x[idx] = 0.5f * v * (1.0f + erff(v * 0.70710678118654752440f));
}

// ---------------------------------------------------------------------------
// Skip-gate + residual + LayerNorm.  One block (128 thr) per node, in-place x.
// ---------------------------------------------------------------------------
__global__ void post_ln(const float* __restrict__ o, float* __restrict__ x,
                        const float* __restrict__ skip_lt,
                        const float* __restrict__ g, const float* __restrict__ b,
                        int N) {
    int n = blockIdx.x;
    if (n >= N) return;
    int t = threadIdx.x;
    float sk = 1.f / (1.f + __expf(-skip_lt[0]));
    size_t base = (size_t)n * 128 + t;
    float xv = x[base];
    float ov = sk * o[base] + (1.f - sk) * xv;
    float y = xv + ov;

    __shared__ float red[4];
    float s = y;
#pragma unroll
    for (int off = 16; off; off >>= 1) s += __shfl_xor_sync(0xffffffff, s, off);
    if ((t & 31) == 0) red[t >> 5] = s;
    __syncthreads();
    float mean = (red[0] + red[1] + red[2] + red[3]) * (1.f / 128.f);
    __syncthreads();

    float dy = y - mean;
    float s2 = dy * dy;
#pragma unroll
    for (int off = 16; off; off >>= 1) s2 += __shfl_xor_sync(0xffffffff, s2, off);
    if ((t & 31) == 0) red[t >> 5] = s2;
    __syncthreads();
    float var = (red[0] + red[1] + red[2] + red[3]) * (1.f / 128.f);

    x[base] = dy * rsqrtf(var + 1e-5f) * g[t] + b[t];
}

// ---------------------------------------------------------------------------
// Output head: out[ND,32] = x[ND,128] @ W[128,32] + b
// ---------------------------------------------------------------------------
__global__ void out_gemm(const float* __restrict__ x, const float* __restrict__ W,
                         const float* __restrict__ b, float* __restrict__ out) {
    size_t idx = (size_t)blockIdx.x * blockDim.x + threadIdx.x;
    if (idx >= (size_t)ND * OUTC) return;
    int n = (int)(idx >> 5), c = (int)(idx & 31);
    const float* xr = x + (size_t)n * 128;
    float s = b[c];
#pragma unroll 8
    for (int k = 0; k < 128; k++) s += xr[k] * W[k * OUTC + c];
    out[idx] = s;
}

// ---------------------------------------------------------------------------
// Host orchestration
// ---------------------------------------------------------------------------
static inline int cdiv(long long a, long long b) { return (int)((a + b - 1) / b); }

extern "C" void kernel_launch(void* const* d_in, const int* in_sizes, int n_in,
                              void* d_out, int out_size) {
    (void)in_sizes; (void)n_in; (void)out_size;

    const float* x_device = (const float*)d_in[0];
    const float* x_feature = (const float*)d_in[1];
    const int* e_df_src = (const int*)d_in[2];
    const int* e_df_dst = (const int*)d_in[3];
    const int* e_fd_src = (const int*)d_in[4];
    const int* e_fd_dst = (const int*)d_in[5];
    const float* W_dev_in = (const float*)d_in[6];
    const float* b_dev_in = (const float*)d_in[7];
    const float* W_feat_in = (const float*)d_in[8];
    const float* b_feat_in = (const float*)d_in[9];
    const float* Wk = (const float*)d_in[10];
    const float* bk = (const float*)d_in[11];
    const float* Wq = (const float*)d_in[12];
    const float* bq = (const float*)d_in[13];
    const float* Wv = (const float*)d_in[14];
    const float* bv = (const float*)d_in[15];
    const float* a_rel = (const float*)d_in[16];
    const float* m_rel = (const float*)d_in[17];
    const float* p_rel = (const float*)d_in[18];
    const float* Wa = (const float*)d_in[19];
    const float* ba = (const float*)d_in[20];
    const float* skip = (const float*)d_in[21];
    const float* ln_g = (const float*)d_in[22];
    const float* ln_b = (const float*)d_in[23];
    const float* W_out = (const float*)d_in[24];
    const float* b_out = (const float*)d_in[25];
    float* out = (float*)d_out;

    float* pool = nullptr;
    cudaGetSymbolAddress((void**)&pool, g_pool);

    float* xd = pool + OFF_XD;  float* xf = pool + OFF_XF;
    float* kd = pool + OFF_KD;  float* qd = pool + OFF_QD;  float* vd = pool + OFF_VD;
    float* kf = pool + OFF_KF;  float* qf = pool + OFF_QF;  float* vf = pool + OFF_VF;
    float* ktd = pool + OFF_KTD; float* vtd = pool + OFF_VTD;
    float* ktf = pool + OFF_KTF; float* vtf = pool + OFF_VTF;
    float* aggd = pool + OFF_AGGD; float* aggf = pool + OFF_AGGF;
    float* tmpd = pool + OFF_TMPD; float* tmpf = pool + OFF_TMPF;
    float* logit = pool + OFF_LOG;
    unsigned* mx = (unsigned*)(pool + OFF_MX);
    float* sm = pool + OFF_SM;

    const int gemmBlkD = cdiv(ND, 64), gemmBlkF = cdiv(NF, 64);
    const int ehBlocks = cdiv((long long)EE * NH, 256);

    // Input projections + ReLU
    gemm128<1><<<gemmBlkD, 256>>>(x_device, W_dev_in, b_dev_in, xd, ND);
    gemm128<1><<<gemmBlkF, 256>>>(x_feature, W_feat_in, b_feat_in, xf, NF);

    for (int l = 0; l < NLYR; l++) {
        const size_t wo0 = (size_t)(l * 2 + 0) * 128 * 128;
        const size_t wo1 = (size_t)(l * 2 + 1) * 128 * 128;
        const size_t bo0 = (size_t)(l * 2 + 0) * 128;
        const size_t bo1 = (size_t)(l * 2 + 1) * 128;

        // q/k/v projections for both node types
        gemm128<0><<<gemmBlkD, 256>>>(xd, Wk + wo0, bk + bo0, kd, ND);
        gemm128<0><<<gemmBlkD, 256>>>(xd, Wq + wo0, bq + bo0, qd, ND);
        gemm128<0><<<gemmBlkD, 256>>>(xd, Wv + wo0, bv + bo0, vd, ND);
        gemm128<0><<<gemmBlkF, 256>>>(xf, Wk + wo1, bk + bo1, kf, NF);
        gemm128<0><<<gemmBlkF, 256>>>(xf, Wq + wo1, bq + bo1, qf, NF);
        gemm128<0><<<gemmBlkF, 256>>>(xf, Wv + wo1, bv + bo1, vf, NF);

        // relation transforms (edge type 0 uses device sources, 1 uses feature)
        const float* a0 = a_rel + (size_t)(l * 2 + 0) * NH * 256;
        const float* m0 = m_rel + (size_t)(l * 2 + 0) * NH * 256;
        const float* a1 = a_rel + (size_t)(l * 2 + 1) * NH * 256;
        const float* m1 = m_rel + (size_t)(l * 2 + 1) * NH * 256;
        rel_transform<<<cdiv(ND128, 256), 256>>>(kd, vd, a0, m0, ktd, vtd, ND);
        rel_transform<<<cdiv(NF128, 256), 256>>>(kf, vf, a1, m1, ktf, vtf, NF);

        const float* p0 = p_rel + (size_t)(l * 2 + 0) * NH;
        const float* p1 = p_rel + (size_t)(l * 2 + 1) * NH;

        // ---- edge type 0: device -> feature (dst = feature nodes) ----
        cudaMemsetAsync(mx, 0, (size_t)NF * NH * sizeof(unsigned), 0);
        cudaMemsetAsync(sm, 0, (size_t)NF * NH * sizeof(float), 0);
        cudaMemsetAsync(aggf, 0, NF128 * sizeof(float), 0);
        edge_logit<<<ehBlocks, 256>>>(e_df_src, e_df_dst, qf, ktd, p0, logit, mx);
        edge_exp<<<ehBlocks, 256>>>(e_df_dst, logit, mx, sm);
        edge_agg<<<ehBlocks, 256>>>(e_df_src, e_df_dst, logit, sm, vtd, aggf);

        // ---- edge type 1: feature -> device (dst = device nodes) ----
        cudaMemsetAsync(mx, 0, (size_t)ND * NH * sizeof(unsigned), 0);
        cudaMemsetAsync(sm, 0, (size_t)ND * NH * sizeof(float), 0);
        cudaMemsetAsync(aggd, 0, ND128 * sizeof(float), 0);
        edge_logit<<<ehBlocks, 256>>>(e_fd_src, e_fd_dst, qd, ktf, p1, logit, mx);
        edge_exp<<<ehBlocks, 256>>>(e_fd_dst, logit, mx, sm);
        edge_agg<<<ehBlocks, 256>>>(e_fd_src, e_fd_dst, logit, sm, vtf, aggd);

        // ---- per-type epilogue: gelu -> Wa -> skip-gate -> residual + LN ----
        gelu_ip<<<cdiv(ND128, 256), 256>>>(aggd, ND128);
        gelu_ip<<<cdiv(NF128, 256), 256>>>(aggf, NF128);
        gemm128<0><<<gemmBlkD, 256>>>(aggd, Wa + wo0, ba + bo0, tmpd, ND);
        gemm128<0><<<gemmBlkF, 256>>>(aggf, Wa + wo1, ba + bo1, tmpf, NF);
        post_ln<<<ND, 128>>>(tmpd, xd, skip + (l * 2 + 0),
                             ln_g + bo0, ln_b + bo0, ND);
        post_ln<<<NF, 128>>>(tmpf, xf, skip + (l * 2 + 1),
                             ln_g + bo1, ln_b + bo1, NF);
    }

    out_gemm<<<cdiv((long long)ND * OUTC, 256), 256>>>(xd, W_out, b_out, out);
}

// round 2
// speedup vs baseline: 1.3190x; 1.3190x over previous
#include <cuda_runtime.h>
#include <cuda_bf16.h>
#include <math.h>

// ---------------------------------------------------------------------------
// Problem constants
// ---------------------------------------------------------------------------
#define ND   20000
#define NF   50000
#define EE   400000
#define HIDN 128
#define NH   8
#define NLYR 2
#define OUTC 32

// ---------------------------------------------------------------------------
// Scratch pool (static device memory; no allocations anywhere)
// ---------------------------------------------------------------------------
constexpr size_t ND128 = (size_t)ND * HIDN;
constexpr size_t NF128 = (size_t)NF * HIDN;

constexpr size_t OFF_XD   = 0;
constexpr size_t OFF_QD   = OFF_XD   + ND128;
constexpr size_t OFF_KTD  = OFF_QD   + ND128;
constexpr size_t OFF_VTD  = OFF_KTD  + ND128;
constexpr size_t OFF_AGGD = OFF_VTD  + ND128;
constexpr size_t OFF_TMPD = OFF_AGGD + ND128;
constexpr size_t OFF_XF   = OFF_TMPD + ND128;
constexpr size_t OFF_QF   = OFF_XF   + NF128;
constexpr size_t OFF_KTF  = OFF_QF   + NF128;
constexpr size_t OFF_VTF  = OFF_KTF  + NF128;
constexpr size_t OFF_AGGF = OFF_VTF  + NF128;
constexpr size_t OFF_TMPF = OFF_AGGF + NF128;
constexpr size_t OFF_SMD  = OFF_TMPF + NF128;              // ND*8
constexpr size_t OFF_SMF  = OFF_SMD  + (size_t)ND * NH;    // NF*8
constexpr size_t OFF_WKE  = OFF_SMF  + (size_t)NF * NH;    // 4*128*128
constexpr size_t OFF_BKE  = OFF_WKE  + 4 * 16384;          // 4*128
constexpr size_t OFF_WVE  = OFF_BKE  + 4 * 128;
constexpr size_t OFF_BVE  = OFF_WVE  + 4 * 16384;
constexpr size_t POOL_SZ  = OFF_BVE  + 4 * 128;

__device__ __align__(256) float g_pool[POOL_SZ];

// ---------------------------------------------------------------------------
// f32x2 packed-FMA helpers (Blackwell sm_100a)
// ---------------------------------------------------------------------------
typedef unsigned long long u64t;

__device__ __forceinline__ void fma2(u64t& acc, u64t a, u64t b) {
    asm("fma.rn.f32x2 %0, %1, %2, %0;" : "+l"(acc) : "l"(a), "l"(b));
}
__device__ __forceinline__ u64t pack2(float x) {
    u64t r;
    asm("mov.b64 %0, {%1, %1};" : "=l"(r) : "f"(x));
    return r;
}
__device__ __forceinline__ void unpack2(u64t v, float& lo, float& hi) {
    asm("mov.b64 {%0, %1}, %2;" : "=f"(lo), "=f"(hi) : "l"(v));
}

__device__ __forceinline__ float gelu_exact(float v) {
    return 0.5f * v * (1.0f + erff(v * 0.70710678118654752440f));
}

// ---------------------------------------------------------------------------
// GEMM: C[N,128] = act(A'[N,128] @ W[128,128] + bias)
//   ACT 0: A' = A, no activation
//   ACT 1: A' = A, relu output
//   ACT 2: A' = gelu(A / (smdiv[node,head] + 1e-16)), no output act
// 128x128 tile, 256 threads, 8x8 per-thread, packed f32x2 accumulation.
// ---------------------------------------------------------------------------
template <int ACT>
__global__ void __launch_bounds__(256, 2)
gemm128(const float* __restrict__ A, const float* __restrict__ W,
        const float* __restrict__ bias, float* __restrict__ C, int N,
        const float* __restrict__ smdiv) {
    __shared__ float As[8][132];
    __shared__ float Bs[8][128];

    const int row0 = blockIdx.x * 128;
    const int tid  = threadIdx.x;
    const int tx   = tid & 15;   // col group: cols tx*8 .. +7
    const int ty   = tid >> 4;   // row group: rows ty*8 .. +7
    const int lr   = tid >> 1;   // A-load row (0..127)
    const int lh   = tid & 1;    // A-load half (k offset 0 or 4)
    const int gr_load = row0 + lr;
    const bool rowok  = gr_load < N;
    const int bkr = tid >> 5;          // B-load k row (0..7)
    const int bc4 = (tid & 31) * 4;    // B-load col

    u64t acc[8][4];
#pragma unroll
    for (int r = 0; r < 8; r++)
#pragma unroll
        for (int c = 0; c < 4; c++) acc[r][c] = 0ULL;

    for (int k0 = 0; k0 < 128; k0 += 8) {
        float4 av = make_float4(0.f, 0.f, 0.f, 0.f);
        if (rowok) {
            av = *(const float4*)(A + (size_t)gr_load * 128 + k0 + lh * 4);
            if (ACT == 2) {
                int head = (k0 + lh * 4) >> 4;
                float s = smdiv[(size_t)gr_load * 8 + head] + 1e-16f;
                float inv = __frcp_rn(s);
                av.x = gelu_exact(av.x * inv);
                av.y = gelu_exact(av.y * inv);
                av.z = gelu_exact(av.z * inv);
                av.w = gelu_exact(av.w * inv);
            }
        }
        As[lh * 4 + 0][lr] = av.x;
        As[lh * 4 + 1][lr] = av.y;
        As[lh * 4 + 2][lr] = av.z;
        As[lh * 4 + 3][lr] = av.w;
        *(float4*)&Bs[bkr][bc4] = *(const float4*)(W + (size_t)(k0 + bkr) * 128 + bc4);
        __syncthreads();

#pragma unroll
        for (int kk = 0; kk < 8; kk++) {
            float4 a0 = *(const float4*)&As[kk][ty * 8];
            float4 a1 = *(const float4*)&As[kk][ty * 8 + 4];
            ulonglong2 b0 = *(const ulonglong2*)&Bs[kk][tx * 8];
            ulonglong2 b1 = *(const ulonglong2*)&Bs[kk][tx * 8 + 4];
            u64t a2[8];
            a2[0] = pack2(a0.x); a2[1] = pack2(a0.y);
            a2[2] = pack2(a0.z); a2[3] = pack2(a0.w);
            a2[4] = pack2(a1.x); a2[5] = pack2(a1.y);
            a2[6] = pack2(a1.z); a2[7] = pack2(a1.w);
#pragma unroll
            for (int r = 0; r < 8; r++) {
                fma2(acc[r][0], a2[r], b0.x);
                fma2(acc[r][1], a2[r], b0.y);
                fma2(acc[r][2], a2[r], b1.x);
                fma2(acc[r][3], a2[r], b1.y);
            }
        }
        __syncthreads();
    }

    float bcol[8];
    *(float4*)&bcol[0] = *(const float4*)(bias + tx * 8);
    *(float4*)&bcol[4] = *(const float4*)(bias + tx * 8 + 4);

#pragma unroll
    for (int r = 0; r < 8; r++) {
        int gr = row0 + ty * 8 + r;
        if (gr < N) {
            float o[8];
#pragma unroll
            for (int cp = 0; cp < 4; cp++) unpack2(acc[r][cp], o[cp * 2], o[cp * 2 + 1]);
#pragma unroll
            for (int c = 0; c < 8; c++) {
                o[c] += bcol[c];
                if (ACT == 1) o[c] = fmaxf(o[c], 0.f);
            }
            *(float4*)(C + (size_t)gr * 128 + tx * 8)     = make_float4(o[0], o[1], o[2], o[3]);
            *(float4*)(C + (size_t)gr * 128 + tx * 8 + 4) = make_float4(o[4], o[5], o[6], o[7]);
        }
    }
}

// ---------------------------------------------------------------------------
// Fold relation transforms into projection weights:
//   WkE[c][r][h*16+e] = sum_d Wk[c][r][h*16+d] * a[c,h,d,e] * p[c,h]/4
//   WvE[c][r][h*16+e] = sum_d Wv[c][r][h*16+d] * m[c,h,d,e]
// r == 128 row handles the bias fold. combo c = l*2 + t.
// ---------------------------------------------------------------------------
__global__ void fold_weights(const float* __restrict__ Wk, const float* __restrict__ bk,
                             const float* __restrict__ Wv, const float* __restrict__ bv,
                             const float* __restrict__ a_rel, const float* __restrict__ m_rel,
                             const float* __restrict__ p_rel,
                             float* __restrict__ WkE, float* __restrict__ bkE,
                             float* __restrict__ WvE, float* __restrict__ bvE) {
    int idx = blockIdx.x * blockDim.x + threadIdx.x;
    if (idx >= 4 * 129 * 128) return;
    int combo = idx / (129 * 128);
    int rem   = idx % (129 * 128);
    int r  = rem >> 7;
    int he = rem & 127;
    int h = he >> 4, e = he & 15;
    const float* a = a_rel + ((size_t)combo * 8 + h) * 256 + e;  // stride 16 over d
    const float* m = m_rel + ((size_t)combo * 8 + h) * 256 + e;
    float ps = p_rel[combo * 8 + h] * 0.25f;  // p / sqrt(D), D = 16

    const float* kr = (r < 128) ? (Wk + (size_t)combo * 16384 + (size_t)r * 128 + h * 16)
                                : (bk + (size_t)combo * 128 + h * 16);
    const float* vr = (r < 128) ? (Wv + (size_t)combo * 16384 + (size_t)r * 128 + h * 16)
                                : (bv + (size_t)combo * 128 + h * 16);
    float sk = 0.f, sv = 0.f;
#pragma unroll
    for (int d = 0; d < 16; d++) {
        sk += kr[d] * a[d * 16];
        sv += vr[d] * m[d * 16];
    }
    sk *= ps;
    if (r < 128) {
        WkE[(size_t)combo * 16384 + (size_t)r * 128 + he] = sk;
        WvE[(size_t)combo * 16384 + (size_t)r * 128 + he] = sv;
    } else {
        bkE[combo * 128 + he] = sk;
        bvE[combo * 128 + he] = sv;
    }
}

// ---------------------------------------------------------------------------
// Single fused edge pass (per edge type):
//   ex = exp(q[dst,h] . kt[src,h])        (prior & 1/sqrt(D) folded into kt)
//   sm[dst,h]     += ex          (atomic)
//   agg[dst,h,:]  += ex * vt[src,h,:]     (red.global.add.v4)
// Normalization agg/sm happens in the Wa-GEMM A-load (ACT=2).
// ---------------------------------------------------------------------------
__global__ void edge_pass(const int* __restrict__ src, const int* __restrict__ dst,
                          const float* __restrict__ q, const float* __restrict__ kt,
                          const float* __restrict__ vt,
                          float* __restrict__ sm, float* __restrict__ agg) {
    size_t idx = (size_t)blockIdx.x * blockDim.x + threadIdx.x;
    if (idx >= (size_t)EE * NH) return;
    int e = (int)(idx >> 3), h = (int)(idx & 7);
    int s = src[e], d = dst[e];

    const float4* qr = (const float4*)(q  + (size_t)d * 128 + h * 16);
    const float4* kr = (const float4*)(kt + (size_t)s * 128 + h * 16);
    float sum = 0.f;
#pragma unroll
    for (int i = 0; i < 4; i++) {
        float4 aa = qr[i], bb = kr[i];
        sum += aa.x * bb.x + aa.y * bb.y + aa.z * bb.z + aa.w * bb.w;
    }
    float ex = __expf(fminf(sum, 80.f));
    atomicAdd(&sm[d * NH + h], ex);

    const float4* vr = (const float4*)(vt + (size_t)s * 128 + h * 16);
    float* out = agg + (size_t)d * 128 + h * 16;
#pragma unroll
    for (int i = 0; i < 4; i++) {
        float4 vv = vr[i];
        asm volatile("red.global.add.v4.f32 [%0], {%1,%2,%3,%4};"
                     :: "l"(out + i * 4),
                        "f"(vv.x * ex), "f"(vv.y * ex),
                        "f"(vv.z * ex), "f"(vv.w * ex)
                     : "memory");
    }
}

// ---------------------------------------------------------------------------
// Skip-gate + residual + LayerNorm.  One block (128 thr) per node, in-place x.
// ---------------------------------------------------------------------------
__global__ void post_ln(const float* __restrict__ o, float* __restrict__ x,
                        const float* __restrict__ skip_lt,
                        const float* __restrict__ g, const float* __restrict__ b,
                        int N) {
    int n = blockIdx.x;
    if (n >= N) return;
    int t = threadIdx.x;
    float sk = 1.f / (1.f + __expf(-skip_lt[0]));
    size_t base = (size_t)n * 128 + t;
    float xv = x[base];
    float ov = sk * o[base] + (1.f - sk) * xv;
    float y = xv + ov;

    __shared__ float red[4];
    float s = y;
#pragma unroll
    for (int off = 16; off; off >>= 1) s += __shfl_xor_sync(0xffffffff, s, off);
    if ((t & 31) == 0) red[t >> 5] = s;
    __syncthreads();
    float mean = (red[0] + red[1] + red[2] + red[3]) * (1.f / 128.f);
    __syncthreads();

    float dy = y - mean;
    float s2 = dy * dy;
#pragma unroll
    for (int off = 16; off; off >>= 1) s2 += __shfl_xor_sync(0xffffffff, s2, off);
    if ((t & 31) == 0) red[t >> 5] = s2;
    __syncthreads();
    float var = (red[0] + red[1] + red[2] + red[3]) * (1.f / 128.f);

    x[base] = dy * rsqrtf(var + 1e-5f) * g[t] + b[t];
}

// ---------------------------------------------------------------------------
// Output head: out[ND,32] = x[ND,128] @ W[128,32] + b
// ---------------------------------------------------------------------------
__global__ void out_gemm(const float* __restrict__ x, const float* __restrict__ W,
                         const float* __restrict__ b, float* __restrict__ out) {
    size_t idx = (size_t)blockIdx.x * blockDim.x + threadIdx.x;
    if (idx >= (size_t)ND * OUTC) return;
    int n = (int)(idx >> 5), c = (int)(idx & 31);
    const float* xr = x + (size_t)n * 128;
    float s = b[c];
#pragma unroll 8
    for (int k = 0; k < 128; k++) s += xr[k] * W[k * OUTC + c];
    out[idx] = s;
}

// ---------------------------------------------------------------------------
// Host orchestration
// ---------------------------------------------------------------------------
static inline int cdiv(long long a, long long b) { return (int)((a + b - 1) / b); }

extern "C" void kernel_launch(void* const* d_in, const int* in_sizes, int n_in,
                              void* d_out, int out_size) {
    (void)in_sizes; (void)n_in; (void)out_size;

    const float* x_device = (const float*)d_in[0];
    const float* x_feature = (const float*)d_in[1];
    const int* e_df_src = (const int*)d_in[2];
    const int* e_df_dst = (const int*)d_in[3];
    const int* e_fd_src = (const int*)d_in[4];
    const int* e_fd_dst = (const int*)d_in[5];
    const float* W_dev_in = (const float*)d_in[6];
    const float* b_dev_in = (const float*)d_in[7];
    const float* W_feat_in = (const float*)d_in[8];
    const float* b_feat_in = (const float*)d_in[9];
    const float* Wk = (const float*)d_in[10];
    const float* bk = (const float*)d_in[11];
    const float* Wq = (const float*)d_in[12];
    const float* bq = (const float*)d_in[13];
    const float* Wv = (const float*)d_in[14];
    const float* bv = (const float*)d_in[15];
    const float* a_rel = (const float*)d_in[16];
    const float* m_rel = (const float*)d_in[17];
    const float* p_rel = (const float*)d_in[18];
    const float* Wa = (const float*)d_in[19];
    const float* ba = (const float*)d_in[20];
    const float* skip = (const float*)d_in[21];
    const float* ln_g = (const float*)d_in[22];
    const float* ln_b = (const float*)d_in[23];
    const float* W_out = (const float*)d_in[24];
    const float* b_out = (const float*)d_in[25];
    float* out = (float*)d_out;

    float* pool = nullptr;
    cudaGetSymbolAddress((void**)&pool, g_pool);

    float* xd   = pool + OFF_XD;   float* xf   = pool + OFF_XF;
    float* qd   = pool + OFF_QD;   float* qf   = pool + OFF_QF;
    float* ktd  = pool + OFF_KTD;  float* ktf  = pool + OFF_KTF;
    float* vtd  = pool + OFF_VTD;  float* vtf  = pool + OFF_VTF;
    float* aggd = pool + OFF_AGGD; float* aggf = pool + OFF_AGGF;
    float* tmpd = pool + OFF_TMPD; float* tmpf = pool + OFF_TMPF;
    float* smd  = pool + OFF_SMD;  float* smf  = pool + OFF_SMF;
    float* WkE  = pool + OFF_WKE;  float* bkE  = pool + OFF_BKE;
    float* WvE  = pool + OFF_WVE;  float* bvE  = pool + OFF_BVE;

    const int gBlkD = cdiv(ND, 128), gBlkF = cdiv(NF, 128);
    const int ehBlocks = cdiv((long long)EE * NH, 256);

    // Fold relation transforms + priors into k/v projection weights
    fold_weights<<<cdiv(4 * 129 * 128, 256), 256>>>(Wk, bk, Wv, bv, a_rel, m_rel, p_rel,
                                                    WkE, bkE, WvE, bvE);

    // Input projections + ReLU
    gemm128<1><<<gBlkD, 256>>>(x_device, W_dev_in, b_dev_in, xd, ND, nullptr);
    gemm128<1><<<gBlkF, 256>>>(x_feature, W_feat_in, b_feat_in, xf, NF, nullptr);

    for (int l = 0; l < NLYR; l++) {
        const int c0 = l * 2 + 0, c1 = l * 2 + 1;
        const size_t wo0 = (size_t)c0 * 16384, wo1 = (size_t)c1 * 16384;
        const size_t bo0 = (size_t)c0 * 128,   bo1 = (size_t)c1 * 128;

        // projections: q from original weights, kt/vt from folded weights
        gemm128<0><<<gBlkD, 256>>>(xd, Wq + wo0, bq + bo0, qd, ND, nullptr);
        gemm128<0><<<gBlkD, 256>>>(xd, WkE + wo0, bkE + bo0, ktd, ND, nullptr);
        gemm128<0><<<gBlkD, 256>>>(xd, WvE + wo0, bvE + bo0, vtd, ND, nullptr);
        gemm128<0><<<gBlkF, 256>>>(xf, Wq + wo1, bq + bo1, qf, NF, nullptr);
        gemm128<0><<<gBlkF, 256>>>(xf, WkE + wo1, bkE + bo1, ktf, NF, nullptr);
        gemm128<0><<<gBlkF, 256>>>(xf, WvE + wo1, bvE + bo1, vtf, NF, nullptr);

        // edge type 0: device -> feature (dst = feature)
        cudaMemsetAsync(smf, 0, (size_t)NF * NH * sizeof(float), 0);
        cudaMemsetAsync(aggf, 0, NF128 * sizeof(float), 0);
        edge_pass<<<ehBlocks, 256>>>(e_df_src, e_df_dst, qf, ktd, vtd, smf, aggf);

        // edge type 1: feature -> device (dst = device)
        cudaMemsetAsync(smd, 0, (size_t)ND * NH * sizeof(float), 0);
        cudaMemsetAsync(aggd, 0, ND128 * sizeof(float), 0);
        edge_pass<<<ehBlocks, 256>>>(e_fd_src, e_fd_dst, qd, ktf, vtf, smd, aggd);

        // epilogue: (normalize + gelu fused into A-load) @ Wa, then skip+LN
        gemm128<2><<<gBlkD, 256>>>(aggd, Wa + wo0, ba + bo0, tmpd, ND, smd);
        gemm128<2><<<gBlkF, 256>>>(aggf, Wa + wo1, ba + bo1, tmpf, NF, smf);
        post_ln<<<ND, 128>>>(tmpd, xd, skip + c0, ln_g + bo0, ln_b + bo0, ND);
        post_ln<<<NF, 128>>>(tmpf, xf, skip + c1, ln_g + bo1, ln_b + bo1, NF);
    }

    out_gemm<<<cdiv((long long)ND * OUTC, 256), 256>>>(xd, W_out, b_out, out);
}

// round 4
// speedup vs baseline: 1.6388x; 1.2425x over previous
#include <cuda_runtime.h>
#include <cuda_bf16.h>
#include <math.h>

// ---------------------------------------------------------------------------
// Problem constants
// ---------------------------------------------------------------------------
#define ND   20000
#define NF   50000
#define EE   400000
#define HIDN 128
#define NH   8
#define NLYR 2
#define OUTC 32

// ---------------------------------------------------------------------------
// Scratch pool (static device memory; no allocations anywhere)
// ---------------------------------------------------------------------------
constexpr size_t ND128 = (size_t)ND * HIDN;
constexpr size_t NF128 = (size_t)NF * HIDN;

constexpr size_t OFF_XD   = 0;
constexpr size_t OFF_QD   = OFF_XD   + ND128;
constexpr size_t OFF_KTD  = OFF_QD   + ND128;
constexpr size_t OFF_VTD  = OFF_KTD  + ND128;
constexpr size_t OFF_AGGD = OFF_VTD  + ND128;
constexpr size_t OFF_TMPD = OFF_AGGD + ND128;
constexpr size_t OFF_XF   = OFF_TMPD + ND128;
constexpr size_t OFF_QF   = OFF_XF   + NF128;
constexpr size_t OFF_KTF  = OFF_QF   + NF128;
constexpr size_t OFF_VTF  = OFF_KTF  + NF128;
constexpr size_t OFF_AGGF = OFF_VTF  + NF128;
constexpr size_t OFF_TMPF = OFF_AGGF + NF128;
constexpr size_t OFF_SMD  = OFF_TMPF + NF128;              // ND*8
constexpr size_t OFF_SMF  = OFF_SMD  + (size_t)ND * NH;    // NF*8
constexpr size_t OFF_WKE  = OFF_SMF  + (size_t)NF * NH;    // 4*128*128
constexpr size_t OFF_BKE  = OFF_WKE  + 4 * 16384;          // 4*128
constexpr size_t OFF_WVE  = OFF_BKE  + 4 * 128;
constexpr size_t OFF_BVE  = OFF_WVE  + 4 * 16384;
constexpr size_t POOL_SZ  = OFF_BVE  + 4 * 128;

__device__ __align__(256) float g_pool[POOL_SZ];

// ---------------------------------------------------------------------------
// Helpers
// ---------------------------------------------------------------------------
__device__ __forceinline__ float gelu_exact(float v) {
    return 0.5f * v * (1.0f + erff(v * 0.70710678118654752440f));
}

__device__ __forceinline__ unsigned tf32r(float x) {
    unsigned r;
    asm("cvt.rna.tf32.f32 %0, %1;" : "=r"(r) : "f"(x));
    return r;
}
__device__ __forceinline__ void split_tf32(float x, unsigned& hi, unsigned& lo) {
    hi = tf32r(x);
    lo = tf32r(x - __uint_as_float(hi));
}

#define MMA_TF32(d, a, b)                                                     \
    asm volatile(                                                             \
        "mma.sync.aligned.m16n8k8.row.col.f32.tf32.tf32.f32 "                 \
        "{%0,%1,%2,%3},{%4,%5,%6,%7},{%8,%9},{%0,%1,%2,%3};"                  \
        : "+f"((d)[0]), "+f"((d)[1]), "+f"((d)[2]), "+f"((d)[3])              \
        : "r"((a)[0]), "r"((a)[1]), "r"((a)[2]), "r"((a)[3]),                 \
          "r"((b)[0]), "r"((b)[1]))

__device__ __forceinline__ void cp16(unsigned dst, const void* src, bool pred) {
    if (pred)
        asm volatile("cp.async.cg.shared.global [%0], [%1], 16;"
                     :: "r"(dst), "l"(src));
}

// ---------------------------------------------------------------------------
// Tensor-core GEMM, 3xTF32 split (fp32-accurate):
//   C[y][N,128] = act(A[N,128] @ W[y][128,128] + bias[y]),  y = blockIdx.y
// 128x128 block tile, BK=16, 8 warps (warp tile 32x64), cp.async double buffer.
// ---------------------------------------------------------------------------
#define ASTRIDE 20
#define BSTRIDE 136

template <int RELU>
__global__ void __launch_bounds__(256)
gemm_tc(const float* __restrict__ A,
        const float* __restrict__ W0, const float* __restrict__ W1, const float* __restrict__ W2,
        const float* __restrict__ b0, const float* __restrict__ b1, const float* __restrict__ b2,
        float* __restrict__ C0, float* __restrict__ C1, float* __restrict__ C2,
        int N) {
    const float* W    = (blockIdx.y == 0) ? W0 : (blockIdx.y == 1) ? W1 : W2;
    const float* bias = (blockIdx.y == 0) ? b0 : (blockIdx.y == 1) ? b1 : b2;
    float*       C    = (blockIdx.y == 0) ? C0 : (blockIdx.y == 1) ? C1 : C2;

    // 16B alignment is REQUIRED for cp.async destinations
    __shared__ __align__(16) float As[2][128 * ASTRIDE];
    __shared__ __align__(16) float Bs[2][16 * BSTRIDE];

    const int tid  = threadIdx.x;
    const int row0 = blockIdx.x * 128;
    const int lane = tid & 31, warp = tid >> 5;
    const int g = lane >> 2, c = lane & 3;
    const int m0 = (warp >> 1) * 32, n0 = (warp & 1) * 64;

    // async stage of one BK=16 chunk (A: 128x16, B: 16x128)
    auto stage = [&](int buf, int k0) {
#pragma unroll
        for (int i = 0; i < 2; i++) {
            int id = tid * 2 + i;
            int r = id >> 2, ch = id & 3;                       // A: row, 16B chunk
            unsigned da = (unsigned)__cvta_generic_to_shared(
                &As[buf][r * ASTRIDE + ch * 4]);
            cp16(da, A + (size_t)(row0 + r) * 128 + k0 + ch * 4, row0 + r < N);
            int k = id >> 5, nch = id & 31;                     // B: k-row, 16B chunk
            unsigned db = (unsigned)__cvta_generic_to_shared(
                &Bs[buf][k * BSTRIDE + nch * 4]);
            cp16(db, W + (size_t)(k0 + k) * 128 + nch * 4, true);
        }
        asm volatile("cp.async.commit_group;");
    };

    float acc[2][8][4];
#pragma unroll
    for (int mi = 0; mi < 2; mi++)
#pragma unroll
        for (int ni = 0; ni < 8; ni++)
#pragma unroll
            for (int j = 0; j < 4; j++) acc[mi][ni][j] = 0.f;

    stage(0, 0);

    for (int it = 0; it < 8; it++) {
        if (it < 7) {
            stage((it + 1) & 1, (it + 1) * 16);
            asm volatile("cp.async.wait_group 1;");
        } else {
            asm volatile("cp.async.wait_group 0;");
        }
        __syncthreads();
        const float* Ab = As[it & 1];
        const float* Bb = Bs[it & 1];

#pragma unroll
        for (int kk = 0; kk < 16; kk += 8) {
            // A fragments for the two 16-row m-sites (split in registers)
            unsigned ahi[2][4], alo[2][4];
#pragma unroll
            for (int mi = 0; mi < 2; mi++) {
                int rb = (m0 + mi * 16 + g) * ASTRIDE;
                split_tf32(Ab[rb + kk + c],                 ahi[mi][0], alo[mi][0]);
                split_tf32(Ab[rb + 8 * ASTRIDE + kk + c],   ahi[mi][1], alo[mi][1]);
                split_tf32(Ab[rb + kk + c + 4],             ahi[mi][2], alo[mi][2]);
                split_tf32(Ab[rb + 8 * ASTRIDE + kk + c + 4], ahi[mi][3], alo[mi][3]);
            }
#pragma unroll
            for (int ni = 0; ni < 8; ni++) {
                int bn = n0 + ni * 8 + g;
                unsigned bh[2], bl[2];
                split_tf32(Bb[(kk + c) * BSTRIDE + bn],     bh[0], bl[0]);
                split_tf32(Bb[(kk + c + 4) * BSTRIDE + bn], bh[1], bl[1]);
#pragma unroll
                for (int mi = 0; mi < 2; mi++) {
                    MMA_TF32(acc[mi][ni], ahi[mi], bh);
                    MMA_TF32(acc[mi][ni], ahi[mi], bl);
                    MMA_TF32(acc[mi][ni], alo[mi], bh);
                }
            }
        }
        __syncthreads();
    }

    // epilogue: bias (+relu), float2 stores
#pragma unroll
    for (int ni = 0; ni < 8; ni++) {
        int col = n0 + ni * 8 + 2 * c;
        float bb0 = bias[col], bb1 = bias[col + 1];
#pragma unroll
        for (int mi = 0; mi < 2; mi++) {
            int r = row0 + m0 + mi * 16 + g;
            float v0 = acc[mi][ni][0] + bb0, v1 = acc[mi][ni][1] + bb1;
            float v2 = acc[mi][ni][2] + bb0, v3 = acc[mi][ni][3] + bb1;
            if (RELU) {
                v0 = fmaxf(v0, 0.f); v1 = fmaxf(v1, 0.f);
                v2 = fmaxf(v2, 0.f); v3 = fmaxf(v3, 0.f);
            }
            if (r < N)     *(float2*)(C + (size_t)r * 128 + col)       = make_float2(v0, v1);
            if (r + 8 < N) *(float2*)(C + (size_t)(r + 8) * 128 + col) = make_float2(v2, v3);
        }
    }
}

// ---------------------------------------------------------------------------
// Fold relation transforms into projection weights (and priors into k):
// ---------------------------------------------------------------------------
__global__ void fold_weights(const float* __restrict__ Wk, const float* __restrict__ bk,
                             const float* __restrict__ Wv, const float* __restrict__ bv,
                             const float* __restrict__ a_rel, const float* __restrict__ m_rel,
                             const float* __restrict__ p_rel,
                             float* __restrict__ WkE, float* __restrict__ bkE,
                             float* __restrict__ WvE, float* __restrict__ bvE) {
    int idx = blockIdx.x * blockDim.x + threadIdx.x;
    if (idx >= 4 * 129 * 128) return;
    int combo = idx / (129 * 128);
    int rem   = idx % (129 * 128);
    int r  = rem >> 7;
    int he = rem & 127;
    int h = he >> 4, e = he & 15;
    const float* a = a_rel + ((size_t)combo * 8 + h) * 256 + e;
    const float* m = m_rel + ((size_t)combo * 8 + h) * 256 + e;
    float ps = p_rel[combo * 8 + h] * 0.25f;  // p / sqrt(D)

    const float* kr = (r < 128) ? (Wk + (size_t)combo * 16384 + (size_t)r * 128 + h * 16)
                                : (bk + (size_t)combo * 128 + h * 16);
    const float* vr = (r < 128) ? (Wv + (size_t)combo * 16384 + (size_t)r * 128 + h * 16)
                                : (bv + (size_t)combo * 128 + h * 16);
    float sk = 0.f, sv = 0.f;
#pragma unroll
    for (int d = 0; d < 16; d++) {
        sk += kr[d] * a[d * 16];
        sv += vr[d] * m[d * 16];
    }
    sk *= ps;
    if (r < 128) {
        WkE[(size_t)combo * 16384 + (size_t)r * 128 + he] = sk;
        WvE[(size_t)combo * 16384 + (size_t)r * 128 + he] = sv;
    } else {
        bkE[combo * 128 + he] = sk;
        bvE[combo * 128 + he] = sv;
    }
}

// ---------------------------------------------------------------------------
// Single fused edge pass (per edge type)
// ---------------------------------------------------------------------------
__global__ void edge_pass(const int* __restrict__ src, const int* __restrict__ dst,
                          const float* __restrict__ q, const float* __restrict__ kt,
                          const float* __restrict__ vt,
                          float* __restrict__ sm, float* __restrict__ agg) {
    size_t idx = (size_t)blockIdx.x * blockDim.x + threadIdx.x;
    if (idx >= (size_t)EE * NH) return;
    int e = (int)(idx >> 3), h = (int)(idx & 7);
    int s = src[e], d = dst[e];

    const float4* qr = (const float4*)(q  + (size_t)d * 128 + h * 16);
    const float4* kr = (const float4*)(kt + (size_t)s * 128 + h * 16);
    float sum = 0.f;
#pragma unroll
    for (int i = 0; i < 4; i++) {
        float4 aa = qr[i], bb = kr[i];
        sum += aa.x * bb.x + aa.y * bb.y + aa.z * bb.z + aa.w * bb.w;
    }
    float ex = __expf(fminf(sum, 80.f));
    atomicAdd(&sm[d * NH + h], ex);

    const float4* vr = (const float4*)(vt + (size_t)s * 128 + h * 16);
    float* out = agg + (size_t)d * 128 + h * 16;
#pragma unroll
    for (int i = 0; i < 4; i++) {
        float4 vv = vr[i];
        asm volatile("red.global.add.v4.f32 [%0], {%1,%2,%3,%4};"
                     :: "l"(out + i * 4),
                        "f"(vv.x * ex), "f"(vv.y * ex),
                        "f"(vv.z * ex), "f"(vv.w * ex)
                     : "memory");
    }
}

// ---------------------------------------------------------------------------
// Normalize by softmax denom + exact GELU, in place
// ---------------------------------------------------------------------------
__global__ void norm_gelu(float* __restrict__ x, const float* __restrict__ sm, size_t n128) {
    size_t idx = (size_t)blockIdx.x * blockDim.x + threadIdx.x;
    if (idx >= n128) return;
    size_t node = idx >> 7;
    int head = (int)((idx >> 4) & 7);
    float s = sm[node * 8 + head] + 1e-16f;
    x[idx] = gelu_exact(x[idx] * __frcp_rn(s));
}

// ---------------------------------------------------------------------------
// Skip-gate + residual + LayerNorm.  One block (128 thr) per node, in-place x.
// ---------------------------------------------------------------------------
__global__ void post_ln(const float* __restrict__ o, float* __restrict__ x,
                        const float* __restrict__ skip_lt,
                        const float* __restrict__ g, const float* __restrict__ b,
                        int N) {
    int n = blockIdx.x;
    if (n >= N) return;
    int t = threadIdx.x;
    float sk = 1.f / (1.f + __expf(-skip_lt[0]));
    size_t base = (size_t)n * 128 + t;
    float xv = x[base];
    float ov = sk * o[base] + (1.f - sk) * xv;
    float y = xv + ov;

    __shared__ float red[4];
    float s = y;
#pragma unroll
    for (int off = 16; off; off >>= 1) s += __shfl_xor_sync(0xffffffff, s, off);
    if ((t & 31) == 0) red[t >> 5] = s;
    __syncthreads();
    float mean = (red[0] + red[1] + red[2] + red[3]) * (1.f / 128.f);
    __syncthreads();

    float dy = y - mean;
    float s2 = dy * dy;
#pragma unroll
    for (int off = 16; off; off >>= 1) s2 += __shfl_xor_sync(0xffffffff, s2, off);
    if ((t & 31) == 0) red[t >> 5] = s2;
    __syncthreads();
    float var = (red[0] + red[1] + red[2] + red[3]) * (1.f / 128.f);

    x[base] = dy * rsqrtf(var + 1e-5f) * g[t] + b[t];
}

// ---------------------------------------------------------------------------
// Output head: out[ND,32] = x[ND,128] @ W[128,32] + b
// ---------------------------------------------------------------------------
__global__ void out_gemm(const float* __restrict__ x, const float* __restrict__ W,
                         const float* __restrict__ b, float* __restrict__ out) {
    size_t idx = (size_t)blockIdx.x * blockDim.x + threadIdx.x;
    if (idx >= (size_t)ND * OUTC) return;
    int n = (int)(idx >> 5), c = (int)(idx & 31);
    const float* xr = x + (size_t)n * 128;
    float s = b[c];
#pragma unroll 8
    for (int k = 0; k < 128; k++) s += xr[k] * W[k * OUTC + c];
    out[idx] = s;
}

// ---------------------------------------------------------------------------
// Host orchestration
// ---------------------------------------------------------------------------
static inline int cdiv(long long a, long long b) { return (int)((a + b - 1) / b); }

extern "C" void kernel_launch(void* const* d_in, const int* in_sizes, int n_in,
                              void* d_out, int out_size) {
    (void)in_sizes; (void)n_in; (void)out_size;

    const float* x_device = (const float*)d_in[0];
    const float* x_feature = (const float*)d_in[1];
    const int* e_df_src = (const int*)d_in[2];
    const int* e_df_dst = (const int*)d_in[3];
    const int* e_fd_src = (const int*)d_in[4];
    const int* e_fd_dst = (const int*)d_in[5];
    const float* W_dev_in = (const float*)d_in[6];
    const float* b_dev_in = (const float*)d_in[7];
    const float* W_feat_in = (const float*)d_in[8];
    const float* b_feat_in = (const float*)d_in[9];
    const float* Wk = (const float*)d_in[10];
    const float* bk = (const float*)d_in[11];
    const float* Wq = (const float*)d_in[12];
    const float* bq = (const float*)d_in[13];
    const float* Wv = (const float*)d_in[14];
    const float* bv = (const float*)d_in[15];
    const float* a_rel = (const float*)d_in[16];
    const float* m_rel = (const float*)d_in[17];
    const float* p_rel = (const float*)d_in[18];
    const float* Wa = (const float*)d_in[19];
    const float* ba = (const float*)d_in[20];
    const float* skip = (const float*)d_in[21];
    const float* ln_g = (const float*)d_in[22];
    const float* ln_b = (const float*)d_in[23];
    const float* W_out = (const float*)d_in[24];
    const float* b_out = (const float*)d_in[25];
    float* out = (float*)d_out;

    float* pool = nullptr;
    cudaGetSymbolAddress((void**)&pool, g_pool);

    float* xd   = pool + OFF_XD;   float* xf   = pool + OFF_XF;
    float* qd   = pool + OFF_QD;   float* qf   = pool + OFF_QF;
    float* ktd  = pool + OFF_KTD;  float* ktf  = pool + OFF_KTF;
    float* vtd  = pool + OFF_VTD;  float* vtf  = pool + OFF_VTF;
    float* aggd = pool + OFF_AGGD; float* aggf = pool + OFF_AGGF;
    float* tmpd = pool + OFF_TMPD; float* tmpf = pool + OFF_TMPF;
    float* smd  = pool + OFF_SMD;  float* smf  = pool + OFF_SMF;
    float* WkE  = pool + OFF_WKE;  float* bkE  = pool + OFF_BKE;
    float* WvE  = pool + OFF_WVE;  float* bvE  = pool + OFF_BVE;

    const int gBlkD = cdiv(ND, 128), gBlkF = cdiv(NF, 128);
    const int ehBlocks = cdiv((long long)EE * NH, 256);

    // Fold relation transforms + priors into k/v projection weights
    fold_weights<<<cdiv(4 * 129 * 128, 256), 256>>>(Wk, bk, Wv, bv, a_rel, m_rel, p_rel,
                                                    WkE, bkE, WvE, bvE);

    // Input projections + ReLU
    gemm_tc<1><<<dim3(gBlkD, 1), 256>>>(x_device, W_dev_in, W_dev_in, W_dev_in,
                                        b_dev_in, b_dev_in, b_dev_in,
                                        xd, xd, xd, ND);
    gemm_tc<1><<<dim3(gBlkF, 1), 256>>>(x_feature, W_feat_in, W_feat_in, W_feat_in,
                                        b_feat_in, b_feat_in, b_feat_in,
                                        xf, xf, xf, NF);

    for (int l = 0; l < NLYR; l++) {
        const int c0 = l * 2 + 0, c1 = l * 2 + 1;
        const size_t wo0 = (size_t)c0 * 16384, wo1 = (size_t)c1 * 16384;
        const size_t bo0 = (size_t)c0 * 128,   bo1 = (size_t)c1 * 128;

        // fused q/kt/vt projections (one launch per node type, gridDim.y = 3)
        gemm_tc<0><<<dim3(gBlkD, 3), 256>>>(xd, Wq + wo0, WkE + wo0, WvE + wo0,
                                            bq + bo0, bkE + bo0, bvE + bo0,
                                            qd, ktd, vtd, ND);
        gemm_tc<0><<<dim3(gBlkF, 3), 256>>>(xf, Wq + wo1, WkE + wo1, WvE + wo1,
                                            bq + bo1, bkE + bo1, bvE + bo1,
                                            qf, ktf, vtf, NF);

        // edge type 0: device -> feature (dst = feature)
        cudaMemsetAsync(smf, 0, (size_t)NF * NH * sizeof(float), 0);
        cudaMemsetAsync(aggf, 0, NF128 * sizeof(float), 0);
        edge_pass<<<ehBlocks, 256>>>(e_df_src, e_df_dst, qf, ktd, vtd, smf, aggf);

        // edge type 1: feature -> device (dst = device)
        cudaMemsetAsync(smd, 0, (size_t)ND * NH * sizeof(float), 0);
        cudaMemsetAsync(aggd, 0, ND128 * sizeof(float), 0);
        edge_pass<<<ehBlocks, 256>>>(e_fd_src, e_fd_dst, qd, ktf, vtf, smd, aggd);

        // epilogue: normalize+gelu, Wa-GEMM, skip+LN
        norm_gelu<<<cdiv(ND128, 256), 256>>>(aggd, smd, ND128);
        norm_gelu<<<cdiv(NF128, 256), 256>>>(aggf, smf, NF128);
        gemm_tc<0><<<dim3(gBlkD, 1), 256>>>(aggd, Wa + wo0, Wa + wo0, Wa + wo0,
                                            ba + bo0, ba + bo0, ba + bo0,
                                            tmpd, tmpd, tmpd, ND);
        gemm_tc<0><<<dim3(gBlkF, 1), 256>>>(aggf, Wa + wo1, Wa + wo1, Wa + wo1,
                                            ba + bo1, ba + bo1, ba + bo1,
                                            tmpf, tmpf, tmpf, NF);
        post_ln<<<ND, 128>>>(tmpd, xd, skip + c0, ln_g + bo0, ln_b + bo0, ND);
        post_ln<<<NF, 128>>>(tmpf, xf, skip + c1, ln_g + bo1, ln_b + bo1, NF);
    }

    out_gemm<<<cdiv((long long)ND * OUTC, 256), 256>>>(xd, W_out, b_out, out);
}

// round 5
// speedup vs baseline: 2.1346x; 1.3025x over previous
#include <cuda_runtime.h>
#include <cuda_bf16.h>
#include <math.h>

// ---------------------------------------------------------------------------
// Problem constants
// ---------------------------------------------------------------------------
#define ND   20000
#define NF   50000
#define EE   400000
#define HIDN 128
#define NH   8
#define NLYR 2
#define OUTC 32

// ---------------------------------------------------------------------------
// Scratch pool (static device memory; no allocations anywhere)
// ---------------------------------------------------------------------------
constexpr size_t ND128 = (size_t)ND * HIDN;
constexpr size_t NF128 = (size_t)NF * HIDN;

constexpr size_t OFF_XD   = 0;
constexpr size_t OFF_QD   = OFF_XD   + ND128;
constexpr size_t OFF_KTD  = OFF_QD   + ND128;
constexpr size_t OFF_VTD  = OFF_KTD  + ND128;
constexpr size_t OFF_AGGD = OFF_VTD  + ND128;
constexpr size_t OFF_TMPD = OFF_AGGD + ND128;
constexpr size_t OFF_XF   = OFF_TMPD + ND128;
constexpr size_t OFF_QF   = OFF_XF   + NF128;
constexpr size_t OFF_KTF  = OFF_QF   + NF128;
constexpr size_t OFF_VTF  = OFF_KTF  + NF128;
constexpr size_t OFF_AGGF = OFF_VTF  + NF128;
constexpr size_t OFF_TMPF = OFF_AGGF + NF128;
// folded fp32 weights
constexpr size_t OFF_WKE  = OFF_TMPF + NF128;          // 4*16384
constexpr size_t OFF_WVE  = OFF_WKE  + 4 * 16384;
constexpr size_t OFF_BKE  = OFF_WVE  + 4 * 16384;      // 4*128
constexpr size_t OFF_BVE  = OFF_BKE  + 4 * 128;
// tf32 hi/lo pre-split weights
constexpr size_t OFF_HQ   = OFF_BVE  + 4 * 128;        // 4*16384 each
constexpr size_t OFF_LQ   = OFF_HQ   + 4 * 16384;
constexpr size_t OFF_HK   = OFF_LQ   + 4 * 16384;
constexpr size_t OFF_LK   = OFF_HK   + 4 * 16384;
constexpr size_t OFF_HV   = OFF_LK   + 4 * 16384;
constexpr size_t OFF_LV   = OFF_HV   + 4 * 16384;
constexpr size_t OFF_HA   = OFF_LV   + 4 * 16384;
constexpr size_t OFF_LA   = OFF_HA   + 4 * 16384;
constexpr size_t OFF_HDI  = OFF_LA   + 4 * 16384;      // 16384 each
constexpr size_t OFF_LDI  = OFF_HDI  + 16384;
constexpr size_t OFF_HFI  = OFF_LDI  + 16384;
constexpr size_t OFF_LFI  = OFF_HFI  + 16384;
// CSR integer area (stored in float pool, cast)
constexpr size_t OFF_RPF  = OFF_LFI  + 16384;          // NF+1
constexpr size_t OFF_RPD  = OFF_RPF  + (NF + 1);       // ND+1
constexpr size_t OFF_CDF  = OFF_RPD  + (ND + 1);       // E (src list for df)
constexpr size_t OFF_CFD  = OFF_CDF  + EE;             // E (src list for fd)
constexpr size_t OFF_CNT  = OFF_CFD  + EE;             // NF
constexpr size_t OFF_CUR  = OFF_CNT  + NF;             // NF
constexpr size_t OFF_BSUM = OFF_CUR  + NF;             // 128
constexpr size_t POOL_SZ  = OFF_BSUM + 128;

__device__ __align__(256) float g_pool[POOL_SZ];

// ---------------------------------------------------------------------------
// Helpers
// ---------------------------------------------------------------------------
__device__ __forceinline__ float gelu_exact(float v) {
    return 0.5f * v * (1.0f + erff(v * 0.70710678118654752440f));
}
__device__ __forceinline__ unsigned tf32r(float x) {
    unsigned r;
    asm("cvt.rna.tf32.f32 %0, %1;" : "=r"(r) : "f"(x));
    return r;
}
__device__ __forceinline__ void split_tf32(float x, unsigned& hi, unsigned& lo) {
    hi = tf32r(x);
    lo = tf32r(x - __uint_as_float(hi));
}

#define MMA_TF32(d, a, b)                                                     \
    asm volatile(                                                             \
        "mma.sync.aligned.m16n8k8.row.col.f32.tf32.tf32.f32 "                 \
        "{%0,%1,%2,%3},{%4,%5,%6,%7},{%8,%9},{%0,%1,%2,%3};"                  \
        : "+f"((d)[0]), "+f"((d)[1]), "+f"((d)[2]), "+f"((d)[3])              \
        : "r"((a)[0]), "r"((a)[1]), "r"((a)[2]), "r"((a)[3]),                 \
          "r"((b)[0]), "r"((b)[1]))

__device__ __forceinline__ void cp16(unsigned dst, const void* src, bool pred) {
    if (pred)
        asm volatile("cp.async.cg.shared.global [%0], [%1], 16;"
                     :: "r"(dst), "l"(src));
}

// ---------------------------------------------------------------------------
// Pre-split a weight matrix into tf32 hi/lo (bit patterns stored as float)
// ---------------------------------------------------------------------------
__global__ void presplit(const float* __restrict__ W, float* __restrict__ Hi,
                         float* __restrict__ Lo, int n) {
    int i = blockIdx.x * blockDim.x + threadIdx.x;
    if (i >= n) return;
    unsigned h, l;
    split_tf32(W[i], h, l);
    Hi[i] = __uint_as_float(h);
    Lo[i] = __uint_as_float(l);
}

// ---------------------------------------------------------------------------
// Tensor-core GEMM, 3xTF32 split. B pre-split (hi/lo loaded directly).
//   C[y][N,128] = act(A[N,128] @ W[y] + bias[y]),  y = blockIdx.y
// 128x128 block tile, BK=8, 8 warps (warp tile 32x64), cp.async double buffer.
// ---------------------------------------------------------------------------
#define ASTR 12
#define BSTR 136

template <int RELU>
__global__ void __launch_bounds__(256)
gemm_tc(const float* __restrict__ A,
        const float* __restrict__ H0, const float* __restrict__ L0,
        const float* __restrict__ H1, const float* __restrict__ L1,
        const float* __restrict__ H2, const float* __restrict__ L2,
        const float* __restrict__ b0, const float* __restrict__ b1, const float* __restrict__ b2,
        float* __restrict__ C0, float* __restrict__ C1, float* __restrict__ C2,
        int N) {
    const float* WH   = (blockIdx.y == 0) ? H0 : (blockIdx.y == 1) ? H1 : H2;
    const float* WL   = (blockIdx.y == 0) ? L0 : (blockIdx.y == 1) ? L1 : L2;
    const float* bias = (blockIdx.y == 0) ? b0 : (blockIdx.y == 1) ? b1 : b2;
    float*       C    = (blockIdx.y == 0) ? C0 : (blockIdx.y == 1) ? C1 : C2;

    __shared__ __align__(16) float As[2][128 * ASTR];
    __shared__ __align__(16) float Bh[2][8 * BSTR];
    __shared__ __align__(16) float Bl[2][8 * BSTR];

    const int tid  = threadIdx.x;
    const int row0 = blockIdx.x * 128;
    const int lane = tid & 31, warp = tid >> 5;
    const int g = lane >> 2, c = lane & 3;
    const int m0 = (warp >> 1) * 32, n0 = (warp & 1) * 64;

    const int ar  = tid >> 1, ach = tid & 1;     // A: row, 8B-pair selector
    const int bk  = tid >> 5, bnc = tid & 31;    // B: k-row, 16B chunk
    const bool arok = row0 + ar < N;

    auto stage = [&](int buf, int k0) {
        cp16((unsigned)__cvta_generic_to_shared(&As[buf][ar * ASTR + ach * 4]),
             A + (size_t)(row0 + ar) * 128 + k0 + ach * 4, arok);
        cp16((unsigned)__cvta_generic_to_shared(&Bh[buf][bk * BSTR + bnc * 4]),
             WH + (size_t)(k0 + bk) * 128 + bnc * 4, true);
        cp16((unsigned)__cvta_generic_to_shared(&Bl[buf][bk * BSTR + bnc * 4]),
             WL + (size_t)(k0 + bk) * 128 + bnc * 4, true);
        asm volatile("cp.async.commit_group;");
    };

    float acc[2][8][4];
#pragma unroll
    for (int mi = 0; mi < 2; mi++)
#pragma unroll
        for (int ni = 0; ni < 8; ni++)
#pragma unroll
            for (int j = 0; j < 4; j++) acc[mi][ni][j] = 0.f;

    stage(0, 0);

    for (int it = 0; it < 16; it++) {
        if (it < 15) {
            stage((it + 1) & 1, (it + 1) * 8);
            asm volatile("cp.async.wait_group 1;");
        } else {
            asm volatile("cp.async.wait_group 0;");
        }
        __syncthreads();
        const float* Ab  = As[it & 1];
        const float* Bhh = Bh[it & 1];
        const float* Bll = Bl[it & 1];

        // A fragments (split in registers)
        unsigned ahi[2][4], alo[2][4];
#pragma unroll
        for (int mi = 0; mi < 2; mi++) {
            int rb = (m0 + mi * 16 + g) * ASTR;
            split_tf32(Ab[rb + c],                  ahi[mi][0], alo[mi][0]);
            split_tf32(Ab[rb + 8 * ASTR + c],       ahi[mi][1], alo[mi][1]);
            split_tf32(Ab[rb + c + 4],              ahi[mi][2], alo[mi][2]);
            split_tf32(Ab[rb + 8 * ASTR + c + 4],   ahi[mi][3], alo[mi][3]);
        }
#pragma unroll
        for (int ni = 0; ni < 8; ni++) {
            int bn = n0 + ni * 8 + g;
            unsigned bh[2], bl[2];
            bh[0] = __float_as_uint(Bhh[c * BSTR + bn]);
            bh[1] = __float_as_uint(Bhh[(c + 4) * BSTR + bn]);
            bl[0] = __float_as_uint(Bll[c * BSTR + bn]);
            bl[1] = __float_as_uint(Bll[(c + 4) * BSTR + bn]);
#pragma unroll
            for (int mi = 0; mi < 2; mi++) {
                MMA_TF32(acc[mi][ni], ahi[mi], bh);
                MMA_TF32(acc[mi][ni], ahi[mi], bl);
                MMA_TF32(acc[mi][ni], alo[mi], bh);
            }
        }
        __syncthreads();
    }

#pragma unroll
    for (int ni = 0; ni < 8; ni++) {
        int col = n0 + ni * 8 + 2 * c;
        float bb0 = bias[col], bb1 = bias[col + 1];
#pragma unroll
        for (int mi = 0; mi < 2; mi++) {
            int r = row0 + m0 + mi * 16 + g;
            float v0 = acc[mi][ni][0] + bb0, v1 = acc[mi][ni][1] + bb1;
            float v2 = acc[mi][ni][2] + bb0, v3 = acc[mi][ni][3] + bb1;
            if (RELU) {
                v0 = fmaxf(v0, 0.f); v1 = fmaxf(v1, 0.f);
                v2 = fmaxf(v2, 0.f); v3 = fmaxf(v3, 0.f);
            }
            if (r < N)     *(float2*)(C + (size_t)r * 128 + col)       = make_float2(v0, v1);
            if (r + 8 < N) *(float2*)(C + (size_t)(r + 8) * 128 + col) = make_float2(v2, v3);
        }
    }
}

// ---------------------------------------------------------------------------
// Fold relation transforms into projection weights (and priors into k)
// ---------------------------------------------------------------------------
__global__ void fold_weights(const float* __restrict__ Wk, const float* __restrict__ bk,
                             const float* __restrict__ Wv, const float* __restrict__ bv,
                             const float* __restrict__ a_rel, const float* __restrict__ m_rel,
                             const float* __restrict__ p_rel,
                             float* __restrict__ WkE, float* __restrict__ bkE,
                             float* __restrict__ WvE, float* __restrict__ bvE) {
    int idx = blockIdx.x * blockDim.x + threadIdx.x;
    if (idx >= 4 * 129 * 128) return;
    int combo = idx / (129 * 128);
    int rem   = idx % (129 * 128);
    int r  = rem >> 7;
    int he = rem & 127;
    int h = he >> 4, e = he & 15;
    const float* a = a_rel + ((size_t)combo * 8 + h) * 256 + e;
    const float* m = m_rel + ((size_t)combo * 8 + h) * 256 + e;
    float ps = p_rel[combo * 8 + h] * 0.25f;  // p / sqrt(D)

    const float* kr = (r < 128) ? (Wk + (size_t)combo * 16384 + (size_t)r * 128 + h * 16)
                                : (bk + (size_t)combo * 128 + h * 16);
    const float* vr = (r < 128) ? (Wv + (size_t)combo * 16384 + (size_t)r * 128 + h * 16)
                                : (bv + (size_t)combo * 128 + h * 16);
    float sk = 0.f, sv = 0.f;
#pragma unroll
    for (int d = 0; d < 16; d++) {
        sk += kr[d] * a[d * 16];
        sv += vr[d] * m[d * 16];
    }
    sk *= ps;
    if (r < 128) {
        WkE[(size_t)combo * 16384 + (size_t)r * 128 + he] = sk;
        WvE[(size_t)combo * 16384 + (size_t)r * 128 + he] = sv;
    } else {
        bkE[combo * 128 + he] = sk;
        bvE[combo * 128 + he] = sv;
    }
}

// ---------------------------------------------------------------------------
// CSR build kernels
// ---------------------------------------------------------------------------
__global__ void k_hist(const int* __restrict__ dst, int* __restrict__ cnt) {
    int i = blockIdx.x * blockDim.x + threadIdx.x;
    if (i < EE) atomicAdd(&cnt[dst[i]], 1);
}

__global__ void k_bsum(const int* __restrict__ cnt, int* __restrict__ bsum, int n) {
    __shared__ int sh[512];
    int t = threadIdx.x, g = blockIdx.x * 512 + t;
    sh[t] = (g < n) ? cnt[g] : 0;
    __syncthreads();
#pragma unroll
    for (int off = 256; off; off >>= 1) {
        if (t < off) sh[t] += sh[t + off];
        __syncthreads();
    }
    if (t == 0) bsum[blockIdx.x] = sh[0];
}

__global__ void k_scan_bsum(int* __restrict__ bsum, int nb) {
    if (threadIdx.x == 0 && blockIdx.x == 0) {
        int run = 0;
        for (int i = 0; i < nb; i++) { int t = bsum[i]; bsum[i] = run; run += t; }
    }
}

__global__ void k_rowptr(const int* __restrict__ cnt, const int* __restrict__ bsum,
                         int* __restrict__ rp, int n) {
    __shared__ int sh[512];
    int t = threadIdx.x, g = blockIdx.x * 512 + t;
    int v = (g < n) ? cnt[g] : 0;
    sh[t] = v;
    __syncthreads();
    for (int off = 1; off < 512; off <<= 1) {
        int u = (t >= off) ? sh[t - off] : 0;
        __syncthreads();
        sh[t] += u;
        __syncthreads();
    }
    if (g < n) rp[g] = bsum[blockIdx.x] + sh[t] - v;   // exclusive prefix
    if (g == 0 && blockIdx.x == 0) rp[n] = EE;
}

__global__ void k_fill(const int* __restrict__ src, const int* __restrict__ dst,
                       const int* __restrict__ rp, int* __restrict__ cur,
                       int* __restrict__ colx) {
    int i = blockIdx.x * blockDim.x + threadIdx.x;
    if (i >= EE) return;
    int d = dst[i];
    int pos = rp[d] + atomicAdd(&cur[d], 1);
    colx[pos] = src[i];
}

// ---------------------------------------------------------------------------
// CSR edge aggregation: one warp per dst node.
//   lane = head*4 + sub  (4 lanes per head, 4 dims each; lane*4 = offset)
// Computes softmax-weighted message sum, normalizes, applies GELU, writes agg.
// ---------------------------------------------------------------------------
__global__ void edge_agg_csr(const int* __restrict__ rp, const int* __restrict__ col,
                             const float* __restrict__ q, const float* __restrict__ kt,
                             const float* __restrict__ vt, float* __restrict__ agg,
                             int Ndst) {
    int w = (blockIdx.x * blockDim.x + threadIdx.x) >> 5;
    if (w >= Ndst) return;
    int lane = threadIdx.x & 31;

    float4 q4 = *(const float4*)(q + (size_t)w * 128 + lane * 4);
    float4 acc = make_float4(0.f, 0.f, 0.f, 0.f);
    float ssum = 0.f;
    int beg = rp[w], end = rp[w + 1];

    if (beg < end) {
        int s = col[beg];
        float4 k4 = __ldg((const float4*)(kt + (size_t)s * 128 + lane * 4));
        float4 v4 = __ldg((const float4*)(vt + (size_t)s * 128 + lane * 4));
        for (int i = beg; i < end; i++) {
            // prefetch next edge before the shfl/exp dependency chain
            float4 k4n, v4n;
            if (i + 1 < end) {
                int sn = col[i + 1];
                k4n = __ldg((const float4*)(kt + (size_t)sn * 128 + lane * 4));
                v4n = __ldg((const float4*)(vt + (size_t)sn * 128 + lane * 4));
            }
            float p = q4.x * k4.x + q4.y * k4.y + q4.z * k4.z + q4.w * k4.w;
            p += __shfl_xor_sync(0xffffffffu, p, 1);
            p += __shfl_xor_sync(0xffffffffu, p, 2);
            float ex = __expf(fminf(p, 80.f));
            ssum += ex;
            acc.x += ex * v4.x; acc.y += ex * v4.y;
            acc.z += ex * v4.z; acc.w += ex * v4.w;
            k4 = k4n; v4 = v4n;
        }
    }
    float inv = __frcp_rn(ssum + 1e-16f);
    acc.x = gelu_exact(acc.x * inv);
    acc.y = gelu_exact(acc.y * inv);
    acc.z = gelu_exact(acc.z * inv);
    acc.w = gelu_exact(acc.w * inv);
    *(float4*)(agg + (size_t)w * 128 + lane * 4) = acc;
}

// ---------------------------------------------------------------------------
// Skip-gate + residual + LayerNorm.  One block (128 thr) per node, in-place x.
// ---------------------------------------------------------------------------
__global__ void post_ln(const float* __restrict__ o, float* __restrict__ x,
                        const float* __restrict__ skip_lt,
                        const float* __restrict__ g, const float* __restrict__ b,
                        int N) {
    int n = blockIdx.x;
    if (n >= N) return;
    int t = threadIdx.x;
    float sk = 1.f / (1.f + __expf(-skip_lt[0]));
    size_t base = (size_t)n * 128 + t;
    float xv = x[base];
    float ov = sk * o[base] + (1.f - sk) * xv;
    float y = xv + ov;

    __shared__ float red[4];
    float s = y;
#pragma unroll
    for (int off = 16; off; off >>= 1) s += __shfl_xor_sync(0xffffffff, s, off);
    if ((t & 31) == 0) red[t >> 5] = s;
    __syncthreads();
    float mean = (red[0] + red[1] + red[2] + red[3]) * (1.f / 128.f);
    __syncthreads();

    float dy = y - mean;
    float s2 = dy * dy;
#pragma unroll
    for (int off = 16; off; off >>= 1) s2 += __shfl_xor_sync(0xffffffff, s2, off);
    if ((t & 31) == 0) red[t >> 5] = s2;
    __syncthreads();
    float var = (red[0] + red[1] + red[2] + red[3]) * (1.f / 128.f);

    x[base] = dy * rsqrtf(var + 1e-5f) * g[t] + b[t];
}

// ---------------------------------------------------------------------------
// Output head: out[ND,32] = x[ND,128] @ W[128,32] + b
// ---------------------------------------------------------------------------
__global__ void out_gemm(const float* __restrict__ x, const float* __restrict__ W,
                         const float* __restrict__ b, float* __restrict__ out) {
    size_t idx = (size_t)blockIdx.x * blockDim.x + threadIdx.x;
    if (idx >= (size_t)ND * OUTC) return;
    int n = (int)(idx >> 5), c = (int)(idx & 31);
    const float* xr = x + (size_t)n * 128;
    float s = b[c];
#pragma unroll 8
    for (int k = 0; k < 128; k++) s += xr[k] * W[k * OUTC + c];
    out[idx] = s;
}

// ---------------------------------------------------------------------------
// Host orchestration
// ---------------------------------------------------------------------------
static inline int cdiv(long long a, long long b) { return (int)((a + b - 1) / b); }

extern "C" void kernel_launch(void* const* d_in, const int* in_sizes, int n_in,
                              void* d_out, int out_size) {
    (void)in_sizes; (void)n_in; (void)out_size;

    const float* x_device = (const float*)d_in[0];
    const float* x_feature = (const float*)d_in[1];
    const int* e_df_src = (const int*)d_in[2];
    const int* e_df_dst = (const int*)d_in[3];
    const int* e_fd_src = (const int*)d_in[4];
    const int* e_fd_dst = (const int*)d_in[5];
    const float* W_dev_in = (const float*)d_in[6];
    const float* b_dev_in = (const float*)d_in[7];
    const float* W_feat_in = (const float*)d_in[8];
    const float* b_feat_in = (const float*)d_in[9];
    const float* Wk = (const float*)d_in[10];
    const float* bk = (const float*)d_in[11];
    const float* Wq = (const float*)d_in[12];
    const float* bq = (const float*)d_in[13];
    const float* Wv = (const float*)d_in[14];
    const float* bv = (const float*)d_in[15];
    const float* a_rel = (const float*)d_in[16];
    const float* m_rel = (const float*)d_in[17];
    const float* p_rel = (const float*)d_in[18];
    const float* Wa = (const float*)d_in[19];
    const float* ba = (const float*)d_in[20];
    const float* skip = (const float*)d_in[21];
    const float* ln_g = (const float*)d_in[22];
    const float* ln_b = (const float*)d_in[23];
    const float* W_out = (const float*)d_in[24];
    const float* b_out = (const float*)d_in[25];
    float* out = (float*)d_out;

    float* pool = nullptr;
    cudaGetSymbolAddress((void**)&pool, g_pool);

    float* xd   = pool + OFF_XD;   float* xf   = pool + OFF_XF;
    float* qd   = pool + OFF_QD;   float* qf   = pool + OFF_QF;
    float* ktd  = pool + OFF_KTD;  float* ktf  = pool + OFF_KTF;
    float* vtd  = pool + OFF_VTD;  float* vtf  = pool + OFF_VTF;
    float* aggd = pool + OFF_AGGD; float* aggf = pool + OFF_AGGF;
    float* tmpd = pool + OFF_TMPD; float* tmpf = pool + OFF_TMPF;
    float* WkE  = pool + OFF_WKE;  float* WvE  = pool + OFF_WVE;
    float* bkE  = pool + OFF_BKE;  float* bvE  = pool + OFF_BVE;
    float* HQ = pool + OFF_HQ, *LQ = pool + OFF_LQ;
    float* HK = pool + OFF_HK, *LK = pool + OFF_LK;
    float* HV = pool + OFF_HV, *LV = pool + OFF_LV;
    float* HA = pool + OFF_HA, *LA = pool + OFF_LA;
    float* HDI = pool + OFF_HDI, *LDI = pool + OFF_LDI;
    float* HFI = pool + OFF_HFI, *LFI = pool + OFF_LFI;
    int* rpf  = (int*)(pool + OFF_RPF);
    int* rpd  = (int*)(pool + OFF_RPD);
    int* cdf  = (int*)(pool + OFF_CDF);
    int* cfd  = (int*)(pool + OFF_CFD);
    int* cnt  = (int*)(pool + OFF_CNT);
    int* cur  = (int*)(pool + OFF_CUR);
    int* bsum = (int*)(pool + OFF_BSUM);

    const int gBlkD = cdiv(ND, 128), gBlkF = cdiv(NF, 128);
    const int eBlk = cdiv(EE, 256);

    // ---- CSR build: device->feature (dst = feature, NF rows) ----
    {
        const int nb = cdiv(NF, 512);
        cudaMemsetAsync(cnt, 0, NF * sizeof(int), 0);
        k_hist<<<eBlk, 256>>>(e_df_dst, cnt);
        k_bsum<<<nb, 512>>>(cnt, bsum, NF);
        k_scan_bsum<<<1, 32>>>(bsum, nb);
        k_rowptr<<<nb, 512>>>(cnt, bsum, rpf, NF);
        cudaMemsetAsync(cur, 0, NF * sizeof(int), 0);
        k_fill<<<eBlk, 256>>>(e_df_src, e_df_dst, rpf, cur, cdf);
    }
    // ---- CSR build: feature->device (dst = device, ND rows) ----
    {
        const int nb = cdiv(ND, 512);
        cudaMemsetAsync(cnt, 0, ND * sizeof(int), 0);
        k_hist<<<eBlk, 256>>>(e_fd_dst, cnt);
        k_bsum<<<nb, 512>>>(cnt, bsum, ND);
        k_scan_bsum<<<1, 32>>>(bsum, nb);
        k_rowptr<<<nb, 512>>>(cnt, bsum, rpd, ND);
        cudaMemsetAsync(cur, 0, ND * sizeof(int), 0);
        k_fill<<<eBlk, 256>>>(e_fd_src, e_fd_dst, rpd, cur, cfd);
    }

    // ---- fold relation transforms, then pre-split all GEMM weights ----
    fold_weights<<<cdiv(4 * 129 * 128, 256), 256>>>(Wk, bk, Wv, bv, a_rel, m_rel, p_rel,
                                                    WkE, bkE, WvE, bvE);
    presplit<<<cdiv(16384, 256), 256>>>(W_dev_in, HDI, LDI, 16384);
    presplit<<<cdiv(16384, 256), 256>>>(W_feat_in, HFI, LFI, 16384);
    presplit<<<cdiv(4 * 16384, 256), 256>>>(Wq, HQ, LQ, 4 * 16384);
    presplit<<<cdiv(4 * 16384, 256), 256>>>(WkE, HK, LK, 4 * 16384);
    presplit<<<cdiv(4 * 16384, 256), 256>>>(WvE, HV, LV, 4 * 16384);
    presplit<<<cdiv(4 * 16384, 256), 256>>>(Wa, HA, LA, 4 * 16384);

    // ---- input projections + ReLU ----
    gemm_tc<1><<<dim3(gBlkD, 1), 256>>>(x_device, HDI, LDI, HDI, LDI, HDI, LDI,
                                        b_dev_in, b_dev_in, b_dev_in, xd, xd, xd, ND);
    gemm_tc<1><<<dim3(gBlkF, 1), 256>>>(x_feature, HFI, LFI, HFI, LFI, HFI, LFI,
                                        b_feat_in, b_feat_in, b_feat_in, xf, xf, xf, NF);

    for (int l = 0; l < NLYR; l++) {
        const int c0 = l * 2 + 0, c1 = l * 2 + 1;
        const size_t wo0 = (size_t)c0 * 16384, wo1 = (size_t)c1 * 16384;
        const size_t bo0 = (size_t)c0 * 128,   bo1 = (size_t)c1 * 128;

        // fused q/kt/vt projections (gridDim.y = 3)
        gemm_tc<0><<<dim3(gBlkD, 3), 256>>>(xd,
            HQ + wo0, LQ + wo0, HK + wo0, LK + wo0, HV + wo0, LV + wo0,
            bq + bo0, bkE + bo0, bvE + bo0, qd, ktd, vtd, ND);
        gemm_tc<0><<<dim3(gBlkF, 3), 256>>>(xf,
            HQ + wo1, LQ + wo1, HK + wo1, LK + wo1, HV + wo1, LV + wo1,
            bq + bo1, bkE + bo1, bvE + bo1, qf, ktf, vtf, NF);

        // edge aggregation (CSR gather; normalize + gelu fused at write)
        edge_agg_csr<<<cdiv((long long)NF * 32, 256), 256>>>(rpf, cdf, qf, ktd, vtd, aggf, NF);
        edge_agg_csr<<<cdiv((long long)ND * 32, 256), 256>>>(rpd, cfd, qd, ktf, vtf, aggd, ND);

        // Wa GEMM, then skip + residual + LN
        gemm_tc<0><<<dim3(gBlkD, 1), 256>>>(aggd, HA + wo0, LA + wo0, HA + wo0, LA + wo0,
                                            HA + wo0, LA + wo0, ba + bo0, ba + bo0, ba + bo0,
                                            tmpd, tmpd, tmpd, ND);
        gemm_tc<0><<<dim3(gBlkF, 1), 256>>>(aggf, HA + wo1, LA + wo1, HA + wo1, LA + wo1,
                                            HA + wo1, LA + wo1, ba + bo1, ba + bo1, ba + bo1,
                                            tmpf, tmpf, tmpf, NF);
        post_ln<<<ND, 128>>>(tmpd, xd, skip + c0, ln_g + bo0, ln_b + bo0, ND);
        post_ln<<<NF, 128>>>(tmpf, xf, skip + c1, ln_g + bo1, ln_b + bo1, NF);
    }

    out_gemm<<<cdiv((long long)ND * OUTC, 256), 256>>>(xd, W_out, b_out, out);
}

// round 6
// speedup vs baseline: 2.5727x; 1.2052x over previous
#include <cuda_runtime.h>
#include <cuda_bf16.h>
#include <math.h>

// ---------------------------------------------------------------------------
// Problem constants
// ---------------------------------------------------------------------------
#define ND   20000
#define NF   50000
#define EE   400000
#define HIDN 128
#define NH   8
#define NLYR 2
#define OUTC 32

// ---------------------------------------------------------------------------
// Scratch pool (static device memory; no allocations anywhere)
// ---------------------------------------------------------------------------
constexpr size_t ND128 = (size_t)ND * HIDN;
constexpr size_t NF128 = (size_t)NF * HIDN;

constexpr size_t OFF_XD   = 0;
constexpr size_t OFF_QD   = OFF_XD   + ND128;
constexpr size_t OFF_KTD  = OFF_QD   + ND128;
constexpr size_t OFF_VTD  = OFF_KTD  + ND128;
constexpr size_t OFF_AGGD = OFF_VTD  + ND128;
constexpr size_t OFF_XF   = OFF_AGGD + ND128;
constexpr size_t OFF_QF   = OFF_XF   + NF128;
constexpr size_t OFF_KTF  = OFF_QF   + NF128;
constexpr size_t OFF_VTF  = OFF_KTF  + NF128;
constexpr size_t OFF_AGGF = OFF_VTF  + NF128;
// folded fp32 weights
constexpr size_t OFF_WKE  = OFF_AGGF + NF128;          // 4*16384
constexpr size_t OFF_WVE  = OFF_WKE  + 4 * 16384;
constexpr size_t OFF_BKE  = OFF_WVE  + 4 * 16384;      // 4*128
constexpr size_t OFF_BVE  = OFF_BKE  + 4 * 128;
// bf16 hi/lo pre-split transposed weights (bf16 stored, region sized in floats/2)
constexpr size_t OFF_HQ   = OFF_BVE  + 4 * 128;        // 4*16384 bf16 = 4*8192 floats
constexpr size_t OFF_LQ   = OFF_HQ   + 4 * 8192;
constexpr size_t OFF_HK   = OFF_LQ   + 4 * 8192;
constexpr size_t OFF_LK   = OFF_HK   + 4 * 8192;
constexpr size_t OFF_HV   = OFF_LK   + 4 * 8192;
constexpr size_t OFF_LV   = OFF_HV   + 4 * 8192;
constexpr size_t OFF_HA   = OFF_LV   + 4 * 8192;
constexpr size_t OFF_LA   = OFF_HA   + 4 * 8192;
constexpr size_t OFF_HDI  = OFF_LA   + 4 * 8192;       // 8192 floats each
constexpr size_t OFF_LDI  = OFF_HDI  + 8192;
constexpr size_t OFF_HFI  = OFF_LDI  + 8192;
constexpr size_t OFF_LFI  = OFF_HFI  + 8192;
// CSR integer area (stored in float pool, cast)
constexpr size_t OFF_RPF  = OFF_LFI  + 8192;           // NF+1
constexpr size_t OFF_RPD  = OFF_RPF  + (NF + 1);       // ND+1
constexpr size_t OFF_CDF  = OFF_RPD  + (ND + 1);       // E
constexpr size_t OFF_CFD  = OFF_CDF  + EE;             // E
constexpr size_t OFF_CNT  = OFF_CFD  + EE;             // NF
constexpr size_t OFF_CUR  = OFF_CNT  + NF;             // NF
constexpr size_t OFF_BSUM = OFF_CUR  + NF;             // 128
constexpr size_t POOL_SZ  = OFF_BSUM + 128;

__device__ __align__(256) float g_pool[POOL_SZ];

// ---------------------------------------------------------------------------
// Helpers
// ---------------------------------------------------------------------------
__device__ __forceinline__ float gelu_exact(float v) {
    return 0.5f * v * (1.0f + erff(v * 0.70710678118654752440f));
}

// bf16x2 pack: {lo half = a, hi half = b}
__device__ __forceinline__ unsigned pack_bf16x2(float a, float b) {
    unsigned r;
    asm("cvt.rn.bf16x2.f32 %0, %1, %2;" : "=r"(r) : "f"(b), "f"(a));
    return r;
}
// split a float2 (consecutive k) into hi/lo packed bf16x2
__device__ __forceinline__ void split_pair(float2 p, unsigned& hi, unsigned& lo) {
    unsigned h = pack_bf16x2(p.x, p.y);
    unsigned hx, hy;
    asm("prmt.b32 %0, 0, %1, 0x5400;" : "=r"(hx) : "r"(h));  // low bf16 -> f32 bits
    asm("prmt.b32 %0, 0, %1, 0x7600;" : "=r"(hy) : "r"(h));  // high bf16 -> f32 bits
    float lx = p.x - __uint_as_float(hx);
    float ly = p.y - __uint_as_float(hy);
    lo = pack_bf16x2(lx, ly);
    hi = h;
}

#define MMA_BF16(d, a, b0v, b1v)                                              \
    asm volatile(                                                             \
        "mma.sync.aligned.m16n8k16.row.col.f32.bf16.bf16.f32 "                \
        "{%0,%1,%2,%3},{%4,%5,%6,%7},{%8,%9},{%0,%1,%2,%3};"                  \
        : "+f"((d)[0]), "+f"((d)[1]), "+f"((d)[2]), "+f"((d)[3])              \
        : "r"((a)[0]), "r"((a)[1]), "r"((a)[2]), "r"((a)[3]),                 \
          "r"(b0v), "r"(b1v))

__device__ __forceinline__ void cp16(unsigned dst, const void* src, bool pred) {
    if (pred)
        asm volatile("cp.async.cg.shared.global [%0], [%1], 16;"
                     :: "r"(dst), "l"(src));
}

// ---------------------------------------------------------------------------
// Pre-split weight W[k][n] (fp32) -> transposed bf16 hi/lo Bt[n][k]
// ---------------------------------------------------------------------------
__global__ void bsplit(const float* __restrict__ W, __nv_bfloat16* __restrict__ Hi,
                       __nv_bfloat16* __restrict__ Lo, int nmats) {
    int i = blockIdx.x * blockDim.x + threadIdx.x;
    if (i >= nmats * 16384) return;
    int mat = i >> 14, rem = i & 16383;
    int n = rem >> 7, k = rem & 127;       // output coords
    float x = W[(size_t)mat * 16384 + k * 128 + n];
    __nv_bfloat16 h = __float2bfloat16(x);
    float hf = __bfloat162float(h);
    Hi[i] = h;
    Lo[i] = __float2bfloat16(x - hf);
}

// ---------------------------------------------------------------------------
// Tensor-core GEMM, 3xBF16 split (hi*hi + hi*lo + lo*hi), fp32 accumulate.
//   MODE 0: C = A@W + bias
//   MODE 1: C = relu(A@W + bias)
//   MODE 2: fused skip+residual+LayerNorm:  X = LN(X + sk*(A@W+bias) + (1-sk)*X)
// 128x128 block tile, BK=16, 8 warps (warp tile 32x64), cp.async double buffer.
// ---------------------------------------------------------------------------
#define ASTR 20   // floats per A row (16 + 4 pad): 80B, 16B-aligned, conflict-free
#define BSTR 24   // bf16 per B row (16 + 8 pad): 48B, 16B-aligned, conflict-free

template <int MODE>
__global__ void __launch_bounds__(256)
gemm_tc(const float* __restrict__ A,
        const __nv_bfloat16* __restrict__ H0, const __nv_bfloat16* __restrict__ L0,
        const __nv_bfloat16* __restrict__ H1, const __nv_bfloat16* __restrict__ L1,
        const __nv_bfloat16* __restrict__ H2, const __nv_bfloat16* __restrict__ L2,
        const float* __restrict__ b0, const float* __restrict__ b1, const float* __restrict__ b2,
        float* __restrict__ C0, float* __restrict__ C1, float* __restrict__ C2,
        int N,
        float* __restrict__ X, const float* __restrict__ skipv,
        const float* __restrict__ lng, const float* __restrict__ lnb) {
    const __nv_bfloat16* WH = (blockIdx.y == 0) ? H0 : (blockIdx.y == 1) ? H1 : H2;
    const __nv_bfloat16* WL = (blockIdx.y == 0) ? L0 : (blockIdx.y == 1) ? L1 : L2;
    const float* bias = (blockIdx.y == 0) ? b0 : (blockIdx.y == 1) ? b1 : b2;
    float*       C    = (blockIdx.y == 0) ? C0 : (blockIdx.y == 1) ? C1 : C2;

    __shared__ __align__(16) float        As[2][128 * ASTR];
    __shared__ __align__(16) __nv_bfloat16 Bh[2][128 * BSTR];
    __shared__ __align__(16) __nv_bfloat16 Bl[2][128 * BSTR];
    __shared__ float rs[128], rq[128];

    const int tid  = threadIdx.x;
    const int row0 = blockIdx.x * 128;
    const int lane = tid & 31, warp = tid >> 5;
    const int g = lane >> 2, c = lane & 3;
    const int m0 = (warp >> 1) * 32, n0 = (warp & 1) * 64;

    const int bn_ld = tid >> 1, bhalf = tid & 1;   // B stage coords

    auto stage = [&](int buf, int k0) {
#pragma unroll
        for (int i = 0; i < 2; i++) {
            int id = tid + i * 256;          // 0..511
            int r = id >> 2, ch = id & 3;    // A row, 16B chunk
            cp16((unsigned)__cvta_generic_to_shared(&As[buf][r * ASTR + ch * 4]),
                 A + (size_t)(row0 + r) * 128 + k0 + ch * 4, row0 + r < N);
        }
        cp16((unsigned)__cvta_generic_to_shared(&Bh[buf][bn_ld * BSTR + bhalf * 8]),
             WH + (size_t)bn_ld * 128 + k0 + bhalf * 8, true);
        cp16((unsigned)__cvta_generic_to_shared(&Bl[buf][bn_ld * BSTR + bhalf * 8]),
             WL + (size_t)bn_ld * 128 + k0 + bhalf * 8, true);
        asm volatile("cp.async.commit_group;");
    };

    float acc[2][8][4];
#pragma unroll
    for (int mi = 0; mi < 2; mi++)
#pragma unroll
        for (int ni = 0; ni < 8; ni++)
#pragma unroll
            for (int j = 0; j < 4; j++) acc[mi][ni][j] = 0.f;

    stage(0, 0);

    for (int it = 0; it < 8; it++) {
        if (it < 7) {
            stage((it + 1) & 1, (it + 1) * 16);
            asm volatile("cp.async.wait_group 1;");
        } else {
            asm volatile("cp.async.wait_group 0;");
        }
        __syncthreads();
        const float* Ab          = As[it & 1];
        const __nv_bfloat16* Bhh = Bh[it & 1];
        const __nv_bfloat16* Bll = Bl[it & 1];

        // A fragments: split fp32 -> bf16 hi/lo in registers
        unsigned ahi[2][4], alo[2][4];
#pragma unroll
        for (int mi = 0; mi < 2; mi++) {
            int rb = (m0 + mi * 16 + g) * ASTR;
            split_pair(*(const float2*)&Ab[rb + 2 * c],                ahi[mi][0], alo[mi][0]);
            split_pair(*(const float2*)&Ab[rb + 8 * ASTR + 2 * c],     ahi[mi][1], alo[mi][1]);
            split_pair(*(const float2*)&Ab[rb + 2 * c + 8],            ahi[mi][2], alo[mi][2]);
            split_pair(*(const float2*)&Ab[rb + 8 * ASTR + 2 * c + 8], ahi[mi][3], alo[mi][3]);
        }
#pragma unroll
        for (int ni = 0; ni < 8; ni++) {
            int bn = n0 + ni * 8 + g;
            unsigned bh0 = *(const unsigned*)&Bhh[bn * BSTR + 2 * c];
            unsigned bh1 = *(const unsigned*)&Bhh[bn * BSTR + 2 * c + 8];
            unsigned bl0 = *(const unsigned*)&Bll[bn * BSTR + 2 * c];
            unsigned bl1 = *(const unsigned*)&Bll[bn * BSTR + 2 * c + 8];
#pragma unroll
            for (int mi = 0; mi < 2; mi++) {
                MMA_BF16(acc[mi][ni], ahi[mi], bh0, bh1);
                MMA_BF16(acc[mi][ni], ahi[mi], bl0, bl1);
                MMA_BF16(acc[mi][ni], alo[mi], bh0, bh1);
            }
        }
        __syncthreads();
    }

    if (MODE != 2) {
        // plain / relu epilogue
#pragma unroll
        for (int ni = 0; ni < 8; ni++) {
            int col = n0 + ni * 8 + 2 * c;
            float bb0 = bias[col], bb1 = bias[col + 1];
#pragma unroll
            for (int mi = 0; mi < 2; mi++) {
                int r = row0 + m0 + mi * 16 + g;
                float v0 = acc[mi][ni][0] + bb0, v1 = acc[mi][ni][1] + bb1;
                float v2 = acc[mi][ni][2] + bb0, v3 = acc[mi][ni][3] + bb1;
                if (MODE == 1) {
                    v0 = fmaxf(v0, 0.f); v1 = fmaxf(v1, 0.f);
                    v2 = fmaxf(v2, 0.f); v3 = fmaxf(v3, 0.f);
                }
                if (r < N)     *(float2*)(C + (size_t)r * 128 + col)       = make_float2(v0, v1);
                if (r + 8 < N) *(float2*)(C + (size_t)(r + 8) * 128 + col) = make_float2(v2, v3);
            }
        }
    } else {
        // fused skip + residual + LayerNorm epilogue (in-place on X)
        float sk = 1.f / (1.f + __expf(-skipv[0]));
        float tms = 2.f - sk;
        if (tid < 128) { rs[tid] = 0.f; rq[tid] = 0.f; }
        __syncthreads();

        float psum[2][2] = {{0.f, 0.f}, {0.f, 0.f}};
        float psq[2][2]  = {{0.f, 0.f}, {0.f, 0.f}};
#pragma unroll
        for (int ni = 0; ni < 8; ni++) {
            int col = n0 + ni * 8 + 2 * c;
            float bb0 = bias[col], bb1 = bias[col + 1];
#pragma unroll
            for (int mi = 0; mi < 2; mi++) {
                int r = row0 + m0 + mi * 16 + g;
                if (r < N) {
                    float2 xv = *(float2*)(X + (size_t)r * 128 + col);
                    float y0 = tms * xv.x + sk * (acc[mi][ni][0] + bb0);
                    float y1 = tms * xv.y + sk * (acc[mi][ni][1] + bb1);
                    *(float2*)(X + (size_t)r * 128 + col) = make_float2(y0, y1);
                    psum[mi][0] += y0 + y1;
                    psq[mi][0]  += y0 * y0 + y1 * y1;
                }
                if (r + 8 < N) {
                    float2 xv = *(float2*)(X + (size_t)(r + 8) * 128 + col);
                    float y2 = tms * xv.x + sk * (acc[mi][ni][2] + bb0);
                    float y3 = tms * xv.y + sk * (acc[mi][ni][3] + bb1);
                    *(float2*)(X + (size_t)(r + 8) * 128 + col) = make_float2(y2, y3);
                    psum[mi][1] += y2 + y3;
                    psq[mi][1]  += y2 * y2 + y3 * y3;
                }
            }
        }
        // quad-reduce (lanes differ only in c) then SMEM accumulate
#pragma unroll
        for (int mi = 0; mi < 2; mi++)
#pragma unroll
            for (int hh = 0; hh < 2; hh++) {
                float s = psum[mi][hh], q = psq[mi][hh];
                s += __shfl_xor_sync(0xffffffffu, s, 1);
                s += __shfl_xor_sync(0xffffffffu, s, 2);
                q += __shfl_xor_sync(0xffffffffu, q, 1);
                q += __shfl_xor_sync(0xffffffffu, q, 2);
                if (c == 0) {
                    int rl = m0 + mi * 16 + g + hh * 8;
                    atomicAdd(&rs[rl], s);
                    atomicAdd(&rq[rl], q);
                }
            }
        __syncthreads();

#pragma unroll
        for (int ni = 0; ni < 8; ni++) {
            int col = n0 + ni * 8 + 2 * c;
            float g0 = lng[col], g1 = lng[col + 1];
            float h0 = lnb[col], h1 = lnb[col + 1];
#pragma unroll
            for (int mi = 0; mi < 2; mi++) {
#pragma unroll
                for (int hh = 0; hh < 2; hh++) {
                    int rl = m0 + mi * 16 + g + hh * 8;
                    int r = row0 + rl;
                    if (r < N) {
                        float mean = rs[rl] * (1.f / 128.f);
                        float var  = rq[rl] * (1.f / 128.f) - mean * mean;
                        float rstd = rsqrtf(var + 1e-5f);
                        float2 yv = *(float2*)(X + (size_t)r * 128 + col);
                        float o0 = (yv.x - mean) * rstd * g0 + h0;
                        float o1 = (yv.y - mean) * rstd * g1 + h1;
                        *(float2*)(X + (size_t)r * 128 + col) = make_float2(o0, o1);
                    }
                }
            }
        }
    }
}

// ---------------------------------------------------------------------------
// Fold relation transforms into projection weights (and priors into k)
// ---------------------------------------------------------------------------
__global__ void fold_weights(const float* __restrict__ Wk, const float* __restrict__ bk,
                             const float* __restrict__ Wv, const float* __restrict__ bv,
                             const float* __restrict__ a_rel, const float* __restrict__ m_rel,
                             const float* __restrict__ p_rel,
                             float* __restrict__ WkE, float* __restrict__ bkE,
                             float* __restrict__ WvE, float* __restrict__ bvE) {
    int idx = blockIdx.x * blockDim.x + threadIdx.x;
    if (idx >= 4 * 129 * 128) return;
    int combo = idx / (129 * 128);
    int rem   = idx % (129 * 128);
    int r  = rem >> 7;
    int he = rem & 127;
    int h = he >> 4, e = he & 15;
    const float* a = a_rel + ((size_t)combo * 8 + h) * 256 + e;
    const float* m = m_rel + ((size_t)combo * 8 + h) * 256 + e;
    float ps = p_rel[combo * 8 + h] * 0.25f;  // p / sqrt(D)

    const float* kr = (r < 128) ? (Wk + (size_t)combo * 16384 + (size_t)r * 128 + h * 16)
                                : (bk + (size_t)combo * 128 + h * 16);
    const float* vr = (r < 128) ? (Wv + (size_t)combo * 16384 + (size_t)r * 128 + h * 16)
                                : (bv + (size_t)combo * 128 + h * 16);
    float sk = 0.f, sv = 0.f;
#pragma unroll
    for (int d = 0; d < 16; d++) {
        sk += kr[d] * a[d * 16];
        sv += vr[d] * m[d * 16];
    }
    sk *= ps;
    if (r < 128) {
        WkE[(size_t)combo * 16384 + (size_t)r * 128 + he] = sk;
        WvE[(size_t)combo * 16384 + (size_t)r * 128 + he] = sv;
    } else {
        bkE[combo * 128 + he] = sk;
        bvE[combo * 128 + he] = sv;
    }
}

// ---------------------------------------------------------------------------
// CSR build kernels
// ---------------------------------------------------------------------------
__global__ void k_hist(const int* __restrict__ dst, int* __restrict__ cnt) {
    int i = blockIdx.x * blockDim.x + threadIdx.x;
    if (i < EE) atomicAdd(&cnt[dst[i]], 1);
}

__global__ void k_bsum(const int* __restrict__ cnt, int* __restrict__ bsum, int n) {
    __shared__ int sh[512];
    int t = threadIdx.x, g = blockIdx.x * 512 + t;
    sh[t] = (g < n) ? cnt[g] : 0;
    __syncthreads();
#pragma unroll
    for (int off = 256; off; off >>= 1) {
        if (t < off) sh[t] += sh[t + off];
        __syncthreads();
    }
    if (t == 0) bsum[blockIdx.x] = sh[0];
}

__global__ void k_scan_bsum(int* __restrict__ bsum, int nb) {
    if (threadIdx.x == 0 && blockIdx.x == 0) {
        int run = 0;
        for (int i = 0; i < nb; i++) { int t = bsum[i]; bsum[i] = run; run += t; }
    }
}

__global__ void k_rowptr(const int* __restrict__ cnt, const int* __restrict__ bsum,
                         int* __restrict__ rp, int n) {
    __shared__ int sh[512];
    int t = threadIdx.x, g = blockIdx.x * 512 + t;
    int v = (g < n) ? cnt[g] : 0;
    sh[t] = v;
    __syncthreads();
    for (int off = 1; off < 512; off <<= 1) {
        int u = (t >= off) ? sh[t - off] : 0;
        __syncthreads();
        sh[t] += u;
        __syncthreads();
    }
    if (g < n) rp[g] = bsum[blockIdx.x] + sh[t] - v;   // exclusive prefix
    if (g == 0 && blockIdx.x == 0) rp[n] = EE;
}

__global__ void k_fill(const int* __restrict__ src, const int* __restrict__ dst,
                       const int* __restrict__ rp, int* __restrict__ cur,
                       int* __restrict__ colx) {
    int i = blockIdx.x * blockDim.x + threadIdx.x;
    if (i >= EE) return;
    int d = dst[i];
    int pos = rp[d] + atomicAdd(&cur[d], 1);
    colx[pos] = src[i];
}

// ---------------------------------------------------------------------------
// CSR edge aggregation: one warp per dst node.
// ---------------------------------------------------------------------------
__global__ void edge_agg_csr(const int* __restrict__ rp, const int* __restrict__ col,
                             const float* __restrict__ q, const float* __restrict__ kt,
                             const float* __restrict__ vt, float* __restrict__ agg,
                             int Ndst) {
    int w = (blockIdx.x * blockDim.x + threadIdx.x) >> 5;
    if (w >= Ndst) return;
    int lane = threadIdx.x & 31;

    float4 q4 = *(const float4*)(q + (size_t)w * 128 + lane * 4);
    float4 acc = make_float4(0.f, 0.f, 0.f, 0.f);
    float ssum = 0.f;
    int beg = rp[w], end = rp[w + 1];

    if (beg < end) {
        int s = col[beg];
        float4 k4 = __ldg((const float4*)(kt + (size_t)s * 128 + lane * 4));
        float4 v4 = __ldg((const float4*)(vt + (size_t)s * 128 + lane * 4));
        for (int i = beg; i < end; i++) {
            float4 k4n, v4n;
            if (i + 1 < end) {
                int sn = col[i + 1];
                k4n = __ldg((const float4*)(kt + (size_t)sn * 128 + lane * 4));
                v4n = __ldg((const float4*)(vt + (size_t)sn * 128 + lane * 4));
            }
            float p = q4.x * k4.x + q4.y * k4.y + q4.z * k4.z + q4.w * k4.w;
            p += __shfl_xor_sync(0xffffffffu, p, 1);
            p += __shfl_xor_sync(0xffffffffu, p, 2);
            float ex = __expf(fminf(p, 80.f));
            ssum += ex;
            acc.x += ex * v4.x; acc.y += ex * v4.y;
            acc.z += ex * v4.z; acc.w += ex * v4.w;
            k4 = k4n; v4 = v4n;
        }
    }
    float inv = __frcp_rn(ssum + 1e-16f);
    acc.x = gelu_exact(acc.x * inv);
    acc.y = gelu_exact(acc.y * inv);
    acc.z = gelu_exact(acc.z * inv);
    acc.w = gelu_exact(acc.w * inv);
    *(float4*)(agg + (size_t)w * 128 + lane * 4) = acc;
}

// ---------------------------------------------------------------------------
// Output head: out[ND,32] = x[ND,128] @ W[128,32] + b
// ---------------------------------------------------------------------------
__global__ void out_gemm(const float* __restrict__ x, const float* __restrict__ W,
                         const float* __restrict__ b, float* __restrict__ out) {
    size_t idx = (size_t)blockIdx.x * blockDim.x + threadIdx.x;
    if (idx >= (size_t)ND * OUTC) return;
    int n = (int)(idx >> 5), c = (int)(idx & 31);
    const float* xr = x + (size_t)n * 128;
    float s = b[c];
#pragma unroll 8
    for (int k = 0; k < 128; k++) s += xr[k] * W[k * OUTC + c];
    out[idx] = s;
}

// ---------------------------------------------------------------------------
// Host orchestration
// ---------------------------------------------------------------------------
static inline int cdiv(long long a, long long b) { return (int)((a + b - 1) / b); }

extern "C" void kernel_launch(void* const* d_in, const int* in_sizes, int n_in,
                              void* d_out, int out_size) {
    (void)in_sizes; (void)n_in; (void)out_size;

    const float* x_device = (const float*)d_in[0];
    const float* x_feature = (const float*)d_in[1];
    const int* e_df_src = (const int*)d_in[2];
    const int* e_df_dst = (const int*)d_in[3];
    const int* e_fd_src = (const int*)d_in[4];
    const int* e_fd_dst = (const int*)d_in[5];
    const float* W_dev_in = (const float*)d_in[6];
    const float* b_dev_in = (const float*)d_in[7];
    const float* W_feat_in = (const float*)d_in[8];
    const float* b_feat_in = (const float*)d_in[9];
    const float* Wk = (const float*)d_in[10];
    const float* bk = (const float*)d_in[11];
    const float* Wq = (const float*)d_in[12];
    const float* bq = (const float*)d_in[13];
    const float* Wv = (const float*)d_in[14];
    const float* bv = (const float*)d_in[15];
    const float* a_rel = (const float*)d_in[16];
    const float* m_rel = (const float*)d_in[17];
    const float* p_rel = (const float*)d_in[18];
    const float* Wa = (const float*)d_in[19];
    const float* ba = (const float*)d_in[20];
    const float* skip = (const float*)d_in[21];
    const float* ln_g = (const float*)d_in[22];
    const float* ln_b = (const float*)d_in[23];
    const float* W_out = (const float*)d_in[24];
    const float* b_out = (const float*)d_in[25];
    float* out = (float*)d_out;

    float* pool = nullptr;
    cudaGetSymbolAddress((void**)&pool, g_pool);

    float* xd   = pool + OFF_XD;   float* xf   = pool + OFF_XF;
    float* qd   = pool + OFF_QD;   float* qf   = pool + OFF_QF;
    float* ktd  = pool + OFF_KTD;  float* ktf  = pool + OFF_KTF;
    float* vtd  = pool + OFF_VTD;  float* vtf  = pool + OFF_VTF;
    float* aggd = pool + OFF_AGGD; float* aggf = pool + OFF_AGGF;
    float* WkE  = pool + OFF_WKE;  float* WvE  = pool + OFF_WVE;
    float* bkE  = pool + OFF_BKE;  float* bvE  = pool + OFF_BVE;
    __nv_bfloat16* HQ = (__nv_bfloat16*)(pool + OFF_HQ);
    __nv_bfloat16* LQ = (__nv_bfloat16*)(pool + OFF_LQ);
    __nv_bfloat16* HK = (__nv_bfloat16*)(pool + OFF_HK);
    __nv_bfloat16* LK = (__nv_bfloat16*)(pool + OFF_LK);
    __nv_bfloat16* HV = (__nv_bfloat16*)(pool + OFF_HV);
    __nv_bfloat16* LV = (__nv_bfloat16*)(pool + OFF_LV);
    __nv_bfloat16* HA = (__nv_bfloat16*)(pool + OFF_HA);
    __nv_bfloat16* LA = (__nv_bfloat16*)(pool + OFF_LA);
    __nv_bfloat16* HDI = (__nv_bfloat16*)(pool + OFF_HDI);
    __nv_bfloat16* LDI = (__nv_bfloat16*)(pool + OFF_LDI);
    __nv_bfloat16* HFI = (__nv_bfloat16*)(pool + OFF_HFI);
    __nv_bfloat16* LFI = (__nv_bfloat16*)(pool + OFF_LFI);
    int* rpf  = (int*)(pool + OFF_RPF);
    int* rpd  = (int*)(pool + OFF_RPD);
    int* cdf  = (int*)(pool + OFF_CDF);
    int* cfd  = (int*)(pool + OFF_CFD);
    int* cnt  = (int*)(pool + OFF_CNT);
    int* cur  = (int*)(pool + OFF_CUR);
    int* bsum = (int*)(pool + OFF_BSUM);

    const int gBlkD = cdiv(ND, 128), gBlkF = cdiv(NF, 128);
    const int eBlk = cdiv(EE, 256);

    // ---- CSR build: device->feature (dst = feature, NF rows) ----
    {
        const int nb = cdiv(NF, 512);
        cudaMemsetAsync(cnt, 0, NF * sizeof(int), 0);
        k_hist<<<eBlk, 256>>>(e_df_dst, cnt);
        k_bsum<<<nb, 512>>>(cnt, bsum, NF);
        k_scan_bsum<<<1, 32>>>(bsum, nb);
        k_rowptr<<<nb, 512>>>(cnt, bsum, rpf, NF);
        cudaMemsetAsync(cur, 0, NF * sizeof(int), 0);
        k_fill<<<eBlk, 256>>>(e_df_src, e_df_dst, rpf, cur, cdf);
    }
    // ---- CSR build: feature->device (dst = device, ND rows) ----
    {
        const int nb = cdiv(ND, 512);
        cudaMemsetAsync(cnt, 0, ND * sizeof(int), 0);
        k_hist<<<eBlk, 256>>>(e_fd_dst, cnt);
        k_bsum<<<nb, 512>>>(cnt, bsum, ND);
        k_scan_bsum<<<1, 32>>>(bsum, nb);
        k_rowptr<<<nb, 512>>>(cnt, bsum, rpd, ND);
        cudaMemsetAsync(cur, 0, ND * sizeof(int), 0);
        k_fill<<<eBlk, 256>>>(e_fd_src, e_fd_dst, rpd, cur, cfd);
    }

    // ---- fold relation transforms, then pre-split all GEMM weights (bf16) ----
    fold_weights<<<cdiv(4 * 129 * 128, 256), 256>>>(Wk, bk, Wv, bv, a_rel, m_rel, p_rel,
                                                    WkE, bkE, WvE, bvE);
    bsplit<<<cdiv(16384, 256), 256>>>(W_dev_in, HDI, LDI, 1);
    bsplit<<<cdiv(16384, 256), 256>>>(W_feat_in, HFI, LFI, 1);
    bsplit<<<cdiv(4 * 16384, 256), 256>>>(Wq, HQ, LQ, 4);
    bsplit<<<cdiv(4 * 16384, 256), 256>>>(WkE, HK, LK, 4);
    bsplit<<<cdiv(4 * 16384, 256), 256>>>(WvE, HV, LV, 4);
    bsplit<<<cdiv(4 * 16384, 256), 256>>>(Wa, HA, LA, 4);

    // ---- input projections + ReLU ----
    gemm_tc<1><<<dim3(gBlkD, 1), 256>>>(x_device, HDI, LDI, HDI, LDI, HDI, LDI,
                                        b_dev_in, b_dev_in, b_dev_in, xd, xd, xd, ND,
                                        nullptr, nullptr, nullptr, nullptr);
    gemm_tc<1><<<dim3(gBlkF, 1), 256>>>(x_feature, HFI, LFI, HFI, LFI, HFI, LFI,
                                        b_feat_in, b_feat_in, b_feat_in, xf, xf, xf, NF,
                                        nullptr, nullptr, nullptr, nullptr);

    for (int l = 0; l < NLYR; l++) {
        const int c0 = l * 2 + 0, c1 = l * 2 + 1;
        const size_t wo = (size_t)c0 * 16384, w1 = (size_t)c1 * 16384;
        const size_t bo0 = (size_t)c0 * 128,  bo1 = (size_t)c1 * 128;

        // fused q/kt/vt projections (gridDim.y = 3)
        gemm_tc<0><<<dim3(gBlkD, 3), 256>>>(xd,
            HQ + wo, LQ + wo, HK + wo, LK + wo, HV + wo, LV + wo,
            bq + bo0, bkE + bo0, bvE + bo0, qd, ktd, vtd, ND,
            nullptr, nullptr, nullptr, nullptr);
        gemm_tc<0><<<dim3(gBlkF, 3), 256>>>(xf,
            HQ + w1, LQ + w1, HK + w1, LK + w1, HV + w1, LV + w1,
            bq + bo1, bkE + bo1, bvE + bo1, qf, ktf, vtf, NF,
            nullptr, nullptr, nullptr, nullptr);

        // edge aggregation (CSR gather; normalize + gelu fused at write)
        edge_agg_csr<<<cdiv((long long)NF * 32, 256), 256>>>(rpf, cdf, qf, ktd, vtd, aggf, NF);
        edge_agg_csr<<<cdiv((long long)ND * 32, 256), 256>>>(rpd, cfd, qd, ktf, vtf, aggd, ND);

        // Wa GEMM with fused skip + residual + LayerNorm (in-place on x)
        gemm_tc<2><<<dim3(gBlkD, 1), 256>>>(aggd, HA + wo, LA + wo, HA + wo, LA + wo,
                                            HA + wo, LA + wo, ba + bo0, ba + bo0, ba + bo0,
                                            nullptr, nullptr, nullptr, ND,
                                            xd, skip + c0, ln_g + bo0, ln_b + bo0);
        gemm_tc<2><<<dim3(gBlkF, 1), 256>>>(aggf, HA + w1, LA + w1, HA + w1, LA + w1,
                                            HA + w1, LA + w1, ba + bo1, ba + bo1, ba + bo1,
                                            nullptr, nullptr, nullptr, NF,
                                            xf, skip + c1, ln_g + bo1, ln_b + bo1);
    }

    out_gemm<<<cdiv((long long)ND * OUTC, 256), 256>>>(xd, W_out, b_out, out);
}

// round 7
// speedup vs baseline: 2.8365x; 1.1026x over previous
#include <cuda_runtime.h>
#include <cuda_bf16.h>
#include <cuda_fp16.h>
#include <math.h>

// ---------------------------------------------------------------------------
// Problem constants
// ---------------------------------------------------------------------------
#define ND   20000
#define NF   50000
#define EE   400000
#define HIDN 128
#define NH   8
#define NLYR 2
#define OUTC 32

// ---------------------------------------------------------------------------
// Scratch pool (static device memory; no allocations anywhere)
// ---------------------------------------------------------------------------
constexpr size_t ND128 = (size_t)ND * HIDN;
constexpr size_t NF128 = (size_t)NF * HIDN;

constexpr size_t OFF_XD   = 0;
constexpr size_t OFF_QD   = OFF_XD   + ND128;
constexpr size_t OFF_KTVD = OFF_QD   + ND128;   // ND*256 half == ND128 floats
constexpr size_t OFF_AGGD = OFF_KTVD + ND128;
constexpr size_t OFF_XF   = OFF_AGGD + ND128;
constexpr size_t OFF_QF   = OFF_XF   + NF128;
constexpr size_t OFF_KTVF = OFF_QF   + NF128;   // NF*256 half
constexpr size_t OFF_AGGF = OFF_KTVF + NF128;
// folded fp32 weights
constexpr size_t OFF_WKE  = OFF_AGGF + NF128;          // 4*16384
constexpr size_t OFF_WVE  = OFF_WKE  + 4 * 16384;
constexpr size_t OFF_BKE  = OFF_WVE  + 4 * 16384;      // 4*128
constexpr size_t OFF_BVE  = OFF_BKE  + 4 * 128;
// bf16 hi/lo pre-split transposed weights (bf16 stored, sized floats/2)
constexpr size_t OFF_HQ   = OFF_BVE  + 4 * 128;        // 4*8192 floats each
constexpr size_t OFF_LQ   = OFF_HQ   + 4 * 8192;
constexpr size_t OFF_HK   = OFF_LQ   + 4 * 8192;
constexpr size_t OFF_LK   = OFF_HK   + 4 * 8192;
constexpr size_t OFF_HV   = OFF_LK   + 4 * 8192;
constexpr size_t OFF_LV   = OFF_HV   + 4 * 8192;
constexpr size_t OFF_HA   = OFF_LV   + 4 * 8192;
constexpr size_t OFF_LA   = OFF_HA   + 4 * 8192;
constexpr size_t OFF_HDI  = OFF_LA   + 4 * 8192;       // 8192 each
constexpr size_t OFF_LDI  = OFF_HDI  + 8192;
constexpr size_t OFF_HFI  = OFF_LDI  + 8192;
constexpr size_t OFF_LFI  = OFF_HFI  + 8192;
// CSR integer area (stored in float pool, cast)
constexpr size_t OFF_RPF  = OFF_LFI  + 8192;           // NF+1
constexpr size_t OFF_RPD  = OFF_RPF  + (NF + 1);       // ND+1
constexpr size_t OFF_CDF  = OFF_RPD  + (ND + 1);       // E
constexpr size_t OFF_CFD  = OFF_CDF  + EE;             // E
constexpr size_t OFF_CNT  = OFF_CFD  + EE;             // NF
constexpr size_t OFF_CUR  = OFF_CNT  + NF;             // NF
constexpr size_t OFF_BSUM = OFF_CUR  + NF;             // 128
constexpr size_t POOL_SZ  = OFF_BSUM + 128;

__device__ __align__(256) float g_pool[POOL_SZ];

// ---------------------------------------------------------------------------
// Helpers
// ---------------------------------------------------------------------------
__device__ __forceinline__ float gelu_exact(float v) {
    return 0.5f * v * (1.0f + erff(v * 0.70710678118654752440f));
}

__device__ __forceinline__ unsigned pack_bf16x2(float a, float b) {
    unsigned r;
    asm("cvt.rn.bf16x2.f32 %0, %1, %2;" : "=r"(r) : "f"(b), "f"(a));
    return r;
}
__device__ __forceinline__ void split_pair(float2 p, unsigned& hi, unsigned& lo) {
    unsigned h = pack_bf16x2(p.x, p.y);
    unsigned hx, hy;
    asm("prmt.b32 %0, 0, %1, 0x5400;" : "=r"(hx) : "r"(h));
    asm("prmt.b32 %0, 0, %1, 0x7600;" : "=r"(hy) : "r"(h));
    float lx = p.x - __uint_as_float(hx);
    float ly = p.y - __uint_as_float(hy);
    lo = pack_bf16x2(lx, ly);
    hi = h;
}

#define MMA_BF16(d, a, b0v, b1v)                                              \
    asm volatile(                                                             \
        "mma.sync.aligned.m16n8k16.row.col.f32.bf16.bf16.f32 "                \
        "{%0,%1,%2,%3},{%4,%5,%6,%7},{%8,%9},{%0,%1,%2,%3};"                  \
        : "+f"((d)[0]), "+f"((d)[1]), "+f"((d)[2]), "+f"((d)[3])              \
        : "r"((a)[0]), "r"((a)[1]), "r"((a)[2]), "r"((a)[3]),                 \
          "r"(b0v), "r"(b1v))

__device__ __forceinline__ void cp16(unsigned dst, const void* src, bool pred) {
    if (pred)
        asm volatile("cp.async.cg.shared.global [%0], [%1], 16;"
                     :: "r"(dst), "l"(src));
}

// ---------------------------------------------------------------------------
// Pre-split weight W[k][n] (fp32) -> transposed bf16 hi/lo Bt[n][k]
// ---------------------------------------------------------------------------
__global__ void bsplit(const float* __restrict__ W, __nv_bfloat16* __restrict__ Hi,
                       __nv_bfloat16* __restrict__ Lo, int nmats) {
    int i = blockIdx.x * blockDim.x + threadIdx.x;
    if (i >= nmats * 16384) return;
    int mat = i >> 14, rem = i & 16383;
    int n = rem >> 7, k = rem & 127;
    float x = W[(size_t)mat * 16384 + k * 128 + n];
    __nv_bfloat16 h = __float2bfloat16(x);
    Hi[i] = h;
    Lo[i] = __float2bfloat16(x - __bfloat162float(h));
}

// ---------------------------------------------------------------------------
// Tensor-core GEMM, 3xBF16 split (hi*hi + hi*lo + lo*hi), fp32 accumulate.
//   MODE 0: y==0 -> fp32 C0;  y==1 -> fp16 kt into packed ktv;  y==2 -> fp16 vt
//   MODE 1: C0 = relu(A@W + bias), fp32
//   MODE 2: fused skip+residual+LayerNorm:  X = LN(X + sk*(A@W+bias) + (1-sk)*X)
// 128x128 block tile, BK=16, 8 warps (warp tile 32x64), cp.async double buffer.
// Packed ktv layout: per node, 32 quads of {kt[4] halves, vt[4] halves} = 256 halves.
// ---------------------------------------------------------------------------
#define ASTR 20
#define BSTR 24

template <int MODE>
__global__ void __launch_bounds__(256)
gemm_tc(const float* __restrict__ A,
        const __nv_bfloat16* __restrict__ H0, const __nv_bfloat16* __restrict__ L0,
        const __nv_bfloat16* __restrict__ H1, const __nv_bfloat16* __restrict__ L1,
        const __nv_bfloat16* __restrict__ H2, const __nv_bfloat16* __restrict__ L2,
        const float* __restrict__ b0, const float* __restrict__ b1, const float* __restrict__ b2,
        float* __restrict__ C0, __half* __restrict__ Ch,
        int N,
        float* __restrict__ X, const float* __restrict__ skipv,
        const float* __restrict__ lng, const float* __restrict__ lnb) {
    const __nv_bfloat16* WH = (blockIdx.y == 0) ? H0 : (blockIdx.y == 1) ? H1 : H2;
    const __nv_bfloat16* WL = (blockIdx.y == 0) ? L0 : (blockIdx.y == 1) ? L1 : L2;
    const float* bias = (blockIdx.y == 0) ? b0 : (blockIdx.y == 1) ? b1 : b2;

    __shared__ __align__(16) float        As[2][128 * ASTR];
    __shared__ __align__(16) __nv_bfloat16 Bh[2][128 * BSTR];
    __shared__ __align__(16) __nv_bfloat16 Bl[2][128 * BSTR];
    __shared__ float rs[128], rq[128];

    const int tid  = threadIdx.x;
    const int row0 = blockIdx.x * 128;
    const int lane = tid & 31, warp = tid >> 5;
    const int g = lane >> 2, c = lane & 3;
    const int m0 = (warp >> 1) * 32, n0 = (warp & 1) * 64;

    const int bn_ld = tid >> 1, bhalf = tid & 1;

    auto stage = [&](int buf, int k0) {
#pragma unroll
        for (int i = 0; i < 2; i++) {
            int id = tid + i * 256;
            int r = id >> 2, ch = id & 3;
            cp16((unsigned)__cvta_generic_to_shared(&As[buf][r * ASTR + ch * 4]),
                 A + (size_t)(row0 + r) * 128 + k0 + ch * 4, row0 + r < N);
        }
        cp16((unsigned)__cvta_generic_to_shared(&Bh[buf][bn_ld * BSTR + bhalf * 8]),
             WH + (size_t)bn_ld * 128 + k0 + bhalf * 8, true);
        cp16((unsigned)__cvta_generic_to_shared(&Bl[buf][bn_ld * BSTR + bhalf * 8]),
             WL + (size_t)bn_ld * 128 + k0 + bhalf * 8, true);
        asm volatile("cp.async.commit_group;");
    };

    float acc[2][8][4];
#pragma unroll
    for (int mi = 0; mi < 2; mi++)
#pragma unroll
        for (int ni = 0; ni < 8; ni++)
#pragma unroll
            for (int j = 0; j < 4; j++) acc[mi][ni][j] = 0.f;

    stage(0, 0);

    for (int it = 0; it < 8; it++) {
        if (it < 7) {
            stage((it + 1) & 1, (it + 1) * 16);
            asm volatile("cp.async.wait_group 1;");
        } else {
            asm volatile("cp.async.wait_group 0;");
        }
        __syncthreads();
        const float* Ab          = As[it & 1];
        const __nv_bfloat16* Bhh = Bh[it & 1];
        const __nv_bfloat16* Bll = Bl[it & 1];

        unsigned ahi[2][4], alo[2][4];
#pragma unroll
        for (int mi = 0; mi < 2; mi++) {
            int rb = (m0 + mi * 16 + g) * ASTR;
            split_pair(*(const float2*)&Ab[rb + 2 * c],                ahi[mi][0], alo[mi][0]);
            split_pair(*(const float2*)&Ab[rb + 8 * ASTR + 2 * c],     ahi[mi][1], alo[mi][1]);
            split_pair(*(const float2*)&Ab[rb + 2 * c + 8],            ahi[mi][2], alo[mi][2]);
            split_pair(*(const float2*)&Ab[rb + 8 * ASTR + 2 * c + 8], ahi[mi][3], alo[mi][3]);
        }
#pragma unroll
        for (int ni = 0; ni < 8; ni++) {
            int bn = n0 + ni * 8 + g;
            unsigned bh0 = *(const unsigned*)&Bhh[bn * BSTR + 2 * c];
            unsigned bh1 = *(const unsigned*)&Bhh[bn * BSTR + 2 * c + 8];
            unsigned bl0 = *(const unsigned*)&Bll[bn * BSTR + 2 * c];
            unsigned bl1 = *(const unsigned*)&Bll[bn * BSTR + 2 * c + 8];
#pragma unroll
            for (int mi = 0; mi < 2; mi++) {
                MMA_BF16(acc[mi][ni], ahi[mi], bh0, bh1);
                MMA_BF16(acc[mi][ni], ahi[mi], bl0, bl1);
                MMA_BF16(acc[mi][ni], alo[mi], bh0, bh1);
            }
        }
        __syncthreads();
    }

    if (MODE == 0 && blockIdx.y != 0) {
        // fp16 packed kt/vt epilogue
        const int voff = (blockIdx.y == 2) ? 4 : 0;
#pragma unroll
        for (int ni = 0; ni < 8; ni++) {
            int col = n0 + ni * 8 + 2 * c;
            float bb0 = bias[col], bb1 = bias[col + 1];
            int po = ((col >> 2) << 3) + (col & 3) + voff;
#pragma unroll
            for (int mi = 0; mi < 2; mi++) {
                int r = row0 + m0 + mi * 16 + g;
                if (r < N)
                    *(__half2*)(Ch + (size_t)r * 256 + po) =
                        __floats2half2_rn(acc[mi][ni][0] + bb0, acc[mi][ni][1] + bb1);
                if (r + 8 < N)
                    *(__half2*)(Ch + (size_t)(r + 8) * 256 + po) =
                        __floats2half2_rn(acc[mi][ni][2] + bb0, acc[mi][ni][3] + bb1);
            }
        }
    } else if (MODE != 2) {
#pragma unroll
        for (int ni = 0; ni < 8; ni++) {
            int col = n0 + ni * 8 + 2 * c;
            float bb0 = bias[col], bb1 = bias[col + 1];
#pragma unroll
            for (int mi = 0; mi < 2; mi++) {
                int r = row0 + m0 + mi * 16 + g;
                float v0 = acc[mi][ni][0] + bb0, v1 = acc[mi][ni][1] + bb1;
                float v2 = acc[mi][ni][2] + bb0, v3 = acc[mi][ni][3] + bb1;
                if (MODE == 1) {
                    v0 = fmaxf(v0, 0.f); v1 = fmaxf(v1, 0.f);
                    v2 = fmaxf(v2, 0.f); v3 = fmaxf(v3, 0.f);
                }
                if (r < N)     *(float2*)(C0 + (size_t)r * 128 + col)       = make_float2(v0, v1);
                if (r + 8 < N) *(float2*)(C0 + (size_t)(r + 8) * 128 + col) = make_float2(v2, v3);
            }
        }
    } else {
        // fused skip + residual + LayerNorm epilogue (in-place on X)
        float sk = 1.f / (1.f + __expf(-skipv[0]));
        float tms = 2.f - sk;
        if (tid < 128) { rs[tid] = 0.f; rq[tid] = 0.f; }
        __syncthreads();

        float psum[2][2] = {{0.f, 0.f}, {0.f, 0.f}};
        float psq[2][2]  = {{0.f, 0.f}, {0.f, 0.f}};
#pragma unroll
        for (int ni = 0; ni < 8; ni++) {
            int col = n0 + ni * 8 + 2 * c;
            float bb0 = bias[col], bb1 = bias[col + 1];
#pragma unroll
            for (int mi = 0; mi < 2; mi++) {
                int r = row0 + m0 + mi * 16 + g;
                if (r < N) {
                    float2 xv = *(float2*)(X + (size_t)r * 128 + col);
                    float y0 = tms * xv.x + sk * (acc[mi][ni][0] + bb0);
                    float y1 = tms * xv.y + sk * (acc[mi][ni][1] + bb1);
                    *(float2*)(X + (size_t)r * 128 + col) = make_float2(y0, y1);
                    psum[mi][0] += y0 + y1;
                    psq[mi][0]  += y0 * y0 + y1 * y1;
                }
                if (r + 8 < N) {
                    float2 xv = *(float2*)(X + (size_t)(r + 8) * 128 + col);
                    float y2 = tms * xv.x + sk * (acc[mi][ni][2] + bb0);
                    float y3 = tms * xv.y + sk * (acc[mi][ni][3] + bb1);
                    *(float2*)(X + (size_t)(r + 8) * 128 + col) = make_float2(y2, y3);
                    psum[mi][1] += y2 + y3;
                    psq[mi][1]  += y2 * y2 + y3 * y3;
                }
            }
        }
#pragma unroll
        for (int mi = 0; mi < 2; mi++)
#pragma unroll
            for (int hh = 0; hh < 2; hh++) {
                float s = psum[mi][hh], q = psq[mi][hh];
                s += __shfl_xor_sync(0xffffffffu, s, 1);
                s += __shfl_xor_sync(0xffffffffu, s, 2);
                q += __shfl_xor_sync(0xffffffffu, q, 1);
                q += __shfl_xor_sync(0xffffffffu, q, 2);
                if (c == 0) {
                    int rl = m0 + mi * 16 + g + hh * 8;
                    atomicAdd(&rs[rl], s);
                    atomicAdd(&rq[rl], q);
                }
            }
        __syncthreads();

#pragma unroll
        for (int ni = 0; ni < 8; ni++) {
            int col = n0 + ni * 8 + 2 * c;
            float g0 = lng[col], g1 = lng[col + 1];
            float h0 = lnb[col], h1 = lnb[col + 1];
#pragma unroll
            for (int mi = 0; mi < 2; mi++) {
#pragma unroll
                for (int hh = 0; hh < 2; hh++) {
                    int rl = m0 + mi * 16 + g + hh * 8;
                    int r = row0 + rl;
                    if (r < N) {
                        float mean = rs[rl] * (1.f / 128.f);
                        float var  = rq[rl] * (1.f / 128.f) - mean * mean;
                        float rstd = rsqrtf(var + 1e-5f);
                        float2 yv = *(float2*)(X + (size_t)r * 128 + col);
                        float o0 = (yv.x - mean) * rstd * g0 + h0;
                        float o1 = (yv.y - mean) * rstd * g1 + h1;
                        *(float2*)(X + (size_t)r * 128 + col) = make_float2(o0, o1);
                    }
                }
            }
        }
    }
}

// ---------------------------------------------------------------------------
// Fold relation transforms into projection weights (and priors into k)
// ---------------------------------------------------------------------------
__global__ void fold_weights(const float* __restrict__ Wk, const float* __restrict__ bk,
                             const float* __restrict__ Wv, const float* __restrict__ bv,
                             const float* __restrict__ a_rel, const float* __restrict__ m_rel,
                             const float* __restrict__ p_rel,
                             float* __restrict__ WkE, float* __restrict__ bkE,
                             float* __restrict__ WvE, float* __restrict__ bvE) {
    int idx = blockIdx.x * blockDim.x + threadIdx.x;
    if (idx >= 4 * 129 * 128) return;
    int combo = idx / (129 * 128);
    int rem   = idx % (129 * 128);
    int r  = rem >> 7;
    int he = rem & 127;
    int h = he >> 4, e = he & 15;
    const float* a = a_rel + ((size_t)combo * 8 + h) * 256 + e;
    const float* m = m_rel + ((size_t)combo * 8 + h) * 256 + e;
    float ps = p_rel[combo * 8 + h] * 0.25f;

    const float* kr = (r < 128) ? (Wk + (size_t)combo * 16384 + (size_t)r * 128 + h * 16)
                                : (bk + (size_t)combo * 128 + h * 16);
    const float* vr = (r < 128) ? (Wv + (size_t)combo * 16384 + (size_t)r * 128 + h * 16)
                                : (bv + (size_t)combo * 128 + h * 16);
    float sk = 0.f, sv = 0.f;
#pragma unroll
    for (int d = 0; d < 16; d++) {
        sk += kr[d] * a[d * 16];
        sv += vr[d] * m[d * 16];
    }
    sk *= ps;
    if (r < 128) {
        WkE[(size_t)combo * 16384 + (size_t)r * 128 + he] = sk;
        WvE[(size_t)combo * 16384 + (size_t)r * 128 + he] = sv;
    } else {
        bkE[combo * 128 + he] = sk;
        bvE[combo * 128 + he] = sv;
    }
}

// ---------------------------------------------------------------------------
// CSR build kernels
// ---------------------------------------------------------------------------
__global__ void k_hist(const int* __restrict__ dst, int* __restrict__ cnt) {
    int i = blockIdx.x * blockDim.x + threadIdx.x;
    if (i < EE) atomicAdd(&cnt[dst[i]], 1);
}

__global__ void k_bsum(const int* __restrict__ cnt, int* __restrict__ bsum, int n) {
    __shared__ int sh[512];
    int t = threadIdx.x, g = blockIdx.x * 512 + t;
    sh[t] = (g < n) ? cnt[g] : 0;
    __syncthreads();
#pragma unroll
    for (int off = 256; off; off >>= 1) {
        if (t < off) sh[t] += sh[t + off];
        __syncthreads();
    }
    if (t == 0) bsum[blockIdx.x] = sh[0];
}

// 1-block exclusive scan over up to 128 block sums
__global__ void k_scan_bsum(int* __restrict__ bsum, int nb) {
    __shared__ int sh[128];
    int t = threadIdx.x;
    int v = (t < nb) ? bsum[t] : 0;
    sh[t] = v;
    __syncthreads();
#pragma unroll
    for (int off = 1; off < 128; off <<= 1) {
        int u = (t >= off) ? sh[t - off] : 0;
        __syncthreads();
        sh[t] += u;
        __syncthreads();
    }
    if (t < nb) bsum[t] = sh[t] - v;   // exclusive
}

__global__ void k_rowptr(const int* __restrict__ cnt, const int* __restrict__ bsum,
                         int* __restrict__ rp, int n) {
    __shared__ int sh[512];
    int t = threadIdx.x, g = blockIdx.x * 512 + t;
    int v = (g < n) ? cnt[g] : 0;
    sh[t] = v;
    __syncthreads();
    for (int off = 1; off < 512; off <<= 1) {
        int u = (t >= off) ? sh[t - off] : 0;
        __syncthreads();
        sh[t] += u;
        __syncthreads();
    }
    if (g < n) rp[g] = bsum[blockIdx.x] + sh[t] - v;
    if (g == 0 && blockIdx.x == 0) rp[n] = EE;
}

__global__ void k_fill(const int* __restrict__ src, const int* __restrict__ dst,
                       const int* __restrict__ rp, int* __restrict__ cur,
                       int* __restrict__ colx) {
    int i = blockIdx.x * blockDim.x + threadIdx.x;
    if (i >= EE) return;
    int d = dst[i];
    int pos = rp[d] + atomicAdd(&cur[d], 1);
    colx[pos] = src[i];
}

// ---------------------------------------------------------------------------
// CSR edge aggregation: one warp per dst node; fp16 packed kt/vt gather.
// Each lane loads ONE uint4 = {kt quad (4 half), vt quad (4 half)} per edge.
// ---------------------------------------------------------------------------
__global__ void edge_agg_csr(const int* __restrict__ rp, const int* __restrict__ col,
                             const float* __restrict__ q, const __half* __restrict__ ktv,
                             float* __restrict__ agg, int Ndst) {
    int w = (blockIdx.x * blockDim.x + threadIdx.x) >> 5;
    if (w >= Ndst) return;
    int lane = threadIdx.x & 31;

    float4 q4 = *(const float4*)(q + (size_t)w * 128 + lane * 4);
    float4 acc = make_float4(0.f, 0.f, 0.f, 0.f);
    float ssum = 0.f;
    int beg = rp[w], end = rp[w + 1];

    if (beg < end) {
        int s = col[beg];
        uint4 ld = __ldg((const uint4*)(ktv + (size_t)s * 256 + lane * 8));
        for (int i = beg; i < end; i++) {
            uint4 ldn;
            if (i + 1 < end) {
                int sn = col[i + 1];
                ldn = __ldg((const uint4*)(ktv + (size_t)sn * 256 + lane * 8));
            }
            float2 k01 = __half22float2(*(__half2*)&ld.x);
            float2 k23 = __half22float2(*(__half2*)&ld.y);
            float2 v01 = __half22float2(*(__half2*)&ld.z);
            float2 v23 = __half22float2(*(__half2*)&ld.w);
            float p = q4.x * k01.x + q4.y * k01.y + q4.z * k23.x + q4.w * k23.y;
            p += __shfl_xor_sync(0xffffffffu, p, 1);
            p += __shfl_xor_sync(0xffffffffu, p, 2);
            float ex = __expf(fminf(p, 80.f));
            ssum += ex;
            acc.x += ex * v01.x; acc.y += ex * v01.y;
            acc.z += ex * v23.x; acc.w += ex * v23.y;
            ld = ldn;
        }
    }
    float inv = __frcp_rn(ssum + 1e-16f);
    acc.x = gelu_exact(acc.x * inv);
    acc.y = gelu_exact(acc.y * inv);
    acc.z = gelu_exact(acc.z * inv);
    acc.w = gelu_exact(acc.w * inv);
    *(float4*)(agg + (size_t)w * 128 + lane * 4) = acc;
}

// ---------------------------------------------------------------------------
// Output head: out[ND,32] = x[ND,128] @ W[128,32] + b
// ---------------------------------------------------------------------------
__global__ void out_gemm(const float* __restrict__ x, const float* __restrict__ W,
                         const float* __restrict__ b, float* __restrict__ out) {
    size_t idx = (size_t)blockIdx.x * blockDim.x + threadIdx.x;
    if (idx >= (size_t)ND * OUTC) return;
    int n = (int)(idx >> 5), c = (int)(idx & 31);
    const float* xr = x + (size_t)n * 128;
    float s = b[c];
#pragma unroll 8
    for (int k = 0; k < 128; k++) s += xr[k] * W[k * OUTC + c];
    out[idx] = s;
}

// ---------------------------------------------------------------------------
// Host orchestration
// ---------------------------------------------------------------------------
static inline int cdiv(long long a, long long b) { return (int)((a + b - 1) / b); }

extern "C" void kernel_launch(void* const* d_in, const int* in_sizes, int n_in,
                              void* d_out, int out_size) {
    (void)in_sizes; (void)n_in; (void)out_size;

    const float* x_device = (const float*)d_in[0];
    const float* x_feature = (const float*)d_in[1];
    const int* e_df_src = (const int*)d_in[2];
    const int* e_df_dst = (const int*)d_in[3];
    const int* e_fd_src = (const int*)d_in[4];
    const int* e_fd_dst = (const int*)d_in[5];
    const float* W_dev_in = (const float*)d_in[6];
    const float* b_dev_in = (const float*)d_in[7];
    const float* W_feat_in = (const float*)d_in[8];
    const float* b_feat_in = (const float*)d_in[9];
    const float* Wk = (const float*)d_in[10];
    const float* bk = (const float*)d_in[11];
    const float* Wq = (const float*)d_in[12];
    const float* bq = (const float*)d_in[13];
    const float* Wv = (const float*)d_in[14];
    const float* bv = (const float*)d_in[15];
    const float* a_rel = (const float*)d_in[16];
    const float* m_rel = (const float*)d_in[17];
    const float* p_rel = (const float*)d_in[18];
    const float* Wa = (const float*)d_in[19];
    const float* ba = (const float*)d_in[20];
    const float* skip = (const float*)d_in[21];
    const float* ln_g = (const float*)d_in[22];
    const float* ln_b = (const float*)d_in[23];
    const float* W_out = (const float*)d_in[24];
    const float* b_out = (const float*)d_in[25];
    float* out = (float*)d_out;

    float* pool = nullptr;
    cudaGetSymbolAddress((void**)&pool, g_pool);

    float* xd   = pool + OFF_XD;   float* xf   = pool + OFF_XF;
    float* qd   = pool + OFF_QD;   float* qf   = pool + OFF_QF;
    __half* ktvd = (__half*)(pool + OFF_KTVD);
    __half* ktvf = (__half*)(pool + OFF_KTVF);
    float* aggd = pool + OFF_AGGD; float* aggf = pool + OFF_AGGF;
    float* WkE  = pool + OFF_WKE;  float* WvE  = pool + OFF_WVE;
    float* bkE  = pool + OFF_BKE;  float* bvE  = pool + OFF_BVE;
    __nv_bfloat16* HQ = (__nv_bfloat16*)(pool + OFF_HQ);
    __nv_bfloat16* LQ = (__nv_bfloat16*)(pool + OFF_LQ);
    __nv_bfloat16* HK = (__nv_bfloat16*)(pool + OFF_HK);
    __nv_bfloat16* LK = (__nv_bfloat16*)(pool + OFF_LK);
    __nv_bfloat16* HV = (__nv_bfloat16*)(pool + OFF_HV);
    __nv_bfloat16* LV = (__nv_bfloat16*)(pool + OFF_LV);
    __nv_bfloat16* HA = (__nv_bfloat16*)(pool + OFF_HA);
    __nv_bfloat16* LA = (__nv_bfloat16*)(pool + OFF_LA);
    __nv_bfloat16* HDI = (__nv_bfloat16*)(pool + OFF_HDI);
    __nv_bfloat16* LDI = (__nv_bfloat16*)(pool + OFF_LDI);
    __nv_bfloat16* HFI = (__nv_bfloat16*)(pool + OFF_HFI);
    __nv_bfloat16* LFI = (__nv_bfloat16*)(pool + OFF_LFI);
    int* rpf  = (int*)(pool + OFF_RPF);
    int* rpd  = (int*)(pool + OFF_RPD);
    int* cdf  = (int*)(pool + OFF_CDF);
    int* cfd  = (int*)(pool + OFF_CFD);
    int* cnt  = (int*)(pool + OFF_CNT);
    int* cur  = (int*)(pool + OFF_CUR);
    int* bsum = (int*)(pool + OFF_BSUM);

    const int gBlkD = cdiv(ND, 128), gBlkF = cdiv(NF, 128);
    const int eBlk = cdiv(EE, 256);

    // ---- CSR build: device->feature (dst = feature, NF rows) ----
    {
        const int nb = cdiv(NF, 512);
        cudaMemsetAsync(cnt, 0, NF * sizeof(int), 0);
        k_hist<<<eBlk, 256>>>(e_df_dst, cnt);
        k_bsum<<<nb, 512>>>(cnt, bsum, NF);
        k_scan_bsum<<<1, 128>>>(bsum, nb);
        k_rowptr<<<nb, 512>>>(cnt, bsum, rpf, NF);
        cudaMemsetAsync(cur, 0, NF * sizeof(int), 0);
        k_fill<<<eBlk, 256>>>(e_df_src, e_df_dst, rpf, cur, cdf);
    }
    // ---- CSR build: feature->device (dst = device, ND rows) ----
    {
        const int nb = cdiv(ND, 512);
        cudaMemsetAsync(cnt, 0, ND * sizeof(int), 0);
        k_hist<<<eBlk, 256>>>(e_fd_dst, cnt);
        k_bsum<<<nb, 512>>>(cnt, bsum, ND);
        k_scan_bsum<<<1, 128>>>(bsum, nb);
        k_rowptr<<<nb, 512>>>(cnt, bsum, rpd, ND);
        cudaMemsetAsync(cur, 0, ND * sizeof(int), 0);
        k_fill<<<eBlk, 256>>>(e_fd_src, e_fd_dst, rpd, cur, cfd);
    }

    // ---- fold relation transforms, then pre-split all GEMM weights (bf16) ----
    fold_weights<<<cdiv(4 * 129 * 128, 256), 256>>>(Wk, bk, Wv, bv, a_rel, m_rel, p_rel,
                                                    WkE, bkE, WvE, bvE);
    bsplit<<<cdiv(16384, 256), 256>>>(W_dev_in, HDI, LDI, 1);
    bsplit<<<cdiv(16384, 256), 256>>>(W_feat_in, HFI, LFI, 1);
    bsplit<<<cdiv(4 * 16384, 256), 256>>>(Wq, HQ, LQ, 4);
    bsplit<<<cdiv(4 * 16384, 256), 256>>>(WkE, HK, LK, 4);
    bsplit<<<cdiv(4 * 16384, 256), 256>>>(WvE, HV, LV, 4);
    bsplit<<<cdiv(4 * 16384, 256), 256>>>(Wa, HA, LA, 4);

    // ---- input projections + ReLU ----
    gemm_tc<1><<<dim3(gBlkD, 1), 256>>>(x_device, HDI, LDI, HDI, LDI, HDI, LDI,
                                        b_dev_in, b_dev_in, b_dev_in, xd, nullptr, ND,
                                        nullptr, nullptr, nullptr, nullptr);
    gemm_tc<1><<<dim3(gBlkF, 1), 256>>>(x_feature, HFI, LFI, HFI, LFI, HFI, LFI,
                                        b_feat_in, b_feat_in, b_feat_in, xf, nullptr, NF,
                                        nullptr, nullptr, nullptr, nullptr);

    for (int l = 0; l < NLYR; l++) {
        const int c0 = l * 2 + 0, c1 = l * 2 + 1;
        const size_t wo = (size_t)c0 * 16384, w1 = (size_t)c1 * 16384;
        const size_t bo0 = (size_t)c0 * 128,  bo1 = (size_t)c1 * 128;

        // fused q (fp32) / kt (fp16 packed) / vt (fp16 packed) projections
        gemm_tc<0><<<dim3(gBlkD, 3), 256>>>(xd,
            HQ + wo, LQ + wo, HK + wo, LK + wo, HV + wo, LV + wo,
            bq + bo0, bkE + bo0, bvE + bo0, qd, ktvd, ND,
            nullptr, nullptr, nullptr, nullptr);
        gemm_tc<0><<<dim3(gBlkF, 3), 256>>>(xf,
            HQ + w1, LQ + w1, HK + w1, LK + w1, HV + w1, LV + w1,
            bq + bo1, bkE + bo1, bvE + bo1, qf, ktvf, NF,
            nullptr, nullptr, nullptr, nullptr);

        // edge aggregation (CSR gather of packed fp16 kt/vt)
        edge_agg_csr<<<cdiv((long long)NF * 32, 256), 256>>>(rpf, cdf, qf, ktvd, aggf, NF);
        edge_agg_csr<<<cdiv((long long)ND * 32, 256), 256>>>(rpd, cfd, qd, ktvf, aggd, ND);

        // Wa GEMM with fused skip + residual + LayerNorm (in-place on x)
        gemm_tc<2><<<dim3(gBlkD, 1), 256>>>(aggd, HA + wo, LA + wo, HA + wo, LA + wo,
                                            HA + wo, LA + wo, ba + bo0, ba + bo0, ba + bo0,
                                            nullptr, nullptr, ND,
                                            xd, skip + c0, ln_g + bo0, ln_b + bo0);
        gemm_tc<2><<<dim3(gBlkF, 1), 256>>>(aggf, HA + w1, LA + w1, HA + w1, LA + w1,
                                            HA + w1, LA + w1, ba + bo1, ba + bo1, ba + bo1,
                                            nullptr, nullptr, NF,
                                            xf, skip + c1, ln_g + bo1, ln_b + bo1);
    }

    out_gemm<<<cdiv((long long)ND * OUTC, 256), 256>>>(xd, W_out, b_out, out);
}

// round 8
// speedup vs baseline: 2.9889x; 1.0537x over previous
#include <cuda_runtime.h>
#include <cuda_bf16.h>
#include <cuda_fp16.h>
#include <math.h>

// ---------------------------------------------------------------------------
// Problem constants
// ---------------------------------------------------------------------------
#define ND   20000
#define NF   50000
#define NT   (ND + NF)
#define EE   400000
#define NLYR 2
#define OUTC 32
#define NBF  98   // cdiv(NF,512)
#define NBD  40   // cdiv(ND,512)

// ---------------------------------------------------------------------------
// Scratch pool (static device memory; no allocations anywhere)
// Global row convention: rows 0..ND-1 = device nodes, ND..NT-1 = feature nodes.
// ---------------------------------------------------------------------------
constexpr size_t NT128 = (size_t)NT * 128;

constexpr size_t OFF_X    = 0;                       // fp32 [NT][128]
constexpr size_t OFF_Q    = OFF_X   + NT128;         // fp32 [NT][128]
constexpr size_t OFF_KTV  = OFF_Q   + NT128;         // half [NT][256]
constexpr size_t OFF_XH   = OFF_KTV + NT128;         // bf16 [NT][128]
constexpr size_t OFF_XL   = OFF_XH  + NT128 / 2;
constexpr size_t OFF_AGH  = OFF_XL  + NT128 / 2;     // bf16 [NT][128]
constexpr size_t OFF_AGL  = OFF_AGH + NT128 / 2;
constexpr size_t OFF_WKE  = OFF_AGL + NT128 / 2;     // 4*16384 fp32
constexpr size_t OFF_WVE  = OFF_WKE + 65536;
constexpr size_t OFF_BKE  = OFF_WVE + 65536;         // 512
constexpr size_t OFF_BVE  = OFF_BKE + 512;
constexpr size_t OFF_HQ   = OFF_BVE + 512;           // bf16 4*16384 = 32768 floats each
constexpr size_t OFF_LQ   = OFF_HQ  + 32768;
constexpr size_t OFF_HK   = OFF_LQ  + 32768;
constexpr size_t OFF_LK   = OFF_HK  + 32768;
constexpr size_t OFF_HV   = OFF_LK  + 32768;
constexpr size_t OFF_LV   = OFF_HV  + 32768;
constexpr size_t OFF_HA   = OFF_LV  + 32768;
constexpr size_t OFF_LA   = OFF_HA  + 32768;
constexpr size_t OFF_HDI  = OFF_LA  + 32768;         // 8192 floats each
constexpr size_t OFF_LDI  = OFF_HDI + 8192;
constexpr size_t OFF_HFI  = OFF_LDI + 8192;
constexpr size_t OFF_LFI  = OFF_HFI + 8192;
constexpr size_t OFF_RPF  = OFF_LFI + 8192;          // NF+1 int
constexpr size_t OFF_RPD  = OFF_RPF + (NF + 1);      // ND+1 int
constexpr size_t OFF_CDF  = OFF_RPD + (ND + 1);      // EE int
constexpr size_t OFF_CFD  = OFF_CDF + EE;            // EE int
constexpr size_t OFF_CNT  = OFF_CFD + EE;            // NT int (F first, then D)
constexpr size_t OFF_CUR  = OFF_CNT + NT;            // NT int
constexpr size_t OFF_BSUM = OFF_CUR + NT;            // 160
constexpr size_t POOL_SZ  = OFF_BSUM + 160;

__device__ __align__(256) float g_pool[POOL_SZ];

// ---------------------------------------------------------------------------
// Helpers
// ---------------------------------------------------------------------------
__device__ __forceinline__ float gelu_exact(float v) {
    return 0.5f * v * (1.0f + erff(v * 0.70710678118654752440f));
}
__device__ __forceinline__ unsigned pack_bf16x2(float a, float b) {
    unsigned r;
    asm("cvt.rn.bf16x2.f32 %0, %1, %2;" : "=r"(r) : "f"(b), "f"(a));
    return r;
}
__device__ __forceinline__ void split_pair(float2 p, unsigned& hi, unsigned& lo) {
    unsigned h = pack_bf16x2(p.x, p.y);
    unsigned hx, hy;
    asm("prmt.b32 %0, 0, %1, 0x5400;" : "=r"(hx) : "r"(h));
    asm("prmt.b32 %0, 0, %1, 0x7600;" : "=r"(hy) : "r"(h));
    float lx = p.x - __uint_as_float(hx);
    float ly = p.y - __uint_as_float(hy);
    lo = pack_bf16x2(lx, ly);
    hi = h;
}
// store v0,v1 as fp32 pair + bf16 hi/lo pairs
__device__ __forceinline__ void store_split(float v0, float v1, float* X,
                                            __nv_bfloat16* Xh, __nv_bfloat16* Xl,
                                            size_t base) {
    *(float2*)(X + base) = make_float2(v0, v1);
    unsigned h, l;
    split_pair(make_float2(v0, v1), h, l);
    *(unsigned*)(Xh + base) = h;
    *(unsigned*)(Xl + base) = l;
}

#define MMA_BF16(d, a, b0v, b1v)                                              \
    asm volatile(                                                             \
        "mma.sync.aligned.m16n8k16.row.col.f32.bf16.bf16.f32 "                \
        "{%0,%1,%2,%3},{%4,%5,%6,%7},{%8,%9},{%0,%1,%2,%3};"                  \
        : "+f"((d)[0]), "+f"((d)[1]), "+f"((d)[2]), "+f"((d)[3])              \
        : "r"((a)[0]), "r"((a)[1]), "r"((a)[2]), "r"((a)[3]),                 \
          "r"(b0v), "r"(b1v))

__device__ __forceinline__ void cp16(unsigned dst, const void* src, bool pred) {
    if (pred)
        asm volatile("cp.async.cg.shared.global [%0], [%1], 16;"
                     :: "r"(dst), "l"(src));
}
__device__ __forceinline__ unsigned cvta(const void* p) {
    return (unsigned)__cvta_generic_to_shared(p);
}

// ---------------------------------------------------------------------------
// GEMM argument bundle
// ---------------------------------------------------------------------------
struct GArgs {
    const float* AfD; const float* AfF;               // APATH0 A (per side)
    const __nv_bfloat16* Ah; const __nv_bfloat16* Al; // APATH1 A (global rows)
    const __nv_bfloat16 *H0, *L0, *H1, *L1, *H2, *L2; // weight family bases
    const float *b0, *b1, *b2;                        // bias bases
    float* Q; __half* KTV;                            // MODE0 outputs
    float* X; __nv_bfloat16 *Xh, *Xl;                 // MODE1/2 outputs
    const float *skipv, *lng, *lnb;                   // MODE2
    int layer, blkD;
};

// ---------------------------------------------------------------------------
// Tensor-core GEMM, 3xBF16 split, merged D/F sides (side = blockIdx.x >= blkD).
//   MODE 0 (APATH1): y=0 -> fp32 Q; y=1 -> fp16 kt into KTV; y=2 -> fp16 vt
//   MODE 1 (APATH0): relu(A@W+b) -> X fp32 + Xh/Xl bf16   (input projection)
//   MODE 2 (APATH1): X = LN(X + sk*(A@W+b) + (1-sk)X) -> X + Xh/Xl
// 128x128 tile, BK=16, 8 warps, cp.async double buffer.
// ---------------------------------------------------------------------------
template <int MODE, int APATH>
__global__ void __launch_bounds__(256)
gemm_tc(GArgs a) {
    const int bx = blockIdx.x;
    const bool isF = bx >= a.blkD;
    const int lbx = isF ? bx - a.blkD : bx;
    const int combo = a.layer * 2 + (isF ? 1 : 0);

    int aRow0, aN, cOff;
    const float* Af = nullptr;
    if (APATH == 0) {
        aRow0 = lbx * 128;
        aN    = isF ? NF : ND;
        cOff  = isF ? ND : 0;
        Af    = isF ? a.AfF : a.AfD;
    } else {
        aRow0 = isF ? (ND + lbx * 128) : lbx * 128;
        aN    = isF ? NT : ND;
        cOff  = 0;
    }

    const __nv_bfloat16* WH;
    const __nv_bfloat16* WL;
    const float* bias;
    if (MODE == 1) {
        WH = isF ? a.H1 : a.H0;  WL = isF ? a.L1 : a.L0;
        bias = isF ? a.b1 : a.b0;
    } else if (MODE == 0) {
        int fam = blockIdx.y;
        WH = (fam == 0 ? a.H0 : fam == 1 ? a.H1 : a.H2) + (size_t)combo * 16384;
        WL = (fam == 0 ? a.L0 : fam == 1 ? a.L1 : a.L2) + (size_t)combo * 16384;
        bias = (fam == 0 ? a.b0 : fam == 1 ? a.b1 : a.b2) + combo * 128;
    } else {
        WH = a.H0 + (size_t)combo * 16384;
        WL = a.L0 + (size_t)combo * 16384;
        bias = a.b0 + combo * 128;
    }

    constexpr int A_RAW = (APATH == 0) ? (2 * 128 * 20 * 4) : (2 * (2 * 128 * 16 * 2));
    __shared__ __align__(16) unsigned char AsRaw[A_RAW];
    __shared__ __align__(16) __nv_bfloat16 Bh[2][128 * 24];
    __shared__ __align__(16) __nv_bfloat16 Bl[2][128 * 24];
    __shared__ float rs[128], rq[128];

    float* Asf = (float*)AsRaw;                                  // [2][128*20]
    __nv_bfloat16* Ahs = (__nv_bfloat16*)AsRaw;                  // [2][128*16]
    __nv_bfloat16* Als = (__nv_bfloat16*)(AsRaw + 2 * 128 * 16 * 2);

    const int tid  = threadIdx.x;
    const int lane = tid & 31, warp = tid >> 5;
    const int g = lane >> 2, c = lane & 3;
    const int m0 = (warp >> 1) * 32, n0 = (warp & 1) * 64;

    auto stage = [&](int buf, int k0) {
        if (APATH == 0) {
#pragma unroll
            for (int i = 0; i < 2; i++) {
                int id = tid + i * 256;
                int r = id >> 2, ch = id & 3;
                cp16(cvta(&Asf[buf * 2560 + r * 20 + ch * 4]),
                     Af + (size_t)(aRow0 + r) * 128 + k0 + ch * 4, aRow0 + r < aN);
            }
        } else {
            int r = tid >> 1, ch = tid & 1;
            bool ok = aRow0 + r < aN;
            cp16(cvta(&Ahs[buf * 2048 + r * 16 + ch * 8]),
                 a.Ah + (size_t)(aRow0 + r) * 128 + k0 + ch * 8, ok);
            cp16(cvta(&Als[buf * 2048 + r * 16 + ch * 8]),
                 a.Al + (size_t)(aRow0 + r) * 128 + k0 + ch * 8, ok);
        }
        int n = tid >> 1, ch = tid & 1;
        cp16(cvta(&Bh[buf][n * 24 + ch * 8]), WH + (size_t)n * 128 + k0 + ch * 8, true);
        cp16(cvta(&Bl[buf][n * 24 + ch * 8]), WL + (size_t)n * 128 + k0 + ch * 8, true);
        asm volatile("cp.async.commit_group;");
    };

    float acc[2][8][4];
#pragma unroll
    for (int mi = 0; mi < 2; mi++)
#pragma unroll
        for (int ni = 0; ni < 8; ni++)
#pragma unroll
            for (int j = 0; j < 4; j++) acc[mi][ni][j] = 0.f;

    stage(0, 0);

    for (int it = 0; it < 8; it++) {
        if (it < 7) {
            stage((it + 1) & 1, (it + 1) * 16);
            asm volatile("cp.async.wait_group 1;");
        } else {
            asm volatile("cp.async.wait_group 0;");
        }
        __syncthreads();

        unsigned ahi[2][4], alo[2][4];
        if (APATH == 0) {
            const float* Ab = &Asf[(it & 1) * 2560];
#pragma unroll
            for (int mi = 0; mi < 2; mi++) {
                int rb = (m0 + mi * 16 + g) * 20;
                split_pair(*(const float2*)&Ab[rb + 2 * c],           ahi[mi][0], alo[mi][0]);
                split_pair(*(const float2*)&Ab[rb + 160 + 2 * c],     ahi[mi][1], alo[mi][1]);
                split_pair(*(const float2*)&Ab[rb + 2 * c + 8],       ahi[mi][2], alo[mi][2]);
                split_pair(*(const float2*)&Ab[rb + 160 + 2 * c + 8], ahi[mi][3], alo[mi][3]);
            }
        } else {
            const __nv_bfloat16* Abh = &Ahs[(it & 1) * 2048];
            const __nv_bfloat16* Abl = &Als[(it & 1) * 2048];
#pragma unroll
            for (int mi = 0; mi < 2; mi++) {
                int rb = (m0 + mi * 16 + g) * 16;
                ahi[mi][0] = *(const unsigned*)&Abh[rb + 2 * c];
                ahi[mi][1] = *(const unsigned*)&Abh[rb + 128 + 2 * c];
                ahi[mi][2] = *(const unsigned*)&Abh[rb + 2 * c + 8];
                ahi[mi][3] = *(const unsigned*)&Abh[rb + 128 + 2 * c + 8];
                alo[mi][0] = *(const unsigned*)&Abl[rb + 2 * c];
                alo[mi][1] = *(const unsigned*)&Abl[rb + 128 + 2 * c];
                alo[mi][2] = *(const unsigned*)&Abl[rb + 2 * c + 8];
                alo[mi][3] = *(const unsigned*)&Abl[rb + 128 + 2 * c + 8];
            }
        }
        const __nv_bfloat16* Bhh = Bh[it & 1];
        const __nv_bfloat16* Bll = Bl[it & 1];
#pragma unroll
        for (int ni = 0; ni < 8; ni++) {
            int bn = n0 + ni * 8 + g;
            unsigned bh0 = *(const unsigned*)&Bhh[bn * 24 + 2 * c];
            unsigned bh1 = *(const unsigned*)&Bhh[bn * 24 + 2 * c + 8];
            unsigned bl0 = *(const unsigned*)&Bll[bn * 24 + 2 * c];
            unsigned bl1 = *(const unsigned*)&Bll[bn * 24 + 2 * c + 8];
#pragma unroll
            for (int mi = 0; mi < 2; mi++) {
                MMA_BF16(acc[mi][ni], ahi[mi], bh0, bh1);
                MMA_BF16(acc[mi][ni], ahi[mi], bl0, bl1);
                MMA_BF16(acc[mi][ni], alo[mi], bh0, bh1);
            }
        }
        __syncthreads();
    }

    if (MODE == 0 && blockIdx.y != 0) {
        // fp16 packed kt/vt epilogue
        const int voff = (blockIdx.y == 2) ? 4 : 0;
#pragma unroll
        for (int ni = 0; ni < 8; ni++) {
            int col = n0 + ni * 8 + 2 * c;
            float bb0 = bias[col], bb1 = bias[col + 1];
            int po = ((col >> 2) << 3) + (col & 3) + voff;
#pragma unroll
            for (int mi = 0; mi < 2; mi++) {
                int ra = aRow0 + m0 + mi * 16 + g;
                if (ra < aN)
                    *(__half2*)(a.KTV + (size_t)ra * 256 + po) =
                        __floats2half2_rn(acc[mi][ni][0] + bb0, acc[mi][ni][1] + bb1);
                if (ra + 8 < aN)
                    *(__half2*)(a.KTV + (size_t)(ra + 8) * 256 + po) =
                        __floats2half2_rn(acc[mi][ni][2] + bb0, acc[mi][ni][3] + bb1);
            }
        }
    } else if (MODE == 0) {
        // fp32 q epilogue
#pragma unroll
        for (int ni = 0; ni < 8; ni++) {
            int col = n0 + ni * 8 + 2 * c;
            float bb0 = bias[col], bb1 = bias[col + 1];
#pragma unroll
            for (int mi = 0; mi < 2; mi++) {
                int ra = aRow0 + m0 + mi * 16 + g;
                if (ra < aN)
                    *(float2*)(a.Q + (size_t)ra * 128 + col) =
                        make_float2(acc[mi][ni][0] + bb0, acc[mi][ni][1] + bb1);
                if (ra + 8 < aN)
                    *(float2*)(a.Q + (size_t)(ra + 8) * 128 + col) =
                        make_float2(acc[mi][ni][2] + bb0, acc[mi][ni][3] + bb1);
            }
        }
    } else if (MODE == 1) {
        // relu -> X + Xh/Xl
#pragma unroll
        for (int ni = 0; ni < 8; ni++) {
            int col = n0 + ni * 8 + 2 * c;
            float bb0 = bias[col], bb1 = bias[col + 1];
#pragma unroll
            for (int mi = 0; mi < 2; mi++) {
                int ra = aRow0 + m0 + mi * 16 + g;
                if (ra < aN) {
                    float v0 = fmaxf(acc[mi][ni][0] + bb0, 0.f);
                    float v1 = fmaxf(acc[mi][ni][1] + bb1, 0.f);
                    store_split(v0, v1, a.X, a.Xh, a.Xl, (size_t)(ra + cOff) * 128 + col);
                }
                if (ra + 8 < aN) {
                    float v2 = fmaxf(acc[mi][ni][2] + bb0, 0.f);
                    float v3 = fmaxf(acc[mi][ni][3] + bb1, 0.f);
                    store_split(v2, v3, a.X, a.Xh, a.Xl, (size_t)(ra + 8 + cOff) * 128 + col);
                }
            }
        }
    } else {
        // MODE 2: fused skip + residual + LayerNorm (in-place on X, global rows)
        float sk = 1.f / (1.f + __expf(-a.skipv[combo]));
        float tms = 2.f - sk;
        const float* lng = a.lng + combo * 128;
        const float* lnb = a.lnb + combo * 128;
        if (tid < 128) { rs[tid] = 0.f; rq[tid] = 0.f; }
        __syncthreads();

        float psum[2][2] = {{0.f, 0.f}, {0.f, 0.f}};
        float psq[2][2]  = {{0.f, 0.f}, {0.f, 0.f}};
#pragma unroll
        for (int ni = 0; ni < 8; ni++) {
            int col = n0 + ni * 8 + 2 * c;
            float bb0 = bias[col], bb1 = bias[col + 1];
#pragma unroll
            for (int mi = 0; mi < 2; mi++) {
                int ra = aRow0 + m0 + mi * 16 + g;
                if (ra < aN) {
                    float2 xv = *(float2*)(a.X + (size_t)ra * 128 + col);
                    float y0 = tms * xv.x + sk * (acc[mi][ni][0] + bb0);
                    float y1 = tms * xv.y + sk * (acc[mi][ni][1] + bb1);
                    *(float2*)(a.X + (size_t)ra * 128 + col) = make_float2(y0, y1);
                    psum[mi][0] += y0 + y1;
                    psq[mi][0]  += y0 * y0 + y1 * y1;
                }
                if (ra + 8 < aN) {
                    float2 xv = *(float2*)(a.X + (size_t)(ra + 8) * 128 + col);
                    float y2 = tms * xv.x + sk * (acc[mi][ni][2] + bb0);
                    float y3 = tms * xv.y + sk * (acc[mi][ni][3] + bb1);
                    *(float2*)(a.X + (size_t)(ra + 8) * 128 + col) = make_float2(y2, y3);
                    psum[mi][1] += y2 + y3;
                    psq[mi][1]  += y2 * y2 + y3 * y3;
                }
            }
        }
#pragma unroll
        for (int mi = 0; mi < 2; mi++)
#pragma unroll
            for (int hh = 0; hh < 2; hh++) {
                float s = psum[mi][hh], q = psq[mi][hh];
                s += __shfl_xor_sync(0xffffffffu, s, 1);
                s += __shfl_xor_sync(0xffffffffu, s, 2);
                q += __shfl_xor_sync(0xffffffffu, q, 1);
                q += __shfl_xor_sync(0xffffffffu, q, 2);
                if (c == 0) {
                    int rl = m0 + mi * 16 + g + hh * 8;
                    atomicAdd(&rs[rl], s);
                    atomicAdd(&rq[rl], q);
                }
            }
        __syncthreads();

#pragma unroll
        for (int ni = 0; ni < 8; ni++) {
            int col = n0 + ni * 8 + 2 * c;
            float g0 = lng[col], g1 = lng[col + 1];
            float h0 = lnb[col], h1 = lnb[col + 1];
#pragma unroll
            for (int mi = 0; mi < 2; mi++) {
#pragma unroll
                for (int hh = 0; hh < 2; hh++) {
                    int rl = m0 + mi * 16 + g + hh * 8;
                    int ra = aRow0 + rl;
                    if (ra < aN) {
                        float mean = rs[rl] * (1.f / 128.f);
                        float var  = rq[rl] * (1.f / 128.f) - mean * mean;
                        float rstd = rsqrtf(var + 1e-5f);
                        float2 yv = *(float2*)(a.X + (size_t)ra * 128 + col);
                        float o0 = (yv.x - mean) * rstd * g0 + h0;
                        float o1 = (yv.y - mean) * rstd * g1 + h1;
                        store_split(o0, o1, a.X, a.Xh, a.Xl, (size_t)ra * 128 + col);
                    }
                }
            }
        }
    }
}

// ---------------------------------------------------------------------------
// Fold relation transforms into projection weights (and priors into k)
// ---------------------------------------------------------------------------
__global__ void fold_weights(const float* __restrict__ Wk, const float* __restrict__ bk,
                             const float* __restrict__ Wv, const float* __restrict__ bv,
                             const float* __restrict__ a_rel, const float* __restrict__ m_rel,
                             const float* __restrict__ p_rel,
                             float* __restrict__ WkE, float* __restrict__ bkE,
                             float* __restrict__ WvE, float* __restrict__ bvE) {
    int idx = blockIdx.x * blockDim.x + threadIdx.x;
    if (idx >= 4 * 129 * 128) return;
    int combo = idx / (129 * 128);
    int rem   = idx % (129 * 128);
    int r  = rem >> 7;
    int he = rem & 127;
    int h = he >> 4, e = he & 15;
    const float* aa = a_rel + ((size_t)combo * 8 + h) * 256 + e;
    const float* mm = m_rel + ((size_t)combo * 8 + h) * 256 + e;
    float ps = p_rel[combo * 8 + h] * 0.25f;

    const float* kr = (r < 128) ? (Wk + (size_t)combo * 16384 + (size_t)r * 128 + h * 16)
                                : (bk + (size_t)combo * 128 + h * 16);
    const float* vr = (r < 128) ? (Wv + (size_t)combo * 16384 + (size_t)r * 128 + h * 16)
                                : (bv + (size_t)combo * 128 + h * 16);
    float sk = 0.f, sv = 0.f;
#pragma unroll
    for (int d = 0; d < 16; d++) {
        sk += kr[d] * aa[d * 16];
        sv += vr[d] * mm[d * 16];
    }
    sk *= ps;
    if (r < 128) {
        WkE[(size_t)combo * 16384 + (size_t)r * 128 + he] = sk;
        WvE[(size_t)combo * 16384 + (size_t)r * 128 + he] = sv;
    } else {
        bkE[combo * 128 + he] = sk;
        bvE[combo * 128 + he] = sv;
    }
}

// ---------------------------------------------------------------------------
// One-shot pre-split of all 18 weight matrices: fp32 [k][n] -> bf16 hi/lo [n][k]
// mats: 0=W_dev_in 1=W_feat_in 2-5=Wq 6-9=WkE 10-13=WvE 14-17=Wa
// ---------------------------------------------------------------------------
__global__ void bsplit_all(const float* __restrict__ Wdev, const float* __restrict__ Wfeat,
                           const float* __restrict__ Wq,  const float* __restrict__ WkE,
                           const float* __restrict__ WvE, const float* __restrict__ Wa,
                           __nv_bfloat16* HDI, __nv_bfloat16* LDI,
                           __nv_bfloat16* HFI, __nv_bfloat16* LFI,
                           __nv_bfloat16* HQ,  __nv_bfloat16* LQ,
                           __nv_bfloat16* HK,  __nv_bfloat16* LK,
                           __nv_bfloat16* HV,  __nv_bfloat16* LV,
                           __nv_bfloat16* HA,  __nv_bfloat16* LA) {
    int i = blockIdx.x * blockDim.x + threadIdx.x;
    if (i >= 18 * 16384) return;
    int mat = i >> 14, rem = i & 16383;
    int n = rem >> 7, k = rem & 127;
    const float* src; __nv_bfloat16 *hi, *lo; size_t off;
    if (mat == 0)      { src = Wdev;  hi = HDI; lo = LDI; off = 0; }
    else if (mat == 1) { src = Wfeat; hi = HFI; lo = LFI; off = 0; }
    else {
        int f = (mat - 2) >> 2, cc = (mat - 2) & 3;
        off = (size_t)cc * 16384;
        src = (f == 0) ? Wq : (f == 1) ? WkE : (f == 2) ? WvE : Wa;
        hi  = (f == 0) ? HQ : (f == 1) ? HK : (f == 2) ? HV : HA;
        lo  = (f == 0) ? LQ : (f == 1) ? LK : (f == 2) ? LV : LA;
    }
    float x = src[off + (size_t)k * 128 + n];
    __nv_bfloat16 h = __float2bfloat16(x);
    hi[off + (size_t)n * 128 + k] = h;
    lo[off + (size_t)n * 128 + k] = __float2bfloat16(x - __bfloat162float(h));
}

// ---------------------------------------------------------------------------
// CSR build (both edge types fused per kernel)
// ---------------------------------------------------------------------------
__global__ void hist2(const int* __restrict__ dstF, const int* __restrict__ dstD,
                      int* __restrict__ cnt) {
    int i = blockIdx.x * blockDim.x + threadIdx.x;
    if (i >= 2 * EE) return;
    if (i < EE) atomicAdd(&cnt[dstF[i]], 1);
    else        atomicAdd(&cnt[NF + dstD[i - EE]], 1);
}

__global__ void bsum2(const int* __restrict__ cnt, int* __restrict__ bsum) {
    __shared__ int sh[512];
    int b = blockIdx.x, t = threadIdx.x;
    const int* arr; int g, lim;
    if (b < NBF) { arr = cnt;      g = b * 512 + t;         lim = NF; }
    else         { arr = cnt + NF; g = (b - NBF) * 512 + t; lim = ND; }
    sh[t] = (g < lim) ? arr[g] : 0;
    __syncthreads();
#pragma unroll
    for (int off = 256; off; off >>= 1) {
        if (t < off) sh[t] += sh[t + off];
        __syncthreads();
    }
    if (t == 0) bsum[b] = sh[0];
}

__global__ void scan2(int* __restrict__ bsum) {
    __shared__ int sh[128];
    int t = threadIdx.x;
    int base = (blockIdx.x == 0) ? 0 : NBF;
    int nb   = (blockIdx.x == 0) ? NBF : NBD;
    int v = (t < nb) ? bsum[base + t] : 0;
    sh[t] = v;
    __syncthreads();
#pragma unroll
    for (int off = 1; off < 128; off <<= 1) {
        int u = (t >= off) ? sh[t - off] : 0;
        __syncthreads();
        sh[t] += u;
        __syncthreads();
    }
    if (t < nb) bsum[base + t] = sh[t] - v;
}

__global__ void rowptr2(const int* __restrict__ cnt, const int* __restrict__ bsum,
                        int* __restrict__ rpf, int* __restrict__ rpd,
                        int* __restrict__ cur) {
    __shared__ int sh[512];
    int b = blockIdx.x, t = threadIdx.x;
    const int* arr; int* rp; int g, lim, curOff;
    if (b < NBF) { arr = cnt;      rp = rpf; g = b * 512 + t;         lim = NF; curOff = 0; }
    else         { arr = cnt + NF; rp = rpd; g = (b - NBF) * 512 + t; lim = ND; curOff = NF; }
    int base = bsum[b];
    int v = (g < lim) ? arr[g] : 0;
    sh[t] = v;
    __syncthreads();
    for (int off = 1; off < 512; off <<= 1) {
        int u = (t >= off) ? sh[t - off] : 0;
        __syncthreads();
        sh[t] += u;
        __syncthreads();
    }
    if (g < lim) { rp[g] = base + sh[t] - v; cur[curOff + g] = 0; }
    if (t == 0 && b == 0)   rpf[NF] = EE;
    if (t == 0 && b == NBF) rpd[ND] = EE;
}

__global__ void fill2(const int* __restrict__ srcF, const int* __restrict__ dstF,
                      const int* __restrict__ srcD, const int* __restrict__ dstD,
                      const int* __restrict__ rpf, const int* __restrict__ rpd,
                      int* __restrict__ cur, int* __restrict__ cdf, int* __restrict__ cfd) {
    int i = blockIdx.x * blockDim.x + threadIdx.x;
    if (i >= 2 * EE) return;
    if (i < EE) {
        int d = dstF[i];
        int pos = rpf[d] + atomicAdd(&cur[d], 1);
        cdf[pos] = srcF[i];
    } else {
        int j = i - EE;
        int d = dstD[j];
        int pos = rpd[d] + atomicAdd(&cur[NF + d], 1);
        cfd[pos] = srcD[j];
    }
}

// ---------------------------------------------------------------------------
// Edge aggregation, both edge types in one launch. One warp per dst node.
// Writes agg as bf16 hi/lo (pre-split for the MODE2 GEMM).
// ---------------------------------------------------------------------------
__global__ void edge_agg2(const int* __restrict__ rpf, const int* __restrict__ cdf,
                          const int* __restrict__ rpd, const int* __restrict__ cfd,
                          const float* __restrict__ q, const __half* __restrict__ ktv,
                          __nv_bfloat16* __restrict__ aggh, __nv_bfloat16* __restrict__ aggl) {
    int w = (blockIdx.x * blockDim.x + threadIdx.x) >> 5;
    if (w >= NT) return;
    int lane = threadIdx.x & 31;
    bool isF = w < NF;
    int wi = isF ? w : (w - NF);
    int dstRow = isF ? (ND + wi) : wi;
    const int* rp  = isF ? rpf : rpd;
    const int* col = isF ? cdf : cfd;
    int srcBase = isF ? 0 : ND;

    float4 q4 = *(const float4*)(q + (size_t)dstRow * 128 + lane * 4);
    float4 acc = make_float4(0.f, 0.f, 0.f, 0.f);
    float ssum = 0.f;
    int beg = rp[wi], end = rp[wi + 1];

    if (beg < end) {
        int s = col[beg];
        uint4 ld = __ldg((const uint4*)(ktv + (size_t)(srcBase + s) * 256 + lane * 8));
        for (int i = beg; i < end; i++) {
            uint4 ldn;
            if (i + 1 < end) {
                int sn = col[i + 1];
                ldn = __ldg((const uint4*)(ktv + (size_t)(srcBase + sn) * 256 + lane * 8));
            }
            float2 k01 = __half22float2(*(__half2*)&ld.x);
            float2 k23 = __half22float2(*(__half2*)&ld.y);
            float2 v01 = __half22float2(*(__half2*)&ld.z);
            float2 v23 = __half22float2(*(__half2*)&ld.w);
            float p = q4.x * k01.x + q4.y * k01.y + q4.z * k23.x + q4.w * k23.y;
            p += __shfl_xor_sync(0xffffffffu, p, 1);
            p += __shfl_xor_sync(0xffffffffu, p, 2);
            float ex = __expf(fminf(p, 80.f));
            ssum += ex;
            acc.x += ex * v01.x; acc.y += ex * v01.y;
            acc.z += ex * v23.x; acc.w += ex * v23.y;
            ld = ldn;
        }
    }
    float inv = __frcp_rn(ssum + 1e-16f);
    float g0 = gelu_exact(acc.x * inv);
    float g1 = gelu_exact(acc.y * inv);
    float g2 = gelu_exact(acc.z * inv);
    float g3 = gelu_exact(acc.w * inv);

    size_t base = (size_t)dstRow * 128 + lane * 4;
    unsigned h01, l01, h23, l23;
    split_pair(make_float2(g0, g1), h01, l01);
    split_pair(make_float2(g2, g3), h23, l23);
    *(unsigned*)(aggh + base)     = h01;
    *(unsigned*)(aggh + base + 2) = h23;
    *(unsigned*)(aggl + base)     = l01;
    *(unsigned*)(aggl + base + 2) = l23;
}

// ---------------------------------------------------------------------------
// Output head: out[ND,32] = X[0:ND,128] @ W[128,32] + b
// ---------------------------------------------------------------------------
__global__ void out_gemm(const float* __restrict__ x, const float* __restrict__ W,
                         const float* __restrict__ b, float* __restrict__ out) {
    size_t idx = (size_t)blockIdx.x * blockDim.x + threadIdx.x;
    if (idx >= (size_t)ND * OUTC) return;
    int n = (int)(idx >> 5), cc = (int)(idx & 31);
    const float* xr = x + (size_t)n * 128;
    float s = b[cc];
#pragma unroll 8
    for (int k = 0; k < 128; k++) s += xr[k] * W[k * OUTC + cc];
    out[idx] = s;
}

// ---------------------------------------------------------------------------
// Host orchestration
// ---------------------------------------------------------------------------
static inline int cdiv(long long a, long long b) { return (int)((a + b - 1) / b); }

extern "C" void kernel_launch(void* const* d_in, const int* in_sizes, int n_in,
                              void* d_out, int out_size) {
    (void)in_sizes; (void)n_in; (void)out_size;

    const float* x_device = (const float*)d_in[0];
    const float* x_feature = (const float*)d_in[1];
    const int* e_df_src = (const int*)d_in[2];
    const int* e_df_dst = (const int*)d_in[3];
    const int* e_fd_src = (const int*)d_in[4];
    const int* e_fd_dst = (const int*)d_in[5];
    const float* W_dev_in = (const float*)d_in[6];
    const float* b_dev_in = (const float*)d_in[7];
    const float* W_feat_in = (const float*)d_in[8];
    const float* b_feat_in = (const float*)d_in[9];
    const float* Wk = (const float*)d_in[10];
    const float* bk = (const float*)d_in[11];
    const float* Wq = (const float*)d_in[12];
    const float* bq = (const float*)d_in[13];
    const float* Wv = (const float*)d_in[14];
    const float* bv = (const float*)d_in[15];
    const float* a_rel = (const float*)d_in[16];
    const float* m_rel = (const float*)d_in[17];
    const float* p_rel = (const float*)d_in[18];
    const float* Wa = (const float*)d_in[19];
    const float* ba = (const float*)d_in[20];
    const float* skip = (const float*)d_in[21];
    const float* ln_g = (const float*)d_in[22];
    const float* ln_b = (const float*)d_in[23];
    const float* W_out = (const float*)d_in[24];
    const float* b_out = (const float*)d_in[25];
    float* out = (float*)d_out;

    float* pool = nullptr;
    cudaGetSymbolAddress((void**)&pool, g_pool);

    float* X   = pool + OFF_X;
    float* Q   = pool + OFF_Q;
    __half* KTV = (__half*)(pool + OFF_KTV);
    __nv_bfloat16* Xh  = (__nv_bfloat16*)(pool + OFF_XH);
    __nv_bfloat16* Xl  = (__nv_bfloat16*)(pool + OFF_XL);
    __nv_bfloat16* AGH = (__nv_bfloat16*)(pool + OFF_AGH);
    __nv_bfloat16* AGL = (__nv_bfloat16*)(pool + OFF_AGL);
    float* WkE = pool + OFF_WKE;  float* WvE = pool + OFF_WVE;
    float* bkE = pool + OFF_BKE;  float* bvE = pool + OFF_BVE;
    __nv_bfloat16* HQ = (__nv_bfloat16*)(pool + OFF_HQ);
    __nv_bfloat16* LQ = (__nv_bfloat16*)(pool + OFF_LQ);
    __nv_bfloat16* HK = (__nv_bfloat16*)(pool + OFF_HK);
    __nv_bfloat16* LK = (__nv_bfloat16*)(pool + OFF_LK);
    __nv_bfloat16* HV = (__nv_bfloat16*)(pool + OFF_HV);
    __nv_bfloat16* LV = (__nv_bfloat16*)(pool + OFF_LV);
    __nv_bfloat16* HA = (__nv_bfloat16*)(pool + OFF_HA);
    __nv_bfloat16* LA = (__nv_bfloat16*)(pool + OFF_LA);
    __nv_bfloat16* HDI = (__nv_bfloat16*)(pool + OFF_HDI);
    __nv_bfloat16* LDI = (__nv_bfloat16*)(pool + OFF_LDI);
    __nv_bfloat16* HFI = (__nv_bfloat16*)(pool + OFF_HFI);
    __nv_bfloat16* LFI = (__nv_bfloat16*)(pool + OFF_LFI);
    int* rpf = (int*)(pool + OFF_RPF);
    int* rpd = (int*)(pool + OFF_RPD);
    int* cdf = (int*)(pool + OFF_CDF);
    int* cfd = (int*)(pool + OFF_CFD);
    int* cnt = (int*)(pool + OFF_CNT);
    int* cur = (int*)(pool + OFF_CUR);
    int* bsum = (int*)(pool + OFF_BSUM);

    const int gBlkD = cdiv(ND, 128), gBlkF = cdiv(NF, 128);
    const int gBlk = gBlkD + gBlkF;

    // ---- CSR build (both edge types) ----
    cudaMemsetAsync(cnt, 0, NT * sizeof(int), 0);
    hist2<<<cdiv(2 * EE, 256), 256>>>(e_df_dst, e_fd_dst, cnt);
    bsum2<<<NBF + NBD, 512>>>(cnt, bsum);
    scan2<<<2, 128>>>(bsum);
    rowptr2<<<NBF + NBD, 512>>>(cnt, bsum, rpf, rpd, cur);
    fill2<<<cdiv(2 * EE, 256), 256>>>(e_df_src, e_df_dst, e_fd_src, e_fd_dst,
                                      rpf, rpd, cur, cdf, cfd);

    // ---- weight prep ----
    fold_weights<<<cdiv(4 * 129 * 128, 256), 256>>>(Wk, bk, Wv, bv, a_rel, m_rel, p_rel,
                                                    WkE, bkE, WvE, bvE);
    bsplit_all<<<cdiv(18 * 16384, 256), 256>>>(W_dev_in, W_feat_in, Wq, WkE, WvE, Wa,
                                               HDI, LDI, HFI, LFI, HQ, LQ, HK, LK,
                                               HV, LV, HA, LA);

    // ---- input projections + ReLU (merged D/F) ----
    {
        GArgs a = {};
        a.AfD = x_device; a.AfF = x_feature;
        a.H0 = HDI; a.L0 = LDI; a.H1 = HFI; a.L1 = LFI;
        a.b0 = b_dev_in; a.b1 = b_feat_in;
        a.X = X; a.Xh = Xh; a.Xl = Xl;
        a.layer = 0; a.blkD = gBlkD;
        gemm_tc<1, 0><<<gBlk, 256>>>(a);
    }

    for (int l = 0; l < NLYR; l++) {
        // fused q / kt / vt projections (merged D/F, gridDim.y = 3)
        {
            GArgs a = {};
            a.Ah = Xh; a.Al = Xl;
            a.H0 = HQ; a.L0 = LQ; a.H1 = HK; a.L1 = LK; a.H2 = HV; a.L2 = LV;
            a.b0 = bq; a.b1 = bkE; a.b2 = bvE;
            a.Q = Q; a.KTV = KTV;
            a.layer = l; a.blkD = gBlkD;
            gemm_tc<0, 1><<<dim3(gBlk, 3), 256>>>(a);
        }
        // edge aggregation (both edge types)
        edge_agg2<<<cdiv((long long)NT * 32, 256), 256>>>(rpf, cdf, rpd, cfd,
                                                          Q, KTV, AGH, AGL);
        // Wa GEMM + fused skip + residual + LayerNorm (merged D/F)
        {
            GArgs a = {};
            a.Ah = AGH; a.Al = AGL;
            a.H0 = HA; a.L0 = LA;
            a.b0 = ba;
            a.X = X; a.Xh = Xh; a.Xl = Xl;
            a.skipv = skip; a.lng = ln_g; a.lnb = ln_b;
            a.layer = l; a.blkD = gBlkD;
            gemm_tc<2, 1><<<gBlk, 256>>>(a);
        }
    }

    out_gemm<<<cdiv((long long)ND * OUTC, 256), 256>>>(X, W_out, b_out, out);
}

// round 9
// speedup vs baseline: 3.2292x; 1.0804x over previous
#include <cuda_runtime.h>
#include <cuda_bf16.h>
#include <cuda_fp16.h>
#include <math.h>

// ---------------------------------------------------------------------------
// Problem constants
// ---------------------------------------------------------------------------
#define ND   20000
#define NF   50000
#define NT   (ND + NF)
#define EE   400000
#define NLYR 2
#define OUTC 32
#define NBF  98   // cdiv(NF,512)
#define NBD  40   // cdiv(ND,512)

// ---------------------------------------------------------------------------
// Scratch pool (static device memory; no allocations anywhere)
// Global row convention: rows 0..ND-1 = device nodes, ND..NT-1 = feature nodes.
// ---------------------------------------------------------------------------
constexpr size_t NT128 = (size_t)NT * 128;

constexpr size_t OFF_X    = 0;                       // fp32 [NT][128]
constexpr size_t OFF_Q    = OFF_X   + NT128;         // fp32 [NT][128]
constexpr size_t OFF_KTV  = OFF_Q   + NT128;         // half [NT][256]
constexpr size_t OFF_XH   = OFF_KTV + NT128;         // bf16 [NT][128]
constexpr size_t OFF_XL   = OFF_XH  + NT128 / 2;
constexpr size_t OFF_AGH  = OFF_XL  + NT128 / 2;     // bf16 [NT][128]
constexpr size_t OFF_AGL  = OFF_AGH + NT128 / 2;
constexpr size_t OFF_WKE  = OFF_AGL + NT128 / 2;     // 4*16384 fp32
constexpr size_t OFF_WVE  = OFF_WKE + 65536;
constexpr size_t OFF_BKE  = OFF_WVE + 65536;         // 512
constexpr size_t OFF_BVE  = OFF_BKE + 512;
constexpr size_t OFF_HQ   = OFF_BVE + 512;           // bf16 4*16384 = 32768 floats each
constexpr size_t OFF_LQ   = OFF_HQ  + 32768;
constexpr size_t OFF_HK   = OFF_LQ  + 32768;
constexpr size_t OFF_LK   = OFF_HK  + 32768;
constexpr size_t OFF_HV   = OFF_LK  + 32768;
constexpr size_t OFF_LV   = OFF_HV  + 32768;
constexpr size_t OFF_HA   = OFF_LV  + 32768;
constexpr size_t OFF_LA   = OFF_HA  + 32768;
constexpr size_t OFF_HDI  = OFF_LA  + 32768;         // 8192 floats each
constexpr size_t OFF_LDI  = OFF_HDI + 8192;
constexpr size_t OFF_HFI  = OFF_LDI + 8192;
constexpr size_t OFF_LFI  = OFF_HFI + 8192;
constexpr size_t OFF_RPF  = OFF_LFI + 8192;          // NF+1 int
constexpr size_t OFF_RPD  = OFF_RPF + (NF + 1);      // ND+1 int
constexpr size_t OFF_CDF  = OFF_RPD + (ND + 1);      // EE int
constexpr size_t OFF_CFD  = OFF_CDF + EE;            // EE int
constexpr size_t OFF_CNT  = OFF_CFD + EE;            // NT int (F first, then D)
constexpr size_t OFF_CUR  = OFF_CNT + NT;            // NT int
constexpr size_t OFF_BSUM = OFF_CUR + NT;            // 160
constexpr size_t POOL_SZ  = OFF_BSUM + 160;

__device__ __align__(256) float g_pool[POOL_SZ];

// ---------------------------------------------------------------------------
// Helpers
// ---------------------------------------------------------------------------
__device__ __forceinline__ float gelu_exact(float v) {
    return 0.5f * v * (1.0f + erff(v * 0.70710678118654752440f));
}
__device__ __forceinline__ unsigned pack_bf16x2(float a, float b) {
    unsigned r;
    asm("cvt.rn.bf16x2.f32 %0, %1, %2;" : "=r"(r) : "f"(b), "f"(a));
    return r;
}
__device__ __forceinline__ void split_pair(float2 p, unsigned& hi, unsigned& lo) {
    unsigned h = pack_bf16x2(p.x, p.y);
    unsigned hx, hy;
    asm("prmt.b32 %0, 0, %1, 0x5400;" : "=r"(hx) : "r"(h));
    asm("prmt.b32 %0, 0, %1, 0x7600;" : "=r"(hy) : "r"(h));
    float lx = p.x - __uint_as_float(hx);
    float ly = p.y - __uint_as_float(hy);
    lo = pack_bf16x2(lx, ly);
    hi = h;
}
__device__ __forceinline__ void store_split(float v0, float v1, float* X,
                                            __nv_bfloat16* Xh, __nv_bfloat16* Xl,
                                            size_t base) {
    *(float2*)(X + base) = make_float2(v0, v1);
    unsigned h, l;
    split_pair(make_float2(v0, v1), h, l);
    *(unsigned*)(Xh + base) = h;
    *(unsigned*)(Xl + base) = l;
}

#define MMA_BF16(d, a, b0v, b1v)                                              \
    asm volatile(                                                             \
        "mma.sync.aligned.m16n8k16.row.col.f32.bf16.bf16.f32 "                \
        "{%0,%1,%2,%3},{%4,%5,%6,%7},{%8,%9},{%0,%1,%2,%3};"                  \
        : "+f"((d)[0]), "+f"((d)[1]), "+f"((d)[2]), "+f"((d)[3])              \
        : "r"((a)[0]), "r"((a)[1]), "r"((a)[2]), "r"((a)[3]),                 \
          "r"(b0v), "r"(b1v))

__device__ __forceinline__ void cp16(unsigned dst, const void* src, bool pred) {
    if (pred)
        asm volatile("cp.async.cg.shared.global [%0], [%1], 16;"
                     :: "r"(dst), "l"(src));
}
__device__ __forceinline__ unsigned cvta(const void* p) {
    return (unsigned)__cvta_generic_to_shared(p);
}

// ---------------------------------------------------------------------------
// GEMM argument bundle
// ---------------------------------------------------------------------------
struct GArgs {
    const float* AfD; const float* AfF;               // APATH0 A (per side)
    const __nv_bfloat16* Ah; const __nv_bfloat16* Al; // APATH1 A (global rows)
    const __nv_bfloat16 *H0, *L0, *H1, *L1, *H2, *L2; // weight family bases
    const float *b0, *b1, *b2;                        // bias bases
    float* Q; __half* KTV;                            // MODE0 outputs
    float* X; __nv_bfloat16 *Xh, *Xl;                 // MODE1/2 outputs
    const float *skipv, *lng, *lnb;                   // MODE2
    int layer, blkD;
};

// ---------------------------------------------------------------------------
// Tensor-core GEMM, bf16-split, merged D/F sides (side = blockIdx.x >= blkD).
//   MODE 0 (APATH1): 2-TERM split (ahi*bh + ahi*bl; A truncated to bf16).
//                    y=0 -> fp32 Q; y=1 -> fp16 kt into KTV; y=2 -> fp16 vt
//   MODE 1 (APATH0): 3-term. relu(A@W+b) -> X fp32 + Xh/Xl bf16
//   MODE 2 (APATH1): 3-term. X = LN(X + sk*(A@W+b) + (1-sk)X) -> X + Xh/Xl
// 128x128 tile, BK=16, 8 warps, cp.async double buffer.
// ---------------------------------------------------------------------------
template <int MODE, int APATH>
__global__ void __launch_bounds__(256)
gemm_tc(GArgs a) {
    constexpr bool TWO_TERM = (MODE == 0);   // MODE0 drops the alo term

    const int bx = blockIdx.x;
    const bool isF = bx >= a.blkD;
    const int lbx = isF ? bx - a.blkD : bx;
    const int combo = a.layer * 2 + (isF ? 1 : 0);

    int aRow0, aN, cOff;
    const float* Af = nullptr;
    if (APATH == 0) {
        aRow0 = lbx * 128;
        aN    = isF ? NF : ND;
        cOff  = isF ? ND : 0;
        Af    = isF ? a.AfF : a.AfD;
    } else {
        aRow0 = isF ? (ND + lbx * 128) : lbx * 128;
        aN    = isF ? NT : ND;
        cOff  = 0;
    }

    const __nv_bfloat16* WH;
    const __nv_bfloat16* WL;
    const float* bias;
    if (MODE == 1) {
        WH = isF ? a.H1 : a.H0;  WL = isF ? a.L1 : a.L0;
        bias = isF ? a.b1 : a.b0;
    } else if (MODE == 0) {
        int fam = blockIdx.y;
        WH = (fam == 0 ? a.H0 : fam == 1 ? a.H1 : a.H2) + (size_t)combo * 16384;
        WL = (fam == 0 ? a.L0 : fam == 1 ? a.L1 : a.L2) + (size_t)combo * 16384;
        bias = (fam == 0 ? a.b0 : fam == 1 ? a.b1 : a.b2) + combo * 128;
    } else {
        WH = a.H0 + (size_t)combo * 16384;
        WL = a.L0 + (size_t)combo * 16384;
        bias = a.b0 + combo * 128;
    }

    constexpr int A_RAW = (APATH == 0) ? (2 * 128 * 20 * 4)
                        : (TWO_TERM ? (2 * 128 * 16 * 2) : (2 * (2 * 128 * 16 * 2)));
    __shared__ __align__(16) unsigned char AsRaw[A_RAW];
    __shared__ __align__(16) __nv_bfloat16 Bh[2][128 * 24];
    __shared__ __align__(16) __nv_bfloat16 Bl[2][128 * 24];
    __shared__ float rs[128], rq[128];

    float* Asf = (float*)AsRaw;                                  // [2][128*20]
    __nv_bfloat16* Ahs = (__nv_bfloat16*)AsRaw;                  // [2][128*16]
    __nv_bfloat16* Als = (__nv_bfloat16*)(AsRaw + (TWO_TERM ? 0 : 2 * 128 * 16 * 2));

    const int tid  = threadIdx.x;
    const int lane = tid & 31, warp = tid >> 5;
    const int g = lane >> 2, c = lane & 3;
    const int m0 = (warp >> 1) * 32, n0 = (warp & 1) * 64;

    auto stage = [&](int buf, int k0) {
        if (APATH == 0) {
#pragma unroll
            for (int i = 0; i < 2; i++) {
                int id = tid + i * 256;
                int r = id >> 2, ch = id & 3;
                cp16(cvta(&Asf[buf * 2560 + r * 20 + ch * 4]),
                     Af + (size_t)(aRow0 + r) * 128 + k0 + ch * 4, aRow0 + r < aN);
            }
        } else {
            int r = tid >> 1, ch = tid & 1;
            bool ok = aRow0 + r < aN;
            cp16(cvta(&Ahs[buf * 2048 + r * 16 + ch * 8]),
                 a.Ah + (size_t)(aRow0 + r) * 128 + k0 + ch * 8, ok);
            if (!TWO_TERM)
                cp16(cvta(&Als[buf * 2048 + r * 16 + ch * 8]),
                     a.Al + (size_t)(aRow0 + r) * 128 + k0 + ch * 8, ok);
        }
        int n = tid >> 1, ch = tid & 1;
        cp16(cvta(&Bh[buf][n * 24 + ch * 8]), WH + (size_t)n * 128 + k0 + ch * 8, true);
        cp16(cvta(&Bl[buf][n * 24 + ch * 8]), WL + (size_t)n * 128 + k0 + ch * 8, true);
        asm volatile("cp.async.commit_group;");
    };

    float acc[2][8][4];
#pragma unroll
    for (int mi = 0; mi < 2; mi++)
#pragma unroll
        for (int ni = 0; ni < 8; ni++)
#pragma unroll
            for (int j = 0; j < 4; j++) acc[mi][ni][j] = 0.f;

    stage(0, 0);

    for (int it = 0; it < 8; it++) {
        if (it < 7) {
            stage((it + 1) & 1, (it + 1) * 16);
            asm volatile("cp.async.wait_group 1;");
        } else {
            asm volatile("cp.async.wait_group 0;");
        }
        __syncthreads();

        unsigned ahi[2][4], alo[2][4];
        if (APATH == 0) {
            const float* Ab = &Asf[(it & 1) * 2560];
#pragma unroll
            for (int mi = 0; mi < 2; mi++) {
                int rb = (m0 + mi * 16 + g) * 20;
                split_pair(*(const float2*)&Ab[rb + 2 * c],           ahi[mi][0], alo[mi][0]);
                split_pair(*(const float2*)&Ab[rb + 160 + 2 * c],     ahi[mi][1], alo[mi][1]);
                split_pair(*(const float2*)&Ab[rb + 2 * c + 8],       ahi[mi][2], alo[mi][2]);
                split_pair(*(const float2*)&Ab[rb + 160 + 2 * c + 8], ahi[mi][3], alo[mi][3]);
            }
        } else {
            const __nv_bfloat16* Abh = &Ahs[(it & 1) * 2048];
#pragma unroll
            for (int mi = 0; mi < 2; mi++) {
                int rb = (m0 + mi * 16 + g) * 16;
                ahi[mi][0] = *(const unsigned*)&Abh[rb + 2 * c];
                ahi[mi][1] = *(const unsigned*)&Abh[rb + 128 + 2 * c];
                ahi[mi][2] = *(const unsigned*)&Abh[rb + 2 * c + 8];
                ahi[mi][3] = *(const unsigned*)&Abh[rb + 128 + 2 * c + 8];
            }
            if (!TWO_TERM) {
                const __nv_bfloat16* Abl = &Als[(it & 1) * 2048];
#pragma unroll
                for (int mi = 0; mi < 2; mi++) {
                    int rb = (m0 + mi * 16 + g) * 16;
                    alo[mi][0] = *(const unsigned*)&Abl[rb + 2 * c];
                    alo[mi][1] = *(const unsigned*)&Abl[rb + 128 + 2 * c];
                    alo[mi][2] = *(const unsigned*)&Abl[rb + 2 * c + 8];
                    alo[mi][3] = *(const unsigned*)&Abl[rb + 128 + 2 * c + 8];
                }
            }
        }
        const __nv_bfloat16* Bhh = Bh[it & 1];
        const __nv_bfloat16* Bll = Bl[it & 1];
#pragma unroll
        for (int ni = 0; ni < 8; ni++) {
            int bn = n0 + ni * 8 + g;
            unsigned bh0 = *(const unsigned*)&Bhh[bn * 24 + 2 * c];
            unsigned bh1 = *(const unsigned*)&Bhh[bn * 24 + 2 * c + 8];
            unsigned bl0 = *(const unsigned*)&Bll[bn * 24 + 2 * c];
            unsigned bl1 = *(const unsigned*)&Bll[bn * 24 + 2 * c + 8];
#pragma unroll
            for (int mi = 0; mi < 2; mi++) {
                MMA_BF16(acc[mi][ni], ahi[mi], bh0, bh1);
                MMA_BF16(acc[mi][ni], ahi[mi], bl0, bl1);
                if (!TWO_TERM) MMA_BF16(acc[mi][ni], alo[mi], bh0, bh1);
            }
        }
        __syncthreads();
    }

    if (MODE == 0 && blockIdx.y != 0) {
        // fp16 packed kt/vt epilogue
        const int voff = (blockIdx.y == 2) ? 4 : 0;
#pragma unroll
        for (int ni = 0; ni < 8; ni++) {
            int col = n0 + ni * 8 + 2 * c;
            float bb0 = bias[col], bb1 = bias[col + 1];
            int po = ((col >> 2) << 3) + (col & 3) + voff;
#pragma unroll
            for (int mi = 0; mi < 2; mi++) {
                int ra = aRow0 + m0 + mi * 16 + g;
                if (ra < aN)
                    *(__half2*)(a.KTV + (size_t)ra * 256 + po) =
                        __floats2half2_rn(acc[mi][ni][0] + bb0, acc[mi][ni][1] + bb1);
                if (ra + 8 < aN)
                    *(__half2*)(a.KTV + (size_t)(ra + 8) * 256 + po) =
                        __floats2half2_rn(acc[mi][ni][2] + bb0, acc[mi][ni][3] + bb1);
            }
        }
    } else if (MODE == 0) {
        // fp32 q epilogue
#pragma unroll
        for (int ni = 0; ni < 8; ni++) {
            int col = n0 + ni * 8 + 2 * c;
            float bb0 = bias[col], bb1 = bias[col + 1];
#pragma unroll
            for (int mi = 0; mi < 2; mi++) {
                int ra = aRow0 + m0 + mi * 16 + g;
                if (ra < aN)
                    *(float2*)(a.Q + (size_t)ra * 128 + col) =
                        make_float2(acc[mi][ni][0] + bb0, acc[mi][ni][1] + bb1);
                if (ra + 8 < aN)
                    *(float2*)(a.Q + (size_t)(ra + 8) * 128 + col) =
                        make_float2(acc[mi][ni][2] + bb0, acc[mi][ni][3] + bb1);
            }
        }
    } else if (MODE == 1) {
        // relu -> X + Xh/Xl
#pragma unroll
        for (int ni = 0; ni < 8; ni++) {
            int col = n0 + ni * 8 + 2 * c;
            float bb0 = bias[col], bb1 = bias[col + 1];
#pragma unroll
            for (int mi = 0; mi < 2; mi++) {
                int ra = aRow0 + m0 + mi * 16 + g;
                if (ra < aN) {
                    float v0 = fmaxf(acc[mi][ni][0] + bb0, 0.f);
                    float v1 = fmaxf(acc[mi][ni][1] + bb1, 0.f);
                    store_split(v0, v1, a.X, a.Xh, a.Xl, (size_t)(ra + cOff) * 128 + col);
                }
                if (ra + 8 < aN) {
                    float v2 = fmaxf(acc[mi][ni][2] + bb0, 0.f);
                    float v3 = fmaxf(acc[mi][ni][3] + bb1, 0.f);
                    store_split(v2, v3, a.X, a.Xh, a.Xl, (size_t)(ra + 8 + cOff) * 128 + col);
                }
            }
        }
    } else {
        // MODE 2: fused skip + residual + LayerNorm (in-place on X, global rows)
        float sk = 1.f / (1.f + __expf(-a.skipv[combo]));
        float tms = 2.f - sk;
        const float* lng = a.lng + combo * 128;
        const float* lnb = a.lnb + combo * 128;
        if (tid < 128) { rs[tid] = 0.f; rq[tid] = 0.f; }
        __syncthreads();

        float psum[2][2] = {{0.f, 0.f}, {0.f, 0.f}};
        float psq[2][2]  = {{0.f, 0.f}, {0.f, 0.f}};
#pragma unroll
        for (int ni = 0; ni < 8; ni++) {
            int col = n0 + ni * 8 + 2 * c;
            float bb0 = bias[col], bb1 = bias[col + 1];
#pragma unroll
            for (int mi = 0; mi < 2; mi++) {
                int ra = aRow0 + m0 + mi * 16 + g;
                if (ra < aN) {
                    float2 xv = *(float2*)(a.X + (size_t)ra * 128 + col);
                    float y0 = tms * xv.x + sk * (acc[mi][ni][0] + bb0);
                    float y1 = tms * xv.y + sk * (acc[mi][ni][1] + bb1);
                    *(float2*)(a.X + (size_t)ra * 128 + col) = make_float2(y0, y1);
                    psum[mi][0] += y0 + y1;
                    psq[mi][0]  += y0 * y0 + y1 * y1;
                }
                if (ra + 8 < aN) {
                    float2 xv = *(float2*)(a.X + (size_t)(ra + 8) * 128 + col);
                    float y2 = tms * xv.x + sk * (acc[mi][ni][2] + bb0);
                    float y3 = tms * xv.y + sk * (acc[mi][ni][3] + bb1);
                    *(float2*)(a.X + (size_t)(ra + 8) * 128 + col) = make_float2(y2, y3);
                    psum[mi][1] += y2 + y3;
                    psq[mi][1]  += y2 * y2 + y3 * y3;
                }
            }
        }
#pragma unroll
        for (int mi = 0; mi < 2; mi++)
#pragma unroll
            for (int hh = 0; hh < 2; hh++) {
                float s = psum[mi][hh], q = psq[mi][hh];
                s += __shfl_xor_sync(0xffffffffu, s, 1);
                s += __shfl_xor_sync(0xffffffffu, s, 2);
                q += __shfl_xor_sync(0xffffffffu, q, 1);
                q += __shfl_xor_sync(0xffffffffu, q, 2);
                if (c == 0) {
                    int rl = m0 + mi * 16 + g + hh * 8;
                    atomicAdd(&rs[rl], s);
                    atomicAdd(&rq[rl], q);
                }
            }
        __syncthreads();

#pragma unroll
        for (int ni = 0; ni < 8; ni++) {
            int col = n0 + ni * 8 + 2 * c;
            float g0 = lng[col], g1 = lng[col + 1];
            float h0 = lnb[col], h1 = lnb[col + 1];
#pragma unroll
            for (int mi = 0; mi < 2; mi++) {
#pragma unroll
                for (int hh = 0; hh < 2; hh++) {
                    int rl = m0 + mi * 16 + g + hh * 8;
                    int ra = aRow0 + rl;
                    if (ra < aN) {
                        float mean = rs[rl] * (1.f / 128.f);
                        float var  = rq[rl] * (1.f / 128.f) - mean * mean;
                        float rstd = rsqrtf(var + 1e-5f);
                        float2 yv = *(float2*)(a.X + (size_t)ra * 128 + col);
                        float o0 = (yv.x - mean) * rstd * g0 + h0;
                        float o1 = (yv.y - mean) * rstd * g1 + h1;
                        store_split(o0, o1, a.X, a.Xh, a.Xl, (size_t)ra * 128 + col);
                    }
                }
            }
        }
    }
}

// ---------------------------------------------------------------------------
// Fold relation transforms into projection weights (and priors into k)
// ---------------------------------------------------------------------------
__global__ void fold_weights(const float* __restrict__ Wk, const float* __restrict__ bk,
                             const float* __restrict__ Wv, const float* __restrict__ bv,
                             const float* __restrict__ a_rel, const float* __restrict__ m_rel,
                             const float* __restrict__ p_rel,
                             float* __restrict__ WkE, float* __restrict__ bkE,
                             float* __restrict__ WvE, float* __restrict__ bvE) {
    int idx = blockIdx.x * blockDim.x + threadIdx.x;
    if (idx >= 4 * 129 * 128) return;
    int combo = idx / (129 * 128);
    int rem   = idx % (129 * 128);
    int r  = rem >> 7;
    int he = rem & 127;
    int h = he >> 4, e = he & 15;
    const float* aa = a_rel + ((size_t)combo * 8 + h) * 256 + e;
    const float* mm = m_rel + ((size_t)combo * 8 + h) * 256 + e;
    float ps = p_rel[combo * 8 + h] * 0.25f;

    const float* kr = (r < 128) ? (Wk + (size_t)combo * 16384 + (size_t)r * 128 + h * 16)
                                : (bk + (size_t)combo * 128 + h * 16);
    const float* vr = (r < 128) ? (Wv + (size_t)combo * 16384 + (size_t)r * 128 + h * 16)
                                : (bv + (size_t)combo * 128 + h * 16);
    float sk = 0.f, sv = 0.f;
#pragma unroll
    for (int d = 0; d < 16; d++) {
        sk += kr[d] * aa[d * 16];
        sv += vr[d] * mm[d * 16];
    }
    sk *= ps;
    if (r < 128) {
        WkE[(size_t)combo * 16384 + (size_t)r * 128 + he] = sk;
        WvE[(size_t)combo * 16384 + (size_t)r * 128 + he] = sv;
    } else {
        bkE[combo * 128 + he] = sk;
        bvE[combo * 128 + he] = sv;
    }
}

// ---------------------------------------------------------------------------
// One-shot pre-split of all 18 weight matrices: fp32 [k][n] -> bf16 hi/lo [n][k]
// ---------------------------------------------------------------------------
__global__ void bsplit_all(const float* __restrict__ Wdev, const float* __restrict__ Wfeat,
                           const float* __restrict__ Wq,  const float* __restrict__ WkE,
                           const float* __restrict__ WvE, const float* __restrict__ Wa,
                           __nv_bfloat16* HDI, __nv_bfloat16* LDI,
                           __nv_bfloat16* HFI, __nv_bfloat16* LFI,
                           __nv_bfloat16* HQ,  __nv_bfloat16* LQ,
                           __nv_bfloat16* HK,  __nv_bfloat16* LK,
                           __nv_bfloat16* HV,  __nv_bfloat16* LV,
                           __nv_bfloat16* HA,  __nv_bfloat16* LA) {
    int i = blockIdx.x * blockDim.x + threadIdx.x;
    if (i >= 18 * 16384) return;
    int mat = i >> 14, rem = i & 16383;
    int n = rem >> 7, k = rem & 127;
    const float* src; __nv_bfloat16 *hi, *lo; size_t off;
    if (mat == 0)      { src = Wdev;  hi = HDI; lo = LDI; off = 0; }
    else if (mat == 1) { src = Wfeat; hi = HFI; lo = LFI; off = 0; }
    else {
        int f = (mat - 2) >> 2, cc = (mat - 2) & 3;
        off = (size_t)cc * 16384;
        src = (f == 0) ? Wq : (f == 1) ? WkE : (f == 2) ? WvE : Wa;
        hi  = (f == 0) ? HQ : (f == 1) ? HK : (f == 2) ? HV : HA;
        lo  = (f == 0) ? LQ : (f == 1) ? LK : (f == 2) ? LV : LA;
    }
    float x = src[off + (size_t)k * 128 + n];
    __nv_bfloat16 h = __float2bfloat16(x);
    hi[off + (size_t)n * 128 + k] = h;
    lo[off + (size_t)n * 128 + k] = __float2bfloat16(x - __bfloat162float(h));
}

// ---------------------------------------------------------------------------
// CSR build (both edge types fused per kernel)
// ---------------------------------------------------------------------------
__global__ void hist2(const int* __restrict__ dstF, const int* __restrict__ dstD,
                      int* __restrict__ cnt) {
    int i = blockIdx.x * blockDim.x + threadIdx.x;
    if (i >= 2 * EE) return;
    if (i < EE) atomicAdd(&cnt[dstF[i]], 1);
    else        atomicAdd(&cnt[NF + dstD[i - EE]], 1);
}

__global__ void bsum2(const int* __restrict__ cnt, int* __restrict__ bsum) {
    __shared__ int sh[512];
    int b = blockIdx.x, t = threadIdx.x;
    const int* arr; int g, lim;
    if (b < NBF) { arr = cnt;      g = b * 512 + t;         lim = NF; }
    else         { arr = cnt + NF; g = (b - NBF) * 512 + t; lim = ND; }
    sh[t] = (g < lim) ? arr[g] : 0;
    __syncthreads();
#pragma unroll
    for (int off = 256; off; off >>= 1) {
        if (t < off) sh[t] += sh[t + off];
        __syncthreads();
    }
    if (t == 0) bsum[b] = sh[0];
}

__global__ void scan2(int* __restrict__ bsum) {
    __shared__ int sh[128];
    int t = threadIdx.x;
    int base = (blockIdx.x == 0) ? 0 : NBF;
    int nb   = (blockIdx.x == 0) ? NBF : NBD;
    int v = (t < nb) ? bsum[base + t] : 0;
    sh[t] = v;
    __syncthreads();
#pragma unroll
    for (int off = 1; off < 128; off <<= 1) {
        int u = (t >= off) ? sh[t - off] : 0;
        __syncthreads();
        sh[t] += u;
        __syncthreads();
    }
    if (t < nb) bsum[base + t] = sh[t] - v;
}

__global__ void rowptr2(const int* __restrict__ cnt, const int* __restrict__ bsum,
                        int* __restrict__ rpf, int* __restrict__ rpd,
                        int* __restrict__ cur) {
    __shared__ int sh[512];
    int b = blockIdx.x, t = threadIdx.x;
    const int* arr; int* rp; int g, lim, curOff;
    if (b < NBF) { arr = cnt;      rp = rpf; g = b * 512 + t;         lim = NF; curOff = 0; }
    else         { arr = cnt + NF; rp = rpd; g = (b - NBF) * 512 + t; lim = ND; curOff = NF; }
    int base = bsum[b];
    int v = (g < lim) ? arr[g] : 0;
    sh[t] = v;
    __syncthreads();
    for (int off = 1; off < 512; off <<= 1) {
        int u = (t >= off) ? sh[t - off] : 0;
        __syncthreads();
        sh[t] += u;
        __syncthreads();
    }
    if (g < lim) { rp[g] = base + sh[t] - v; cur[curOff + g] = 0; }
    if (t == 0 && b == 0)   rpf[NF] = EE;
    if (t == 0 && b == NBF) rpd[ND] = EE;
}

__global__ void fill2(const int* __restrict__ srcF, const int* __restrict__ dstF,
                      const int* __restrict__ srcD, const int* __restrict__ dstD,
                      const int* __restrict__ rpf, const int* __restrict__ rpd,
                      int* __restrict__ cur, int* __restrict__ cdf, int* __restrict__ cfd) {
    int i = blockIdx.x * blockDim.x + threadIdx.x;
    if (i >= 2 * EE) return;
    if (i < EE) {
        int d = dstF[i];
        int pos = rpf[d] + atomicAdd(&cur[d], 1);
        cdf[pos] = srcF[i];
    } else {
        int j = i - EE;
        int d = dstD[j];
        int pos = rpd[d] + atomicAdd(&cur[NF + d], 1);
        cfd[pos] = srcD[j];
    }
}

// ---------------------------------------------------------------------------
// Edge aggregation, both edge types in one launch. One warp per dst node.
// 2-wide edge ILP: two independent dot/shfl/exp chains per loop iteration.
// Writes agg as bf16 hi/lo (pre-split for the MODE2 GEMM).
// ---------------------------------------------------------------------------
__global__ void edge_agg2(const int* __restrict__ rpf, const int* __restrict__ cdf,
                          const int* __restrict__ rpd, const int* __restrict__ cfd,
                          const float* __restrict__ q, const __half* __restrict__ ktv,
                          __nv_bfloat16* __restrict__ aggh, __nv_bfloat16* __restrict__ aggl) {
    int w = (blockIdx.x * blockDim.x + threadIdx.x) >> 5;
    if (w >= NT) return;
    int lane = threadIdx.x & 31;
    bool isF = w < NF;
    int wi = isF ? w : (w - NF);
    int dstRow = isF ? (ND + wi) : wi;
    const int* rp  = isF ? rpf : rpd;
    const int* col = isF ? cdf : cfd;
    int srcBase = isF ? 0 : ND;

    float4 q4 = *(const float4*)(q + (size_t)dstRow * 128 + lane * 4);
    float4 acc = make_float4(0.f, 0.f, 0.f, 0.f);
    float ssum = 0.f;
    int beg = rp[wi], end = rp[wi + 1];
    int n = end - beg;

    auto ldkv = [&](int i) {
        int s = col[beg + i];
        return __ldg((const uint4*)(ktv + (size_t)(srcBase + s) * 256 + lane * 8));
    };
    auto proc = [&](uint4 ld) {
        float2 k01 = __half22float2(*(__half2*)&ld.x);
        float2 k23 = __half22float2(*(__half2*)&ld.y);
        float p = q4.x * k01.x + q4.y * k01.y + q4.z * k23.x + q4.w * k23.y;
        p += __shfl_xor_sync(0xffffffffu, p, 1);
        p += __shfl_xor_sync(0xffffffffu, p, 2);
        float ex = __expf(fminf(p, 80.f));
        float2 v01 = __half22float2(*(__half2*)&ld.z);
        float2 v23 = __half22float2(*(__half2*)&ld.w);
        ssum += ex;
        acc.x += ex * v01.x; acc.y += ex * v01.y;
        acc.z += ex * v23.x; acc.w += ex * v23.y;
    };

    uint4 c0 = {}, c1 = {};
    if (n > 0) c0 = ldkv(0);
    if (n > 1) c1 = ldkv(1);
    for (int i = 0; i < n; i += 2) {
        uint4 p0 = {}, p1 = {};
        if (i + 2 < n) p0 = ldkv(i + 2);
        if (i + 3 < n) p1 = ldkv(i + 3);
        proc(c0);
        if (i + 1 < n) proc(c1);
        c0 = p0; c1 = p1;
    }

    float inv = __frcp_rn(ssum + 1e-16f);
    float g0 = gelu_exact(acc.x * inv);
    float g1 = gelu_exact(acc.y * inv);
    float g2 = gelu_exact(acc.z * inv);
    float g3 = gelu_exact(acc.w * inv);

    size_t base = (size_t)dstRow * 128 + lane * 4;
    unsigned h01, l01, h23, l23;
    split_pair(make_float2(g0, g1), h01, l01);
    split_pair(make_float2(g2, g3), h23, l23);
    *(unsigned*)(aggh + base)     = h01;
    *(unsigned*)(aggh + base + 2) = h23;
    *(unsigned*)(aggl + base)     = l01;
    *(unsigned*)(aggl + base + 2) = l23;
}

// ---------------------------------------------------------------------------
// Output head: out[ND,32] = X[0:ND,128] @ W[128,32] + b
// ---------------------------------------------------------------------------
__global__ void out_gemm(const float* __restrict__ x, const float* __restrict__ W,
                         const float* __restrict__ b, float* __restrict__ out) {
    size_t idx = (size_t)blockIdx.x * blockDim.x + threadIdx.x;
    if (idx >= (size_t)ND * OUTC) return;
    int n = (int)(idx >> 5), cc = (int)(idx & 31);
    const float* xr = x + (size_t)n * 128;
    float s = b[cc];
#pragma unroll 8
    for (int k = 0; k < 128; k++) s += xr[k] * W[k * OUTC + cc];
    out[idx] = s;
}

// ---------------------------------------------------------------------------
// Host orchestration
// ---------------------------------------------------------------------------
static inline int cdiv(long long a, long long b) { return (int)((a + b - 1) / b); }

extern "C" void kernel_launch(void* const* d_in, const int* in_sizes, int n_in,
                              void* d_out, int out_size) {
    (void)in_sizes; (void)n_in; (void)out_size;

    const float* x_device = (const float*)d_in[0];
    const float* x_feature = (const float*)d_in[1];
    const int* e_df_src = (const int*)d_in[2];
    const int* e_df_dst = (const int*)d_in[3];
    const int* e_fd_src = (const int*)d_in[4];
    const int* e_fd_dst = (const int*)d_in[5];
    const float* W_dev_in = (const float*)d_in[6];
    const float* b_dev_in = (const float*)d_in[7];
    const float* W_feat_in = (const float*)d_in[8];
    const float* b_feat_in = (const float*)d_in[9];
    const float* Wk = (const float*)d_in[10];
    const float* bk = (const float*)d_in[11];
    const float* Wq = (const float*)d_in[12];
    const float* bq = (const float*)d_in[13];
    const float* Wv = (const float*)d_in[14];
    const float* bv = (const float*)d_in[15];
    const float* a_rel = (const float*)d_in[16];
    const float* m_rel = (const float*)d_in[17];
    const float* p_rel = (const float*)d_in[18];
    const float* Wa = (const float*)d_in[19];
    const float* ba = (const float*)d_in[20];
    const float* skip = (const float*)d_in[21];
    const float* ln_g = (const float*)d_in[22];
    const float* ln_b = (const float*)d_in[23];
    const float* W_out = (const float*)d_in[24];
    const float* b_out = (const float*)d_in[25];
    float* out = (float*)d_out;

    float* pool = nullptr;
    cudaGetSymbolAddress((void**)&pool, g_pool);

    float* X   = pool + OFF_X;
    float* Q   = pool + OFF_Q;
    __half* KTV = (__half*)(pool + OFF_KTV);
    __nv_bfloat16* Xh  = (__nv_bfloat16*)(pool + OFF_XH);
    __nv_bfloat16* Xl  = (__nv_bfloat16*)(pool + OFF_XL);
    __nv_bfloat16* AGH = (__nv_bfloat16*)(pool + OFF_AGH);
    __nv_bfloat16* AGL = (__nv_bfloat16*)(pool + OFF_AGL);
    float* WkE = pool + OFF_WKE;  float* WvE = pool + OFF_WVE;
    float* bkE = pool + OFF_BKE;  float* bvE = pool + OFF_BVE;
    __nv_bfloat16* HQ = (__nv_bfloat16*)(pool + OFF_HQ);
    __nv_bfloat16* LQ = (__nv_bfloat16*)(pool + OFF_LQ);
    __nv_bfloat16* HK = (__nv_bfloat16*)(pool + OFF_HK);
    __nv_bfloat16* LK = (__nv_bfloat16*)(pool + OFF_LK);
    __nv_bfloat16* HV = (__nv_bfloat16*)(pool + OFF_HV);
    __nv_bfloat16* LV = (__nv_bfloat16*)(pool + OFF_LV);
    __nv_bfloat16* HA = (__nv_bfloat16*)(pool + OFF_HA);
    __nv_bfloat16* LA = (__nv_bfloat16*)(pool + OFF_LA);
    __nv_bfloat16* HDI = (__nv_bfloat16*)(pool + OFF_HDI);
    __nv_bfloat16* LDI = (__nv_bfloat16*)(pool + OFF_LDI);
    __nv_bfloat16* HFI = (__nv_bfloat16*)(pool + OFF_HFI);
    __nv_bfloat16* LFI = (__nv_bfloat16*)(pool + OFF_LFI);
    int* rpf = (int*)(pool + OFF_RPF);
    int* rpd = (int*)(pool + OFF_RPD);
    int* cdf = (int*)(pool + OFF_CDF);
    int* cfd = (int*)(pool + OFF_CFD);
    int* cnt = (int*)(pool + OFF_CNT);
    int* cur = (int*)(pool + OFF_CUR);
    int* bsum = (int*)(pool + OFF_BSUM);

    const int gBlkD = cdiv(ND, 128), gBlkF = cdiv(NF, 128);
    const int gBlk = gBlkD + gBlkF;

    // ---- CSR build (both edge types) ----
    cudaMemsetAsync(cnt, 0, NT * sizeof(int), 0);
    hist2<<<cdiv(2 * EE, 256), 256>>>(e_df_dst, e_fd_dst, cnt);
    bsum2<<<NBF + NBD, 512>>>(cnt, bsum);
    scan2<<<2, 128>>>(bsum);
    rowptr2<<<NBF + NBD, 512>>>(cnt, bsum, rpf, rpd, cur);
    fill2<<<cdiv(2 * EE, 256), 256>>>(e_df_src, e_df_dst, e_fd_src, e_fd_dst,
                                      rpf, rpd, cur, cdf, cfd);

    // ---- weight prep ----
    fold_weights<<<cdiv(4 * 129 * 128, 256), 256>>>(Wk, bk, Wv, bv, a_rel, m_rel, p_rel,
                                                    WkE, bkE, WvE, bvE);
    bsplit_all<<<cdiv(18 * 16384, 256), 256>>>(W_dev_in, W_feat_in, Wq, WkE, WvE, Wa,
                                               HDI, LDI, HFI, LFI, HQ, LQ, HK, LK,
                                               HV, LV, HA, LA);

    // ---- input projections + ReLU (merged D/F) ----
    {
        GArgs a = {};
        a.AfD = x_device; a.AfF = x_feature;
        a.H0 = HDI; a.L0 = LDI; a.H1 = HFI; a.L1 = LFI;
        a.b0 = b_dev_in; a.b1 = b_feat_in;
        a.X = X; a.Xh = Xh; a.Xl = Xl;
        a.layer = 0; a.blkD = gBlkD;
        gemm_tc<1, 0><<<gBlk, 256>>>(a);
    }

    for (int l = 0; l < NLYR; l++) {
        // fused q / kt / vt projections (merged D/F, gridDim.y = 3, 2-term split)
        {
            GArgs a = {};
            a.Ah = Xh; a.Al = Xl;
            a.H0 = HQ; a.L0 = LQ; a.H1 = HK; a.L1 = LK; a.H2 = HV; a.L2 = LV;
            a.b0 = bq; a.b1 = bkE; a.b2 = bvE;
            a.Q = Q; a.KTV = KTV;
            a.layer = l; a.blkD = gBlkD;
            gemm_tc<0, 1><<<dim3(gBlk, 3), 256>>>(a);
        }
        // edge aggregation (both edge types)
        edge_agg2<<<cdiv((long long)NT * 32, 256), 256>>>(rpf, cdf, rpd, cfd,
                                                          Q, KTV, AGH, AGL);
        // Wa GEMM + fused skip + residual + LayerNorm (merged D/F)
        {
            GArgs a = {};
            a.Ah = AGH; a.Al = AGL;
            a.H0 = HA; a.L0 = LA;
            a.b0 = ba;
            a.X = X; a.Xh = Xh; a.Xl = Xl;
            a.skipv = skip; a.lng = ln_g; a.lnb = ln_b;
            a.layer = l; a.blkD = gBlkD;
            gemm_tc<2, 1><<<gBlk, 256>>>(a);
        }
    }

    out_gemm<<<cdiv((long long)ND * OUTC, 256), 256>>>(X, W_out, b_out, out);
}

// round 11
// speedup vs baseline: 3.3115x; 1.0255x over previous
#include <cuda_runtime.h>
#include <cuda_bf16.h>
#include <cuda_fp16.h>
#include <math.h>

// ---------------------------------------------------------------------------
// Problem constants
// ---------------------------------------------------------------------------
#define ND   20000
#define NF   50000
#define NT   (ND + NF)
#define EE   400000
#define NLYR 2
#define OUTC 32
#define NBF  98   // cdiv(NF,512)
#define NBD  40   // cdiv(ND,512)

// ---------------------------------------------------------------------------
// Scratch pool (static device memory; no allocations anywhere)
// Global row convention: rows 0..ND-1 = device nodes, ND..NT-1 = feature nodes.
// ---------------------------------------------------------------------------
constexpr size_t NT128 = (size_t)NT * 128;

constexpr size_t OFF_X    = 0;                       // fp32 [NT][128]
constexpr size_t OFF_Q    = OFF_X   + NT128;         // fp32 [NT][128]
constexpr size_t OFF_KTV  = OFF_Q   + NT128;         // half [NT][256]
constexpr size_t OFF_XH   = OFF_KTV + NT128;         // bf16 [NT][128]
constexpr size_t OFF_XL   = OFF_XH  + NT128 / 2;
constexpr size_t OFF_AGH  = OFF_XL  + NT128 / 2;     // bf16 [NT][128]
constexpr size_t OFF_AGL  = OFF_AGH + NT128 / 2;
constexpr size_t OFF_WKE  = OFF_AGL + NT128 / 2;     // 4*16384 fp32
constexpr size_t OFF_WVE  = OFF_WKE + 65536;
constexpr size_t OFF_BKE  = OFF_WVE + 65536;         // 512
constexpr size_t OFF_BVE  = OFF_BKE + 512;
constexpr size_t OFF_HQ   = OFF_BVE + 512;           // bf16 4*16384 = 32768 floats each
constexpr size_t OFF_LQ   = OFF_HQ  + 32768;
constexpr size_t OFF_HK   = OFF_LQ  + 32768;
constexpr size_t OFF_LK   = OFF_HK  + 32768;
constexpr size_t OFF_HV   = OFF_LK  + 32768;
constexpr size_t OFF_LV   = OFF_HV  + 32768;
constexpr size_t OFF_HA   = OFF_LV  + 32768;
constexpr size_t OFF_LA   = OFF_HA  + 32768;
constexpr size_t OFF_HDI  = OFF_LA  + 32768;         // 8192 floats each
constexpr size_t OFF_LDI  = OFF_HDI + 8192;
constexpr size_t OFF_HFI  = OFF_LDI + 8192;
constexpr size_t OFF_LFI  = OFF_HFI + 8192;
constexpr size_t OFF_RPF  = OFF_LFI + 8192;          // NF+1 int
constexpr size_t OFF_RPD  = OFF_RPF + (NF + 1);      // ND+1 int
constexpr size_t OFF_CDF  = OFF_RPD + (ND + 1);      // EE int
constexpr size_t OFF_CFD  = OFF_CDF + EE;            // EE int
constexpr size_t OFF_CNT  = OFF_CFD + EE;            // NT int (F first, then D)
constexpr size_t OFF_CUR  = OFF_CNT + NT;            // NT int
constexpr size_t OFF_BSUM = OFF_CUR + NT;            // 160
constexpr size_t POOL_SZ  = OFF_BSUM + 160;

__device__ __align__(256) float g_pool[POOL_SZ];

// ---------------------------------------------------------------------------
// Helpers
// ---------------------------------------------------------------------------
__device__ __forceinline__ float gelu_exact(float v) {
    return 0.5f * v * (1.0f + erff(v * 0.70710678118654752440f));
}
__device__ __forceinline__ unsigned pack_bf16x2(float a, float b) {
    unsigned r;
    asm("cvt.rn.bf16x2.f32 %0, %1, %2;" : "=r"(r) : "f"(b), "f"(a));
    return r;
}
__device__ __forceinline__ void split_pair(float2 p, unsigned& hi, unsigned& lo) {
    unsigned h = pack_bf16x2(p.x, p.y);
    unsigned hx, hy;
    asm("prmt.b32 %0, 0, %1, 0x5400;" : "=r"(hx) : "r"(h));
    asm("prmt.b32 %0, 0, %1, 0x7600;" : "=r"(hy) : "r"(h));
    float lx = p.x - __uint_as_float(hx);
    float ly = p.y - __uint_as_float(hy);
    lo = pack_bf16x2(lx, ly);
    hi = h;
}
__device__ __forceinline__ void store_split(float v0, float v1, float* X,
                                            __nv_bfloat16* Xh, __nv_bfloat16* Xl,
                                            size_t base) {
    *(float2*)(X + base) = make_float2(v0, v1);
    unsigned h, l;
    split_pair(make_float2(v0, v1), h, l);
    *(unsigned*)(Xh + base) = h;
    *(unsigned*)(Xl + base) = l;
}

#define MMA_BF16(d, a, b0v, b1v)                                              \
    asm volatile(                                                             \
        "mma.sync.aligned.m16n8k16.row.col.f32.bf16.bf16.f32 "                \
        "{%0,%1,%2,%3},{%4,%5,%6,%7},{%8,%9},{%0,%1,%2,%3};"                  \
        : "+f"((d)[0]), "+f"((d)[1]), "+f"((d)[2]), "+f"((d)[3])              \
        : "r"((a)[0]), "r"((a)[1]), "r"((a)[2]), "r"((a)[3]),                 \
          "r"(b0v), "r"(b1v))

__device__ __forceinline__ void cp16(unsigned dst, const void* src, bool pred) {
    if (pred)
        asm volatile("cp.async.cg.shared.global [%0], [%1], 16;"
                     :: "r"(dst), "l"(src));
}
__device__ __forceinline__ unsigned cvta(const void* p) {
    return (unsigned)__cvta_generic_to_shared(p);
}

// ---------------------------------------------------------------------------
// GEMM argument bundle
// ---------------------------------------------------------------------------
struct GArgs {
    const float* AfD; const float* AfF;               // APATH0 A (per side)
    const __nv_bfloat16* Ah; const __nv_bfloat16* Al; // APATH1 A (global rows)
    const __nv_bfloat16 *H0, *L0, *H1, *L1, *H2, *L2; // weight family bases
    const float *b0, *b1, *b2;                        // bias bases
    float* Q; __half* KTV;                            // MODE0 outputs
    float* X; __nv_bfloat16 *Xh, *Xl;                 // MODE1/2 outputs
    const float *skipv, *lng, *lnb;                   // MODE2
    int layer, blkD;
};

// ---------------------------------------------------------------------------
// Tensor-core GEMM, bf16-split, merged D/F sides (side = blockIdx.x >= blkD).
//   MODE 0 (APATH1): 2-TERM split (ahi*bh + ahi*bl; A truncated to bf16).
//                    y=0 -> fp32 Q; y=1 -> fp16 kt into KTV; y=2 -> fp16 vt
//   MODE 1 (APATH0): 3-term. relu(A@W+b) -> X fp32 + Xh/Xl bf16
//   MODE 2 (APATH1): 3-term. X = LN(X + sk*(A@W+b) + (1-sk)X) -> X + Xh/Xl
// 128x128 tile, BK=16, 8 warps, cp.async double buffer.
// ---------------------------------------------------------------------------
template <int MODE, int APATH>
__global__ void __launch_bounds__(256)
gemm_tc(GArgs a) {
    constexpr bool TWO_TERM = (MODE == 0);   // MODE0 drops the alo term

    const int bx = blockIdx.x;
    const bool isF = bx >= a.blkD;
    const int lbx = isF ? bx - a.blkD : bx;
    const int combo = a.layer * 2 + (isF ? 1 : 0);

    int aRow0, aN, cOff;
    const float* Af = nullptr;
    if (APATH == 0) {
        aRow0 = lbx * 128;
        aN    = isF ? NF : ND;
        cOff  = isF ? ND : 0;
        Af    = isF ? a.AfF : a.AfD;
    } else {
        aRow0 = isF ? (ND + lbx * 128) : lbx * 128;
        aN    = isF ? NT : ND;
        cOff  = 0;
    }

    const __nv_bfloat16* WH;
    const __nv_bfloat16* WL;
    const float* bias;
    if (MODE == 1) {
        WH = isF ? a.H1 : a.H0;  WL = isF ? a.L1 : a.L0;
        bias = isF ? a.b1 : a.b0;
    } else if (MODE == 0) {
        int fam = blockIdx.y;
        WH = (fam == 0 ? a.H0 : fam == 1 ? a.H1 : a.H2) + (size_t)combo * 16384;
        WL = (fam == 0 ? a.L0 : fam == 1 ? a.L1 : a.L2) + (size_t)combo * 16384;
        bias = (fam == 0 ? a.b0 : fam == 1 ? a.b1 : a.b2) + combo * 128;
    } else {
        WH = a.H0 + (size_t)combo * 16384;
        WL = a.L0 + (size_t)combo * 16384;
        bias = a.b0 + combo * 128;
    }

    constexpr int A_RAW = (APATH == 0) ? (2 * 128 * 20 * 4)
                        : (TWO_TERM ? (2 * 128 * 16 * 2) : (2 * (2 * 128 * 16 * 2)));
    __shared__ __align__(16) unsigned char AsRaw[A_RAW];
    __shared__ __align__(16) __nv_bfloat16 Bh[2][128 * 24];
    __shared__ __align__(16) __nv_bfloat16 Bl[2][128 * 24];
    __shared__ float rs[128], rq[128];

    float* Asf = (float*)AsRaw;                                  // [2][128*20]
    __nv_bfloat16* Ahs = (__nv_bfloat16*)AsRaw;                  // [2][128*16]
    __nv_bfloat16* Als = (__nv_bfloat16*)(AsRaw + (TWO_TERM ? 0 : 2 * 128 * 16 * 2));

    const int tid  = threadIdx.x;
    const int lane = tid & 31, warp = tid >> 5;
    const int g = lane >> 2, c = lane & 3;
    const int m0 = (warp >> 1) * 32, n0 = (warp & 1) * 64;

    auto stage = [&](int buf, int k0) {
        if (APATH == 0) {
#pragma unroll
            for (int i = 0; i < 2; i++) {
                int id = tid + i * 256;
                int r = id >> 2, ch = id & 3;
                cp16(cvta(&Asf[buf * 2560 + r * 20 + ch * 4]),
                     Af + (size_t)(aRow0 + r) * 128 + k0 + ch * 4, aRow0 + r < aN);
            }
        } else {
            int r = tid >> 1, ch = tid & 1;
            bool ok = aRow0 + r < aN;
            cp16(cvta(&Ahs[buf * 2048 + r * 16 + ch * 8]),
                 a.Ah + (size_t)(aRow0 + r) * 128 + k0 + ch * 8, ok);
            if (!TWO_TERM)
                cp16(cvta(&Als[buf * 2048 + r * 16 + ch * 8]),
                     a.Al + (size_t)(aRow0 + r) * 128 + k0 + ch * 8, ok);
        }
        int n = tid >> 1, ch = tid & 1;
        cp16(cvta(&Bh[buf][n * 24 + ch * 8]), WH + (size_t)n * 128 + k0 + ch * 8, true);
        cp16(cvta(&Bl[buf][n * 24 + ch * 8]), WL + (size_t)n * 128 + k0 + ch * 8, true);
        asm volatile("cp.async.commit_group;");
    };

    float acc[2][8][4];
#pragma unroll
    for (int mi = 0; mi < 2; mi++)
#pragma unroll
        for (int ni = 0; ni < 8; ni++)
#pragma unroll
            for (int j = 0; j < 4; j++) acc[mi][ni][j] = 0.f;

    stage(0, 0);

    for (int it = 0; it < 8; it++) {
        if (it < 7) {
            stage((it + 1) & 1, (it + 1) * 16);
            asm volatile("cp.async.wait_group 1;");
        } else {
            asm volatile("cp.async.wait_group 0;");
        }
        __syncthreads();

        unsigned ahi[2][4], alo[2][4];
        if (APATH == 0) {
            const float* Ab = &Asf[(it & 1) * 2560];
#pragma unroll
            for (int mi = 0; mi < 2; mi++) {
                int rb = (m0 + mi * 16 + g) * 20;
                split_pair(*(const float2*)&Ab[rb + 2 * c],           ahi[mi][0], alo[mi][0]);
                split_pair(*(const float2*)&Ab[rb + 160 + 2 * c],     ahi[mi][1], alo[mi][1]);
                split_pair(*(const float2*)&Ab[rb + 2 * c + 8],       ahi[mi][2], alo[mi][2]);
                split_pair(*(const float2*)&Ab[rb + 160 + 2 * c + 8], ahi[mi][3], alo[mi][3]);
            }
        } else {
            const __nv_bfloat16* Abh = &Ahs[(it & 1) * 2048];
#pragma unroll
            for (int mi = 0; mi < 2; mi++) {
                int rb = (m0 + mi * 16 + g) * 16;
                ahi[mi][0] = *(const unsigned*)&Abh[rb + 2 * c];
                ahi[mi][1] = *(const unsigned*)&Abh[rb + 128 + 2 * c];
                ahi[mi][2] = *(const unsigned*)&Abh[rb + 2 * c + 8];
                ahi[mi][3] = *(const unsigned*)&Abh[rb + 128 + 2 * c + 8];
            }
            if (!TWO_TERM) {
                const __nv_bfloat16* Abl = &Als[(it & 1) * 2048];
#pragma unroll
                for (int mi = 0; mi < 2; mi++) {
                    int rb = (m0 + mi * 16 + g) * 16;
                    alo[mi][0] = *(const unsigned*)&Abl[rb + 2 * c];
                    alo[mi][1] = *(const unsigned*)&Abl[rb + 128 + 2 * c];
                    alo[mi][2] = *(const unsigned*)&Abl[rb + 2 * c + 8];
                    alo[mi][3] = *(const unsigned*)&Abl[rb + 128 + 2 * c + 8];
                }
            }
        }
        const __nv_bfloat16* Bhh = Bh[it & 1];
        const __nv_bfloat16* Bll = Bl[it & 1];
#pragma unroll
        for (int ni = 0; ni < 8; ni++) {
            int bn = n0 + ni * 8 + g;
            unsigned bh0 = *(const unsigned*)&Bhh[bn * 24 + 2 * c];
            unsigned bh1 = *(const unsigned*)&Bhh[bn * 24 + 2 * c + 8];
            unsigned bl0 = *(const unsigned*)&Bll[bn * 24 + 2 * c];
            unsigned bl1 = *(const unsigned*)&Bll[bn * 24 + 2 * c + 8];
#pragma unroll
            for (int mi = 0; mi < 2; mi++) {
                MMA_BF16(acc[mi][ni], ahi[mi], bh0, bh1);
                MMA_BF16(acc[mi][ni], ahi[mi], bl0, bl1);
                if (!TWO_TERM) MMA_BF16(acc[mi][ni], alo[mi], bh0, bh1);
            }
        }
        __syncthreads();
    }

    if (MODE == 0 && blockIdx.y != 0) {
        // fp16 packed kt/vt epilogue
        const int voff = (blockIdx.y == 2) ? 4 : 0;
#pragma unroll
        for (int ni = 0; ni < 8; ni++) {
            int col = n0 + ni * 8 + 2 * c;
            float bb0 = bias[col], bb1 = bias[col + 1];
            int po = ((col >> 2) << 3) + (col & 3) + voff;
#pragma unroll
            for (int mi = 0; mi < 2; mi++) {
                int ra = aRow0 + m0 + mi * 16 + g;
                if (ra < aN)
                    *(__half2*)(a.KTV + (size_t)ra * 256 + po) =
                        __floats2half2_rn(acc[mi][ni][0] + bb0, acc[mi][ni][1] + bb1);
                if (ra + 8 < aN)
                    *(__half2*)(a.KTV + (size_t)(ra + 8) * 256 + po) =
                        __floats2half2_rn(acc[mi][ni][2] + bb0, acc[mi][ni][3] + bb1);
            }
        }
    } else if (MODE == 0) {
        // fp32 q epilogue
#pragma unroll
        for (int ni = 0; ni < 8; ni++) {
            int col = n0 + ni * 8 + 2 * c;
            float bb0 = bias[col], bb1 = bias[col + 1];
#pragma unroll
            for (int mi = 0; mi < 2; mi++) {
                int ra = aRow0 + m0 + mi * 16 + g;
                if (ra < aN)
                    *(float2*)(a.Q + (size_t)ra * 128 + col) =
                        make_float2(acc[mi][ni][0] + bb0, acc[mi][ni][1] + bb1);
                if (ra + 8 < aN)
                    *(float2*)(a.Q + (size_t)(ra + 8) * 128 + col) =
                        make_float2(acc[mi][ni][2] + bb0, acc[mi][ni][3] + bb1);
            }
        }
    } else if (MODE == 1) {
        // relu -> X + Xh/Xl
#pragma unroll
        for (int ni = 0; ni < 8; ni++) {
            int col = n0 + ni * 8 + 2 * c;
            float bb0 = bias[col], bb1 = bias[col + 1];
#pragma unroll
            for (int mi = 0; mi < 2; mi++) {
                int ra = aRow0 + m0 + mi * 16 + g;
                if (ra < aN) {
                    float v0 = fmaxf(acc[mi][ni][0] + bb0, 0.f);
                    float v1 = fmaxf(acc[mi][ni][1] + bb1, 0.f);
                    store_split(v0, v1, a.X, a.Xh, a.Xl, (size_t)(ra + cOff) * 128 + col);
                }
                if (ra + 8 < aN) {
                    float v2 = fmaxf(acc[mi][ni][2] + bb0, 0.f);
                    float v3 = fmaxf(acc[mi][ni][3] + bb1, 0.f);
                    store_split(v2, v3, a.X, a.Xh, a.Xl, (size_t)(ra + 8 + cOff) * 128 + col);
                }
            }
        }
    } else {
        // MODE 2: fused skip + residual + LayerNorm (in-place on X, global rows)
        float sk = 1.f / (1.f + __expf(-a.skipv[combo]));
        float tms = 2.f - sk;
        const float* lng = a.lng + combo * 128;
        const float* lnb = a.lnb + combo * 128;
        if (tid < 128) { rs[tid] = 0.f; rq[tid] = 0.f; }
        __syncthreads();

        float psum[2][2] = {{0.f, 0.f}, {0.f, 0.f}};
        float psq[2][2]  = {{0.f, 0.f}, {0.f, 0.f}};
#pragma unroll
        for (int ni = 0; ni < 8; ni++) {
            int col = n0 + ni * 8 + 2 * c;
            float bb0 = bias[col], bb1 = bias[col + 1];
#pragma unroll
            for (int mi = 0; mi < 2; mi++) {
                int ra = aRow0 + m0 + mi * 16 + g;
                if (ra < aN) {
                    float2 xv = *(float2*)(a.X + (size_t)ra * 128 + col);
                    float y0 = tms * xv.x + sk * (acc[mi][ni][0] + bb0);
                    float y1 = tms * xv.y + sk * (acc[mi][ni][1] + bb1);
                    *(float2*)(a.X + (size_t)ra * 128 + col) = make_float2(y0, y1);
                    psum[mi][0] += y0 + y1;
                    psq[mi][0]  += y0 * y0 + y1 * y1;
                }
                if (ra + 8 < aN) {
                    float2 xv = *(float2*)(a.X + (size_t)(ra + 8) * 128 + col);
                    float y2 = tms * xv.x + sk * (acc[mi][ni][2] + bb0);
                    float y3 = tms * xv.y + sk * (acc[mi][ni][3] + bb1);
                    *(float2*)(a.X + (size_t)(ra + 8) * 128 + col) = make_float2(y2, y3);
                    psum[mi][1] += y2 + y3;
                    psq[mi][1]  += y2 * y2 + y3 * y3;
                }
            }
        }
#pragma unroll
        for (int mi = 0; mi < 2; mi++)
#pragma unroll
            for (int hh = 0; hh < 2; hh++) {
                float s = psum[mi][hh], q = psq[mi][hh];
                s += __shfl_xor_sync(0xffffffffu, s, 1);
                s += __shfl_xor_sync(0xffffffffu, s, 2);
                q += __shfl_xor_sync(0xffffffffu, q, 1);
                q += __shfl_xor_sync(0xffffffffu, q, 2);
                if (c == 0) {
                    int rl = m0 + mi * 16 + g + hh * 8;
                    atomicAdd(&rs[rl], s);
                    atomicAdd(&rq[rl], q);
                }
            }
        __syncthreads();

#pragma unroll
        for (int ni = 0; ni < 8; ni++) {
            int col = n0 + ni * 8 + 2 * c;
            float g0 = lng[col], g1 = lng[col + 1];
            float h0 = lnb[col], h1 = lnb[col + 1];
#pragma unroll
            for (int mi = 0; mi < 2; mi++) {
#pragma unroll
                for (int hh = 0; hh < 2; hh++) {
                    int rl = m0 + mi * 16 + g + hh * 8;
                    int ra = aRow0 + rl;
                    if (ra < aN) {
                        float mean = rs[rl] * (1.f / 128.f);
                        float var  = rq[rl] * (1.f / 128.f) - mean * mean;
                        float rstd = rsqrtf(var + 1e-5f);
                        float2 yv = *(float2*)(a.X + (size_t)ra * 128 + col);
                        float o0 = (yv.x - mean) * rstd * g0 + h0;
                        float o1 = (yv.y - mean) * rstd * g1 + h1;
                        store_split(o0, o1, a.X, a.Xh, a.Xl, (size_t)ra * 128 + col);
                    }
                }
            }
        }
    }
}

// ---------------------------------------------------------------------------
// Fold relation transforms into projection weights (and priors into k)
// ---------------------------------------------------------------------------
__global__ void fold_weights(const float* __restrict__ Wk, const float* __restrict__ bk,
                             const float* __restrict__ Wv, const float* __restrict__ bv,
                             const float* __restrict__ a_rel, const float* __restrict__ m_rel,
                             const float* __restrict__ p_rel,
                             float* __restrict__ WkE, float* __restrict__ bkE,
                             float* __restrict__ WvE, float* __restrict__ bvE) {
    int idx = blockIdx.x * blockDim.x + threadIdx.x;
    if (idx >= 4 * 129 * 128) return;
    int combo = idx / (129 * 128);
    int rem   = idx % (129 * 128);
    int r  = rem >> 7;
    int he = rem & 127;
    int h = he >> 4, e = he & 15;
    const float* aa = a_rel + ((size_t)combo * 8 + h) * 256 + e;
    const float* mm = m_rel + ((size_t)combo * 8 + h) * 256 + e;
    float ps = p_rel[combo * 8 + h] * 0.25f;

    const float* kr = (r < 128) ? (Wk + (size_t)combo * 16384 + (size_t)r * 128 + h * 16)
                                : (bk + (size_t)combo * 128 + h * 16);
    const float* vr = (r < 128) ? (Wv + (size_t)combo * 16384 + (size_t)r * 128 + h * 16)
                                : (bv + (size_t)combo * 128 + h * 16);
    float sk = 0.f, sv = 0.f;
#pragma unroll
    for (int d = 0; d < 16; d++) {
        sk += kr[d] * aa[d * 16];
        sv += vr[d] * mm[d * 16];
    }
    sk *= ps;
    if (r < 128) {
        WkE[(size_t)combo * 16384 + (size_t)r * 128 + he] = sk;
        WvE[(size_t)combo * 16384 + (size_t)r * 128 + he] = sv;
    } else {
        bkE[combo * 128 + he] = sk;
        bvE[combo * 128 + he] = sv;
    }
}

// ---------------------------------------------------------------------------
// Pre-split input-projection weights (2 mats): fp32 [k][n] -> bf16 hi/lo [n][k]
// ---------------------------------------------------------------------------
__global__ void bsplit_in(const float* __restrict__ Wdev, const float* __restrict__ Wfeat,
                          __nv_bfloat16* HDI, __nv_bfloat16* LDI,
                          __nv_bfloat16* HFI, __nv_bfloat16* LFI) {
    int i = blockIdx.x * blockDim.x + threadIdx.x;
    if (i >= 2 * 16384) return;
    int mat = i >> 14, rem = i & 16383;
    int n = rem >> 7, k = rem & 127;
    const float* src = mat ? Wfeat : Wdev;
    __nv_bfloat16* hi = mat ? HFI : HDI;
    __nv_bfloat16* lo = mat ? LFI : LDI;
    float x = src[(size_t)k * 128 + n];
    __nv_bfloat16 h = __float2bfloat16(x);
    hi[(size_t)n * 128 + k] = h;
    lo[(size_t)n * 128 + k] = __float2bfloat16(x - __bfloat162float(h));
}

// ---------------------------------------------------------------------------
// Pre-split the 16 layer matrices: mats 0-3 Wq, 4-7 WkE, 8-11 WvE, 12-15 Wa
// ---------------------------------------------------------------------------
__global__ void bsplit_rest(const float* __restrict__ Wq,  const float* __restrict__ WkE,
                            const float* __restrict__ WvE, const float* __restrict__ Wa,
                            __nv_bfloat16* HQ,  __nv_bfloat16* LQ,
                            __nv_bfloat16* HK,  __nv_bfloat16* LK,
                            __nv_bfloat16* HV,  __nv_bfloat16* LV,
                            __nv_bfloat16* HA,  __nv_bfloat16* LA) {
    int i = blockIdx.x * blockDim.x + threadIdx.x;
    if (i >= 16 * 16384) return;
    int mat = i >> 14, rem = i & 16383;
    int n = rem >> 7, k = rem & 127;
    int f = mat >> 2, cc = mat & 3;
    size_t off = (size_t)cc * 16384;
    const float* src = (f == 0) ? Wq : (f == 1) ? WkE : (f == 2) ? WvE : Wa;
    __nv_bfloat16* hi = (f == 0) ? HQ : (f == 1) ? HK : (f == 2) ? HV : HA;
    __nv_bfloat16* lo = (f == 0) ? LQ : (f == 1) ? LK : (f == 2) ? LV : LA;
    float x = src[off + (size_t)k * 128 + n];
    __nv_bfloat16 h = __float2bfloat16(x);
    hi[off + (size_t)n * 128 + k] = h;
    lo[off + (size_t)n * 128 + k] = __float2bfloat16(x - __bfloat162float(h));
}

// ---------------------------------------------------------------------------
// CSR build (both edge types fused per kernel)
// ---------------------------------------------------------------------------
__global__ void hist2(const int* __restrict__ dstF, const int* __restrict__ dstD,
                      int* __restrict__ cnt) {
    int i = blockIdx.x * blockDim.x + threadIdx.x;
    if (i >= 2 * EE) return;
    if (i < EE) atomicAdd(&cnt[dstF[i]], 1);
    else        atomicAdd(&cnt[NF + dstD[i - EE]], 1);
}

__global__ void bsum2(const int* __restrict__ cnt, int* __restrict__ bsum) {
    __shared__ int sh[512];
    int b = blockIdx.x, t = threadIdx.x;
    const int* arr; int g, lim;
    if (b < NBF) { arr = cnt;      g = b * 512 + t;         lim = NF; }
    else         { arr = cnt + NF; g = (b - NBF) * 512 + t; lim = ND; }
    sh[t] = (g < lim) ? arr[g] : 0;
    __syncthreads();
#pragma unroll
    for (int off = 256; off; off >>= 1) {
        if (t < off) sh[t] += sh[t + off];
        __syncthreads();
    }
    if (t == 0) bsum[b] = sh[0];
}

__global__ void scan2(int* __restrict__ bsum) {
    __shared__ int sh[128];
    int t = threadIdx.x;
    int base = (blockIdx.x == 0) ? 0 : NBF;
    int nb   = (blockIdx.x == 0) ? NBF : NBD;
    int v = (t < nb) ? bsum[base + t] : 0;
    sh[t] = v;
    __syncthreads();
#pragma unroll
    for (int off = 1; off < 128; off <<= 1) {
        int u = (t >= off) ? sh[t - off] : 0;
        __syncthreads();
        sh[t] += u;
        __syncthreads();
    }
    if (t < nb) bsum[base + t] = sh[t] - v;
}

__global__ void rowptr2(const int* __restrict__ cnt, const int* __restrict__ bsum,
                        int* __restrict__ rpf, int* __restrict__ rpd,
                        int* __restrict__ cur) {
    __shared__ int sh[512];
    int b = blockIdx.x, t = threadIdx.x;
    const int* arr; int* rp; int g, lim, curOff;
    if (b < NBF) { arr = cnt;      rp = rpf; g = b * 512 + t;         lim = NF; curOff = 0; }
    else         { arr = cnt + NF; rp = rpd; g = (b - NBF) * 512 + t; lim = ND; curOff = NF; }
    int base = bsum[b];
    int v = (g < lim) ? arr[g] : 0;
    sh[t] = v;
    __syncthreads();
    for (int off = 1; off < 512; off <<= 1) {
        int u = (t >= off) ? sh[t - off] : 0;
        __syncthreads();
        sh[t] += u;
        __syncthreads();
    }
    if (g < lim) { rp[g] = base + sh[t] - v; cur[curOff + g] = 0; }
    if (t == 0 && b == 0)   rpf[NF] = EE;
    if (t == 0 && b == NBF) rpd[ND] = EE;
}

__global__ void fill2(const int* __restrict__ srcF, const int* __restrict__ dstF,
                      const int* __restrict__ srcD, const int* __restrict__ dstD,
                      const int* __restrict__ rpf, const int* __restrict__ rpd,
                      int* __restrict__ cur, int* __restrict__ cdf, int* __restrict__ cfd) {
    int i = blockIdx.x * blockDim.x + threadIdx.x;
    if (i >= 2 * EE) return;
    if (i < EE) {
        int d = dstF[i];
        int pos = rpf[d] + atomicAdd(&cur[d], 1);
        cdf[pos] = srcF[i];
    } else {
        int j = i - EE;
        int d = dstD[j];
        int pos = rpd[d] + atomicAdd(&cur[NF + d], 1);
        cfd[pos] = srcD[j];
    }
}

// ---------------------------------------------------------------------------
// Edge aggregation, both edge types in one launch. One warp per dst node.
// 2-wide edge ILP. Writes agg as bf16 hi/lo (pre-split for the MODE2 GEMM).
// ---------------------------------------------------------------------------
__global__ void edge_agg2(const int* __restrict__ rpf, const int* __restrict__ cdf,
                          const int* __restrict__ rpd, const int* __restrict__ cfd,
                          const float* __restrict__ q, const __half* __restrict__ ktv,
                          __nv_bfloat16* __restrict__ aggh, __nv_bfloat16* __restrict__ aggl) {
    int w = (blockIdx.x * blockDim.x + threadIdx.x) >> 5;
    if (w >= NT) return;
    int lane = threadIdx.x & 31;
    bool isF = w < NF;
    int wi = isF ? w : (w - NF);
    int dstRow = isF ? (ND + wi) : wi;
    const int* rp  = isF ? rpf : rpd;
    const int* col = isF ? cdf : cfd;
    int srcBase = isF ? 0 : ND;

    float4 q4 = *(const float4*)(q + (size_t)dstRow * 128 + lane * 4);
    float4 acc = make_float4(0.f, 0.f, 0.f, 0.f);
    float ssum = 0.f;
    int beg = rp[wi], end = rp[wi + 1];
    int n = end - beg;

    auto ldkv = [&](int i) {
        int s = col[beg + i];
        return __ldg((const uint4*)(ktv + (size_t)(srcBase + s) * 256 + lane * 8));
    };
    auto proc = [&](uint4 ld) {
        float2 k01 = __half22float2(*(__half2*)&ld.x);
        float2 k23 = __half22float2(*(__half2*)&ld.y);
        float p = q4.x * k01.x + q4.y * k01.y + q4.z * k23.x + q4.w * k23.y;
        p += __shfl_xor_sync(0xffffffffu, p, 1);
        p += __shfl_xor_sync(0xffffffffu, p, 2);
        float ex = __expf(fminf(p, 80.f));
        float2 v01 = __half22float2(*(__half2*)&ld.z);
        float2 v23 = __half22float2(*(__half2*)&ld.w);
        ssum += ex;
        acc.x += ex * v01.x; acc.y += ex * v01.y;
        acc.z += ex * v23.x; acc.w += ex * v23.y;
    };

    uint4 c0 = {}, c1 = {};
    if (n > 0) c0 = ldkv(0);
    if (n > 1) c1 = ldkv(1);
    for (int i = 0; i < n; i += 2) {
        uint4 p0 = {}, p1 = {};
        if (i + 2 < n) p0 = ldkv(i + 2);
        if (i + 3 < n) p1 = ldkv(i + 3);
        proc(c0);
        if (i + 1 < n) proc(c1);
        c0 = p0; c1 = p1;
    }

    float inv = __frcp_rn(ssum + 1e-16f);
    float g0 = gelu_exact(acc.x * inv);
    float g1 = gelu_exact(acc.y * inv);
    float g2 = gelu_exact(acc.z * inv);
    float g3 = gelu_exact(acc.w * inv);

    size_t base = (size_t)dstRow * 128 + lane * 4;
    unsigned h01, l01, h23, l23;
    split_pair(make_float2(g0, g1), h01, l01);
    split_pair(make_float2(g2, g3), h23, l23);
    *(unsigned*)(aggh + base)     = h01;
    *(unsigned*)(aggh + base + 2) = h23;
    *(unsigned*)(aggl + base)     = l01;
    *(unsigned*)(aggl + base + 2) = l23;
}

// ---------------------------------------------------------------------------
// Output head: out[ND,32] = X[0:ND,128] @ W[128,32] + b
// ---------------------------------------------------------------------------
__global__ void out_gemm(const float* __restrict__ x, const float* __restrict__ W,
                         const float* __restrict__ b, float* __restrict__ out) {
    size_t idx = (size_t)blockIdx.x * blockDim.x + threadIdx.x;
    if (idx >= (size_t)ND * OUTC) return;
    int n = (int)(idx >> 5), cc = (int)(idx & 31);
    const float* xr = x + (size_t)n * 128;
    float s = b[cc];
#pragma unroll 8
    for (int k = 0; k < 128; k++) s += xr[k] * W[k * OUTC + cc];
    out[idx] = s;
}

// ---------------------------------------------------------------------------
// Host orchestration. Fork/join: s2 = CSR build, s3 = weight prep.
// Streams/events are created ONCE, on the first (eager, uncaptured) call —
// the harness runs a correctness call before capture, so no resource creation
// happens during capture. Non-blocking streams avoid legacy-stream
// serialization so the forked branches genuinely overlap in the graph.
// ---------------------------------------------------------------------------
static inline int cdiv(long long a, long long b) { return (int)((a + b - 1) / b); }

extern "C" void kernel_launch(void* const* d_in, const int* in_sizes, int n_in,
                              void* d_out, int out_size) {
    (void)in_sizes; (void)n_in; (void)out_size;

    const float* x_device = (const float*)d_in[0];
    const float* x_feature = (const float*)d_in[1];
    const int* e_df_src = (const int*)d_in[2];
    const int* e_df_dst = (const int*)d_in[3];
    const int* e_fd_src = (const int*)d_in[4];
    const int* e_fd_dst = (const int*)d_in[5];
    const float* W_dev_in = (const float*)d_in[6];
    const float* b_dev_in = (const float*)d_in[7];
    const float* W_feat_in = (const float*)d_in[8];
    const float* b_feat_in = (const float*)d_in[9];
    const float* Wk = (const float*)d_in[10];
    const float* bk = (const float*)d_in[11];
    const float* Wq = (const float*)d_in[12];
    const float* bq = (const float*)d_in[13];
    const float* Wv = (const float*)d_in[14];
    const float* bv = (const float*)d_in[15];
    const float* a_rel = (const float*)d_in[16];
    const float* m_rel = (const float*)d_in[17];
    const float* p_rel = (const float*)d_in[18];
    const float* Wa = (const float*)d_in[19];
    const float* ba = (const float*)d_in[20];
    const float* skip = (const float*)d_in[21];
    const float* ln_g = (const float*)d_in[22];
    const float* ln_b = (const float*)d_in[23];
    const float* W_out = (const float*)d_in[24];
    const float* b_out = (const float*)d_in[25];
    float* out = (float*)d_out;

    float* pool = nullptr;
    cudaGetSymbolAddress((void**)&pool, g_pool);

    float* X   = pool + OFF_X;
    float* Q   = pool + OFF_Q;
    __half* KTV = (__half*)(pool + OFF_KTV);
    __nv_bfloat16* Xh  = (__nv_bfloat16*)(pool + OFF_XH);
    __nv_bfloat16* Xl  = (__nv_bfloat16*)(pool + OFF_XL);
    __nv_bfloat16* AGH = (__nv_bfloat16*)(pool + OFF_AGH);
    __nv_bfloat16* AGL = (__nv_bfloat16*)(pool + OFF_AGL);
    float* WkE = pool + OFF_WKE;  float* WvE = pool + OFF_WVE;
    float* bkE = pool + OFF_BKE;  float* bvE = pool + OFF_BVE;
    __nv_bfloat16* HQ = (__nv_bfloat16*)(pool + OFF_HQ);
    __nv_bfloat16* LQ = (__nv_bfloat16*)(pool + OFF_LQ);
    __nv_bfloat16* HK = (__nv_bfloat16*)(pool + OFF_HK);
    __nv_bfloat16* LK = (__nv_bfloat16*)(pool + OFF_LK);
    __nv_bfloat16* HV = (__nv_bfloat16*)(pool + OFF_HV);
    __nv_bfloat16* LV = (__nv_bfloat16*)(pool + OFF_LV);
    __nv_bfloat16* HA = (__nv_bfloat16*)(pool + OFF_HA);
    __nv_bfloat16* LA = (__nv_bfloat16*)(pool + OFF_LA);
    __nv_bfloat16* HDI = (__nv_bfloat16*)(pool + OFF_HDI);
    __nv_bfloat16* LDI = (__nv_bfloat16*)(pool + OFF_LDI);
    __nv_bfloat16* HFI = (__nv_bfloat16*)(pool + OFF_HFI);
    __nv_bfloat16* LFI = (__nv_bfloat16*)(pool + OFF_LFI);
    int* rpf = (int*)(pool + OFF_RPF);
    int* rpd = (int*)(pool + OFF_RPD);
    int* cdf = (int*)(pool + OFF_CDF);
    int* cfd = (int*)(pool + OFF_CFD);
    int* cnt = (int*)(pool + OFF_CNT);
    int* cur = (int*)(pool + OFF_CUR);
    int* bsum = (int*)(pool + OFF_BSUM);

    const int gBlkD = cdiv(ND, 128), gBlkF = cdiv(NF, 128);
    const int gBlk = gBlkD + gBlkF;

    // One-time resource creation (first call is eager per harness contract)
    static cudaStream_t s2 = nullptr, s3 = nullptr;
    static cudaEvent_t evRoot = nullptr, evCsr = nullptr, evW = nullptr;
    if (s2 == nullptr) {
        cudaStreamCreateWithFlags(&s2, cudaStreamNonBlocking);
        cudaStreamCreateWithFlags(&s3, cudaStreamNonBlocking);
        cudaEventCreateWithFlags(&evRoot, cudaEventDisableTiming);
        cudaEventCreateWithFlags(&evCsr, cudaEventDisableTiming);
        cudaEventCreateWithFlags(&evW, cudaEventDisableTiming);
    }

    cudaEventRecord(evRoot, 0);
    cudaStreamWaitEvent(s2, evRoot, 0);
    cudaStreamWaitEvent(s3, evRoot, 0);

    // ---- branch s2: CSR build (both edge types) ----
    cudaMemsetAsync(cnt, 0, NT * sizeof(int), s2);
    hist2<<<cdiv(2 * EE, 256), 256, 0, s2>>>(e_df_dst, e_fd_dst, cnt);
    bsum2<<<NBF + NBD, 512, 0, s2>>>(cnt, bsum);
    scan2<<<2, 128, 0, s2>>>(bsum);
    rowptr2<<<NBF + NBD, 512, 0, s2>>>(cnt, bsum, rpf, rpd, cur);
    fill2<<<cdiv(2 * EE, 256), 256, 0, s2>>>(e_df_src, e_df_dst, e_fd_src, e_fd_dst,
                                             rpf, rpd, cur, cdf, cfd);
    cudaEventRecord(evCsr, s2);

    // ---- branch s3: fold relation transforms + split the 16 layer matrices ----
    fold_weights<<<cdiv(4 * 129 * 128, 256), 256, 0, s3>>>(Wk, bk, Wv, bv,
                                                           a_rel, m_rel, p_rel,
                                                           WkE, bkE, WvE, bvE);
    bsplit_rest<<<cdiv(16 * 16384, 256), 256, 0, s3>>>(Wq, WkE, WvE, Wa,
                                                       HQ, LQ, HK, LK, HV, LV, HA, LA);
    cudaEventRecord(evW, s3);

    // ---- main: input-weight split + input projections + ReLU (merged D/F) ----
    bsplit_in<<<cdiv(2 * 16384, 256), 256>>>(W_dev_in, W_feat_in, HDI, LDI, HFI, LFI);
    {
        GArgs a = {};
        a.AfD = x_device; a.AfF = x_feature;
        a.H0 = HDI; a.L0 = LDI; a.H1 = HFI; a.L1 = LFI;
        a.b0 = b_dev_in; a.b1 = b_feat_in;
        a.X = X; a.Xh = Xh; a.Xl = Xl;
        a.layer = 0; a.blkD = gBlkD;
        gemm_tc<1, 0><<<gBlk, 256>>>(a);
    }

    cudaStreamWaitEvent(0, evW, 0);   // layer weights ready before qkv

    for (int l = 0; l < NLYR; l++) {
        // fused q / kt / vt projections (merged D/F, gridDim.y = 3, 2-term split)
        {
            GArgs a = {};
            a.Ah = Xh; a.Al = Xl;
            a.H0 = HQ; a.L0 = LQ; a.H1 = HK; a.L1 = LK; a.H2 = HV; a.L2 = LV;
            a.b0 = bq; a.b1 = bkE; a.b2 = bvE;
            a.Q = Q; a.KTV = KTV;
            a.layer = l; a.blkD = gBlkD;
            gemm_tc<0, 1><<<dim3(gBlk, 3), 256>>>(a);
        }
        if (l == 0) cudaStreamWaitEvent(0, evCsr, 0);  // CSR ready before first edge pass
        // edge aggregation (both edge types)
        edge_agg2<<<cdiv((long long)NT * 32, 256), 256>>>(rpf, cdf, rpd, cfd,
                                                          Q, KTV, AGH, AGL);
        // Wa GEMM + fused skip + residual + LayerNorm (merged D/F)
        {
            GArgs a = {};
            a.Ah = AGH; a.Al = AGL;
            a.H0 = HA; a.L0 = LA;
            a.b0 = ba;
            a.X = X; a.Xh = Xh; a.Xl = Xl;
            a.skipv = skip; a.lng = ln_g; a.lnb = ln_b;
            a.layer = l; a.blkD = gBlkD;
            gemm_tc<2, 1><<<gBlk, 256>>>(a);
        }
    }

    out_gemm<<<cdiv((long long)ND * OUTC, 256), 256>>>(X, W_out, b_out, out);
}

// round 12
// speedup vs baseline: 3.3158x; 1.0013x over previous
#include <cuda_runtime.h>
#include <cuda_bf16.h>
#include <cuda_fp16.h>
#include <math.h>

// ---------------------------------------------------------------------------
// Problem constants
// ---------------------------------------------------------------------------
#define ND   20000
#define NF   50000
#define NT   (ND + NF)
#define EE   400000
#define NLYR 2
#define OUTC 32
#define NBF  98   // cdiv(NF,512)
#define NBD  40   // cdiv(ND,512)

// ---------------------------------------------------------------------------
// Scratch pool (static device memory; no allocations anywhere)
// Global row convention: rows 0..ND-1 = device nodes, ND..NT-1 = feature nodes.
// ---------------------------------------------------------------------------
constexpr size_t NT128 = (size_t)NT * 128;

constexpr size_t OFF_X    = 0;                       // fp32 [NT][128]
constexpr size_t OFF_Q    = OFF_X   + NT128;         // fp32 [NT][128]
constexpr size_t OFF_KTV  = OFF_Q   + NT128;         // half [NT][256]
constexpr size_t OFF_XH   = OFF_KTV + NT128;         // bf16 [NT][128]
constexpr size_t OFF_XL   = OFF_XH  + NT128 / 2;
constexpr size_t OFF_AGH  = OFF_XL  + NT128 / 2;     // bf16 [NT][128]
constexpr size_t OFF_AGL  = OFF_AGH + NT128 / 2;
constexpr size_t OFF_WKE  = OFF_AGL + NT128 / 2;     // 4*16384 fp32
constexpr size_t OFF_WVE  = OFF_WKE + 65536;
constexpr size_t OFF_BKE  = OFF_WVE + 65536;         // 512
constexpr size_t OFF_BVE  = OFF_BKE + 512;
constexpr size_t OFF_HQ   = OFF_BVE + 512;           // bf16 4*16384 = 32768 floats each
constexpr size_t OFF_LQ   = OFF_HQ  + 32768;
constexpr size_t OFF_HK   = OFF_LQ  + 32768;
constexpr size_t OFF_LK   = OFF_HK  + 32768;
constexpr size_t OFF_HV   = OFF_LK  + 32768;
constexpr size_t OFF_LV   = OFF_HV  + 32768;
constexpr size_t OFF_HA   = OFF_LV  + 32768;
constexpr size_t OFF_LA   = OFF_HA  + 32768;
constexpr size_t OFF_HDI  = OFF_LA  + 32768;         // 8192 floats each
constexpr size_t OFF_LDI  = OFF_HDI + 8192;
constexpr size_t OFF_HFI  = OFF_LDI + 8192;
constexpr size_t OFF_LFI  = OFF_HFI + 8192;
constexpr size_t OFF_RPF  = OFF_LFI + 8192;          // NF+1 int
constexpr size_t OFF_RPD  = OFF_RPF + (NF + 1);      // ND+1 int
constexpr size_t OFF_CDF  = OFF_RPD + (ND + 1);      // EE int
constexpr size_t OFF_CFD  = OFF_CDF + EE;            // EE int
constexpr size_t OFF_CNT  = OFF_CFD + EE;            // NT int (F first, then D)
constexpr size_t OFF_CUR  = OFF_CNT + NT;            // NT int
constexpr size_t OFF_BSUM = OFF_CUR + NT;            // 160
constexpr size_t POOL_SZ  = OFF_BSUM + 160;

__device__ __align__(256) float g_pool[POOL_SZ];

// ---------------------------------------------------------------------------
// Helpers
// ---------------------------------------------------------------------------
__device__ __forceinline__ float gelu_exact(float v) {
    return 0.5f * v * (1.0f + erff(v * 0.70710678118654752440f));
}
__device__ __forceinline__ unsigned pack_bf16x2(float a, float b) {
    unsigned r;
    asm("cvt.rn.bf16x2.f32 %0, %1, %2;" : "=r"(r) : "f"(b), "f"(a));
    return r;
}
__device__ __forceinline__ void split_pair(float2 p, unsigned& hi, unsigned& lo) {
    unsigned h = pack_bf16x2(p.x, p.y);
    unsigned hx, hy;
    asm("prmt.b32 %0, 0, %1, 0x5400;" : "=r"(hx) : "r"(h));
    asm("prmt.b32 %0, 0, %1, 0x7600;" : "=r"(hy) : "r"(h));
    float lx = p.x - __uint_as_float(hx);
    float ly = p.y - __uint_as_float(hy);
    lo = pack_bf16x2(lx, ly);
    hi = h;
}
__device__ __forceinline__ void store_split(float v0, float v1, float* X,
                                            __nv_bfloat16* Xh, __nv_bfloat16* Xl,
                                            size_t base) {
    *(float2*)(X + base) = make_float2(v0, v1);
    unsigned h, l;
    split_pair(make_float2(v0, v1), h, l);
    *(unsigned*)(Xh + base) = h;
    *(unsigned*)(Xl + base) = l;
}

#define MMA_BF16(d, a, b0v, b1v)                                              \
    asm volatile(                                                             \
        "mma.sync.aligned.m16n8k16.row.col.f32.bf16.bf16.f32 "                \
        "{%0,%1,%2,%3},{%4,%5,%6,%7},{%8,%9},{%0,%1,%2,%3};"                  \
        : "+f"((d)[0]), "+f"((d)[1]), "+f"((d)[2]), "+f"((d)[3])              \
        : "r"((a)[0]), "r"((a)[1]), "r"((a)[2]), "r"((a)[3]),                 \
          "r"(b0v), "r"(b1v))

__device__ __forceinline__ void cp16(unsigned dst, const void* src, bool pred) {
    if (pred)
        asm volatile("cp.async.cg.shared.global [%0], [%1], 16;"
                     :: "r"(dst), "l"(src));
}
__device__ __forceinline__ unsigned cvta(const void* p) {
    return (unsigned)__cvta_generic_to_shared(p);
}

// ---------------------------------------------------------------------------
// GEMM argument bundle
// ---------------------------------------------------------------------------
struct GArgs {
    const float* AfD; const float* AfF;               // APATH0 A (per side)
    const __nv_bfloat16* Ah; const __nv_bfloat16* Al; // APATH1 A (global rows)
    const __nv_bfloat16 *H0, *L0, *H1, *L1, *H2, *L2; // weight family bases
    const float *b0, *b1, *b2;                        // bias bases
    float* Q; __half* KTV;                            // MODE0 outputs
    float* X; __nv_bfloat16 *Xh, *Xl;                 // MODE1/2 outputs
    const float *skipv, *lng, *lnb;                   // MODE2
    int layer, blkD;
};

// ---------------------------------------------------------------------------
// Tensor-core GEMM, bf16-split, merged D/F sides (side = blockIdx.x >= blkD).
//   MODE 0 (APATH1): 2-TERM split (ahi*bh + ahi*bl; A truncated to bf16).
//                    y=0 -> fp32 Q; y=1 -> fp16 kt into KTV; y=2 -> fp16 vt
//   MODE 1 (APATH0): 3-term. relu(A@W+b) -> X fp32 + Xh/Xl bf16
//   MODE 2 (APATH1): 3-term. X = LN(X + sk*(A@W+b) + (1-sk)X) -> X + Xh/Xl
// 128x128 tile, BK=16, 8 warps, cp.async double buffer.
// ---------------------------------------------------------------------------
template <int MODE, int APATH>
__global__ void __launch_bounds__(256)
gemm_tc(GArgs a) {
    constexpr bool TWO_TERM = (MODE == 0);   // MODE0 drops the alo term

    const int bx = blockIdx.x;
    const bool isF = bx >= a.blkD;
    const int lbx = isF ? bx - a.blkD : bx;
    const int combo = a.layer * 2 + (isF ? 1 : 0);

    int aRow0, aN, cOff;
    const float* Af = nullptr;
    if (APATH == 0) {
        aRow0 = lbx * 128;
        aN    = isF ? NF : ND;
        cOff  = isF ? ND : 0;
        Af    = isF ? a.AfF : a.AfD;
    } else {
        aRow0 = isF ? (ND + lbx * 128) : lbx * 128;
        aN    = isF ? NT : ND;
        cOff  = 0;
    }

    const __nv_bfloat16* WH;
    const __nv_bfloat16* WL;
    const float* bias;
    if (MODE == 1) {
        WH = isF ? a.H1 : a.H0;  WL = isF ? a.L1 : a.L0;
        bias = isF ? a.b1 : a.b0;
    } else if (MODE == 0) {
        int fam = blockIdx.y;
        WH = (fam == 0 ? a.H0 : fam == 1 ? a.H1 : a.H2) + (size_t)combo * 16384;
        WL = (fam == 0 ? a.L0 : fam == 1 ? a.L1 : a.L2) + (size_t)combo * 16384;
        bias = (fam == 0 ? a.b0 : fam == 1 ? a.b1 : a.b2) + combo * 128;
    } else {
        WH = a.H0 + (size_t)combo * 16384;
        WL = a.L0 + (size_t)combo * 16384;
        bias = a.b0 + combo * 128;
    }

    constexpr int A_RAW = (APATH == 0) ? (2 * 128 * 20 * 4)
                        : (TWO_TERM ? (2 * 128 * 16 * 2) : (2 * (2 * 128 * 16 * 2)));
    __shared__ __align__(16) unsigned char AsRaw[A_RAW];
    __shared__ __align__(16) __nv_bfloat16 Bh[2][128 * 24];
    __shared__ __align__(16) __nv_bfloat16 Bl[2][128 * 24];
    __shared__ float rs[128], rq[128];

    float* Asf = (float*)AsRaw;                                  // [2][128*20]
    __nv_bfloat16* Ahs = (__nv_bfloat16*)AsRaw;                  // [2][128*16]
    __nv_bfloat16* Als = (__nv_bfloat16*)(AsRaw + (TWO_TERM ? 0 : 2 * 128 * 16 * 2));

    const int tid  = threadIdx.x;
    const int lane = tid & 31, warp = tid >> 5;
    const int g = lane >> 2, c = lane & 3;
    const int m0 = (warp >> 1) * 32, n0 = (warp & 1) * 64;

    auto stage = [&](int buf, int k0) {
        if (APATH == 0) {
#pragma unroll
            for (int i = 0; i < 2; i++) {
                int id = tid + i * 256;
                int r = id >> 2, ch = id & 3;
                cp16(cvta(&Asf[buf * 2560 + r * 20 + ch * 4]),
                     Af + (size_t)(aRow0 + r) * 128 + k0 + ch * 4, aRow0 + r < aN);
            }
        } else {
            int r = tid >> 1, ch = tid & 1;
            bool ok = aRow0 + r < aN;
            cp16(cvta(&Ahs[buf * 2048 + r * 16 + ch * 8]),
                 a.Ah + (size_t)(aRow0 + r) * 128 + k0 + ch * 8, ok);
            if (!TWO_TERM)
                cp16(cvta(&Als[buf * 2048 + r * 16 + ch * 8]),
                     a.Al + (size_t)(aRow0 + r) * 128 + k0 + ch * 8, ok);
        }
        int n = tid >> 1, ch = tid & 1;
        cp16(cvta(&Bh[buf][n * 24 + ch * 8]), WH + (size_t)n * 128 + k0 + ch * 8, true);
        cp16(cvta(&Bl[buf][n * 24 + ch * 8]), WL + (size_t)n * 128 + k0 + ch * 8, true);
        asm volatile("cp.async.commit_group;");
    };

    float acc[2][8][4];
#pragma unroll
    for (int mi = 0; mi < 2; mi++)
#pragma unroll
        for (int ni = 0; ni < 8; ni++)
#pragma unroll
            for (int j = 0; j < 4; j++) acc[mi][ni][j] = 0.f;

    stage(0, 0);

    for (int it = 0; it < 8; it++) {
        if (it < 7) {
            stage((it + 1) & 1, (it + 1) * 16);
            asm volatile("cp.async.wait_group 1;");
        } else {
            asm volatile("cp.async.wait_group 0;");
        }
        __syncthreads();

        unsigned ahi[2][4], alo[2][4];
        if (APATH == 0) {
            const float* Ab = &Asf[(it & 1) * 2560];
#pragma unroll
            for (int mi = 0; mi < 2; mi++) {
                int rb = (m0 + mi * 16 + g) * 20;
                split_pair(*(const float2*)&Ab[rb + 2 * c],           ahi[mi][0], alo[mi][0]);
                split_pair(*(const float2*)&Ab[rb + 160 + 2 * c],     ahi[mi][1], alo[mi][1]);
                split_pair(*(const float2*)&Ab[rb + 2 * c + 8],       ahi[mi][2], alo[mi][2]);
                split_pair(*(const float2*)&Ab[rb + 160 + 2 * c + 8], ahi[mi][3], alo[mi][3]);
            }
        } else {
            const __nv_bfloat16* Abh = &Ahs[(it & 1) * 2048];
#pragma unroll
            for (int mi = 0; mi < 2; mi++) {
                int rb = (m0 + mi * 16 + g) * 16;
                ahi[mi][0] = *(const unsigned*)&Abh[rb + 2 * c];
                ahi[mi][1] = *(const unsigned*)&Abh[rb + 128 + 2 * c];
                ahi[mi][2] = *(const unsigned*)&Abh[rb + 2 * c + 8];
                ahi[mi][3] = *(const unsigned*)&Abh[rb + 128 + 2 * c + 8];
            }
            if (!TWO_TERM) {
                const __nv_bfloat16* Abl = &Als[(it & 1) * 2048];
#pragma unroll
                for (int mi = 0; mi < 2; mi++) {
                    int rb = (m0 + mi * 16 + g) * 16;
                    alo[mi][0] = *(const unsigned*)&Abl[rb + 2 * c];
                    alo[mi][1] = *(const unsigned*)&Abl[rb + 128 + 2 * c];
                    alo[mi][2] = *(const unsigned*)&Abl[rb + 2 * c + 8];
                    alo[mi][3] = *(const unsigned*)&Abl[rb + 128 + 2 * c + 8];
                }
            }
        }
        const __nv_bfloat16* Bhh = Bh[it & 1];
        const __nv_bfloat16* Bll = Bl[it & 1];
#pragma unroll
        for (int ni = 0; ni < 8; ni++) {
            int bn = n0 + ni * 8 + g;
            unsigned bh0 = *(const unsigned*)&Bhh[bn * 24 + 2 * c];
            unsigned bh1 = *(const unsigned*)&Bhh[bn * 24 + 2 * c + 8];
            unsigned bl0 = *(const unsigned*)&Bll[bn * 24 + 2 * c];
            unsigned bl1 = *(const unsigned*)&Bll[bn * 24 + 2 * c + 8];
#pragma unroll
            for (int mi = 0; mi < 2; mi++) {
                MMA_BF16(acc[mi][ni], ahi[mi], bh0, bh1);
                MMA_BF16(acc[mi][ni], ahi[mi], bl0, bl1);
                if (!TWO_TERM) MMA_BF16(acc[mi][ni], alo[mi], bh0, bh1);
            }
        }
        __syncthreads();
    }

    if (MODE == 0 && blockIdx.y != 0) {
        // fp16 packed kt/vt epilogue
        const int voff = (blockIdx.y == 2) ? 4 : 0;
#pragma unroll
        for (int ni = 0; ni < 8; ni++) {
            int col = n0 + ni * 8 + 2 * c;
            float bb0 = bias[col], bb1 = bias[col + 1];
            int po = ((col >> 2) << 3) + (col & 3) + voff;
#pragma unroll
            for (int mi = 0; mi < 2; mi++) {
                int ra = aRow0 + m0 + mi * 16 + g;
                if (ra < aN)
                    *(__half2*)(a.KTV + (size_t)ra * 256 + po) =
                        __floats2half2_rn(acc[mi][ni][0] + bb0, acc[mi][ni][1] + bb1);
                if (ra + 8 < aN)
                    *(__half2*)(a.KTV + (size_t)(ra + 8) * 256 + po) =
                        __floats2half2_rn(acc[mi][ni][2] + bb0, acc[mi][ni][3] + bb1);
            }
        }
    } else if (MODE == 0) {
        // fp32 q epilogue
#pragma unroll
        for (int ni = 0; ni < 8; ni++) {
            int col = n0 + ni * 8 + 2 * c;
            float bb0 = bias[col], bb1 = bias[col + 1];
#pragma unroll
            for (int mi = 0; mi < 2; mi++) {
                int ra = aRow0 + m0 + mi * 16 + g;
                if (ra < aN)
                    *(float2*)(a.Q + (size_t)ra * 128 + col) =
                        make_float2(acc[mi][ni][0] + bb0, acc[mi][ni][1] + bb1);
                if (ra + 8 < aN)
                    *(float2*)(a.Q + (size_t)(ra + 8) * 128 + col) =
                        make_float2(acc[mi][ni][2] + bb0, acc[mi][ni][3] + bb1);
            }
        }
    } else if (MODE == 1) {
        // relu -> X + Xh/Xl
#pragma unroll
        for (int ni = 0; ni < 8; ni++) {
            int col = n0 + ni * 8 + 2 * c;
            float bb0 = bias[col], bb1 = bias[col + 1];
#pragma unroll
            for (int mi = 0; mi < 2; mi++) {
                int ra = aRow0 + m0 + mi * 16 + g;
                if (ra < aN) {
                    float v0 = fmaxf(acc[mi][ni][0] + bb0, 0.f);
                    float v1 = fmaxf(acc[mi][ni][1] + bb1, 0.f);
                    store_split(v0, v1, a.X, a.Xh, a.Xl, (size_t)(ra + cOff) * 128 + col);
                }
                if (ra + 8 < aN) {
                    float v2 = fmaxf(acc[mi][ni][2] + bb0, 0.f);
                    float v3 = fmaxf(acc[mi][ni][3] + bb1, 0.f);
                    store_split(v2, v3, a.X, a.Xh, a.Xl, (size_t)(ra + 8 + cOff) * 128 + col);
                }
            }
        }
    } else {
        // MODE 2: fused skip + residual + LayerNorm (in-place on X, global rows)
        float sk = 1.f / (1.f + __expf(-a.skipv[combo]));
        float tms = 2.f - sk;
        const float* lng = a.lng + combo * 128;
        const float* lnb = a.lnb + combo * 128;
        if (tid < 128) { rs[tid] = 0.f; rq[tid] = 0.f; }
        __syncthreads();

        float psum[2][2] = {{0.f, 0.f}, {0.f, 0.f}};
        float psq[2][2]  = {{0.f, 0.f}, {0.f, 0.f}};
#pragma unroll
        for (int ni = 0; ni < 8; ni++) {
            int col = n0 + ni * 8 + 2 * c;
            float bb0 = bias[col], bb1 = bias[col + 1];
#pragma unroll
            for (int mi = 0; mi < 2; mi++) {
                int ra = aRow0 + m0 + mi * 16 + g;
                if (ra < aN) {
                    float2 xv = *(float2*)(a.X + (size_t)ra * 128 + col);
                    float y0 = tms * xv.x + sk * (acc[mi][ni][0] + bb0);
                    float y1 = tms * xv.y + sk * (acc[mi][ni][1] + bb1);
                    *(float2*)(a.X + (size_t)ra * 128 + col) = make_float2(y0, y1);
                    psum[mi][0] += y0 + y1;
                    psq[mi][0]  += y0 * y0 + y1 * y1;
                }
                if (ra + 8 < aN) {
                    float2 xv = *(float2*)(a.X + (size_t)(ra + 8) * 128 + col);
                    float y2 = tms * xv.x + sk * (acc[mi][ni][2] + bb0);
                    float y3 = tms * xv.y + sk * (acc[mi][ni][3] + bb1);
                    *(float2*)(a.X + (size_t)(ra + 8) * 128 + col) = make_float2(y2, y3);
                    psum[mi][1] += y2 + y3;
                    psq[mi][1]  += y2 * y2 + y3 * y3;
                }
            }
        }
#pragma unroll
        for (int mi = 0; mi < 2; mi++)
#pragma unroll
            for (int hh = 0; hh < 2; hh++) {
                float s = psum[mi][hh], q = psq[mi][hh];
                s += __shfl_xor_sync(0xffffffffu, s, 1);
                s += __shfl_xor_sync(0xffffffffu, s, 2);
                q += __shfl_xor_sync(0xffffffffu, q, 1);
                q += __shfl_xor_sync(0xffffffffu, q, 2);
                if (c == 0) {
                    int rl = m0 + mi * 16 + g + hh * 8;
                    atomicAdd(&rs[rl], s);
                    atomicAdd(&rq[rl], q);
                }
            }
        __syncthreads();

#pragma unroll
        for (int ni = 0; ni < 8; ni++) {
            int col = n0 + ni * 8 + 2 * c;
            float g0 = lng[col], g1 = lng[col + 1];
            float h0 = lnb[col], h1 = lnb[col + 1];
#pragma unroll
            for (int mi = 0; mi < 2; mi++) {
#pragma unroll
                for (int hh = 0; hh < 2; hh++) {
                    int rl = m0 + mi * 16 + g + hh * 8;
                    int ra = aRow0 + rl;
                    if (ra < aN) {
                        float mean = rs[rl] * (1.f / 128.f);
                        float var  = rq[rl] * (1.f / 128.f) - mean * mean;
                        float rstd = rsqrtf(var + 1e-5f);
                        float2 yv = *(float2*)(a.X + (size_t)ra * 128 + col);
                        float o0 = (yv.x - mean) * rstd * g0 + h0;
                        float o1 = (yv.y - mean) * rstd * g1 + h1;
                        store_split(o0, o1, a.X, a.Xh, a.Xl, (size_t)ra * 128 + col);
                    }
                }
            }
        }
    }
}

// ---------------------------------------------------------------------------
// Fold relation transforms into projection weights (and priors into k)
// ---------------------------------------------------------------------------
__global__ void fold_weights(const float* __restrict__ Wk, const float* __restrict__ bk,
                             const float* __restrict__ Wv, const float* __restrict__ bv,
                             const float* __restrict__ a_rel, const float* __restrict__ m_rel,
                             const float* __restrict__ p_rel,
                             float* __restrict__ WkE, float* __restrict__ bkE,
                             float* __restrict__ WvE, float* __restrict__ bvE) {
    int idx = blockIdx.x * blockDim.x + threadIdx.x;
    if (idx >= 4 * 129 * 128) return;
    int combo = idx / (129 * 128);
    int rem   = idx % (129 * 128);
    int r  = rem >> 7;
    int he = rem & 127;
    int h = he >> 4, e = he & 15;
    const float* aa = a_rel + ((size_t)combo * 8 + h) * 256 + e;
    const float* mm = m_rel + ((size_t)combo * 8 + h) * 256 + e;
    float ps = p_rel[combo * 8 + h] * 0.25f;

    const float* kr = (r < 128) ? (Wk + (size_t)combo * 16384 + (size_t)r * 128 + h * 16)
                                : (bk + (size_t)combo * 128 + h * 16);
    const float* vr = (r < 128) ? (Wv + (size_t)combo * 16384 + (size_t)r * 128 + h * 16)
                                : (bv + (size_t)combo * 128 + h * 16);
    float sk = 0.f, sv = 0.f;
#pragma unroll
    for (int d = 0; d < 16; d++) {
        sk += kr[d] * aa[d * 16];
        sv += vr[d] * mm[d * 16];
    }
    sk *= ps;
    if (r < 128) {
        WkE[(size_t)combo * 16384 + (size_t)r * 128 + he] = sk;
        WvE[(size_t)combo * 16384 + (size_t)r * 128 + he] = sv;
    } else {
        bkE[combo * 128 + he] = sk;
        bvE[combo * 128 + he] = sv;
    }
}

// ---------------------------------------------------------------------------
// Pre-split input-projection weights (2 mats): fp32 [k][n] -> bf16 hi/lo [n][k]
// ---------------------------------------------------------------------------
__global__ void bsplit_in(const float* __restrict__ Wdev, const float* __restrict__ Wfeat,
                          __nv_bfloat16* HDI, __nv_bfloat16* LDI,
                          __nv_bfloat16* HFI, __nv_bfloat16* LFI) {
    int i = blockIdx.x * blockDim.x + threadIdx.x;
    if (i >= 2 * 16384) return;
    int mat = i >> 14, rem = i & 16383;
    int n = rem >> 7, k = rem & 127;
    const float* src = mat ? Wfeat : Wdev;
    __nv_bfloat16* hi = mat ? HFI : HDI;
    __nv_bfloat16* lo = mat ? LFI : LDI;
    float x = src[(size_t)k * 128 + n];
    __nv_bfloat16 h = __float2bfloat16(x);
    hi[(size_t)n * 128 + k] = h;
    lo[(size_t)n * 128 + k] = __float2bfloat16(x - __bfloat162float(h));
}

// ---------------------------------------------------------------------------
// Pre-split the 16 layer matrices: mats 0-3 Wq, 4-7 WkE, 8-11 WvE, 12-15 Wa
// ---------------------------------------------------------------------------
__global__ void bsplit_rest(const float* __restrict__ Wq,  const float* __restrict__ WkE,
                            const float* __restrict__ WvE, const float* __restrict__ Wa,
                            __nv_bfloat16* HQ,  __nv_bfloat16* LQ,
                            __nv_bfloat16* HK,  __nv_bfloat16* LK,
                            __nv_bfloat16* HV,  __nv_bfloat16* LV,
                            __nv_bfloat16* HA,  __nv_bfloat16* LA) {
    int i = blockIdx.x * blockDim.x + threadIdx.x;
    if (i >= 16 * 16384) return;
    int mat = i >> 14, rem = i & 16383;
    int n = rem >> 7, k = rem & 127;
    int f = mat >> 2, cc = mat & 3;
    size_t off = (size_t)cc * 16384;
    const float* src = (f == 0) ? Wq : (f == 1) ? WkE : (f == 2) ? WvE : Wa;
    __nv_bfloat16* hi = (f == 0) ? HQ : (f == 1) ? HK : (f == 2) ? HV : HA;
    __nv_bfloat16* lo = (f == 0) ? LQ : (f == 1) ? LK : (f == 2) ? LV : LA;
    float x = src[off + (size_t)k * 128 + n];
    __nv_bfloat16 h = __float2bfloat16(x);
    hi[off + (size_t)n * 128 + k] = h;
    lo[off + (size_t)n * 128 + k] = __float2bfloat16(x - __bfloat162float(h));
}

// ---------------------------------------------------------------------------
// CSR build (both edge types fused per kernel)
// ---------------------------------------------------------------------------
__global__ void hist2(const int* __restrict__ dstF, const int* __restrict__ dstD,
                      int* __restrict__ cnt) {
    int i = blockIdx.x * blockDim.x + threadIdx.x;
    if (i >= 2 * EE) return;
    if (i < EE) atomicAdd(&cnt[dstF[i]], 1);
    else        atomicAdd(&cnt[NF + dstD[i - EE]], 1);
}

__global__ void bsum2(const int* __restrict__ cnt, int* __restrict__ bsum) {
    __shared__ int sh[512];
    int b = blockIdx.x, t = threadIdx.x;
    const int* arr; int g, lim;
    if (b < NBF) { arr = cnt;      g = b * 512 + t;         lim = NF; }
    else         { arr = cnt + NF; g = (b - NBF) * 512 + t; lim = ND; }
    sh[t] = (g < lim) ? arr[g] : 0;
    __syncthreads();
#pragma unroll
    for (int off = 256; off; off >>= 1) {
        if (t < off) sh[t] += sh[t + off];
        __syncthreads();
    }
    if (t == 0) bsum[b] = sh[0];
}

__global__ void scan2(int* __restrict__ bsum) {
    __shared__ int sh[128];
    int t = threadIdx.x;
    int base = (blockIdx.x == 0) ? 0 : NBF;
    int nb   = (blockIdx.x == 0) ? NBF : NBD;
    int v = (t < nb) ? bsum[base + t] : 0;
    sh[t] = v;
    __syncthreads();
#pragma unroll
    for (int off = 1; off < 128; off <<= 1) {
        int u = (t >= off) ? sh[t - off] : 0;
        __syncthreads();
        sh[t] += u;
        __syncthreads();
    }
    if (t < nb) bsum[base + t] = sh[t] - v;
}

__global__ void rowptr2(const int* __restrict__ cnt, const int* __restrict__ bsum,
                        int* __restrict__ rpf, int* __restrict__ rpd,
                        int* __restrict__ cur) {
    __shared__ int sh[512];
    int b = blockIdx.x, t = threadIdx.x;
    const int* arr; int* rp; int g, lim, curOff;
    if (b < NBF) { arr = cnt;      rp = rpf; g = b * 512 + t;         lim = NF; curOff = 0; }
    else         { arr = cnt + NF; rp = rpd; g = (b - NBF) * 512 + t; lim = ND; curOff = NF; }
    int base = bsum[b];
    int v = (g < lim) ? arr[g] : 0;
    sh[t] = v;
    __syncthreads();
    for (int off = 1; off < 512; off <<= 1) {
        int u = (t >= off) ? sh[t - off] : 0;
        __syncthreads();
        sh[t] += u;
        __syncthreads();
    }
    if (g < lim) { rp[g] = base + sh[t] - v; cur[curOff + g] = 0; }
    if (t == 0 && b == 0)   rpf[NF] = EE;
    if (t == 0 && b == NBF) rpd[ND] = EE;
}

__global__ void fill2(const int* __restrict__ srcF, const int* __restrict__ dstF,
                      const int* __restrict__ srcD, const int* __restrict__ dstD,
                      const int* __restrict__ rpf, const int* __restrict__ rpd,
                      int* __restrict__ cur, int* __restrict__ cdf, int* __restrict__ cfd) {
    int i = blockIdx.x * blockDim.x + threadIdx.x;
    if (i >= 2 * EE) return;
    if (i < EE) {
        int d = dstF[i];
        int pos = rpf[d] + atomicAdd(&cur[d], 1);
        cdf[pos] = srcF[i];
    } else {
        int j = i - EE;
        int d = dstD[j];
        int pos = rpd[d] + atomicAdd(&cur[NF + d], 1);
        cfd[pos] = srcD[j];
    }
}

// ---------------------------------------------------------------------------
// Edge aggregation, both edge types in one launch. One warp per dst node.
// 2-wide edge ILP. Writes agg as bf16 hi/lo (pre-split for the MODE2 GEMM).
// ---------------------------------------------------------------------------
__global__ void edge_agg2(const int* __restrict__ rpf, const int* __restrict__ cdf,
                          const int* __restrict__ rpd, const int* __restrict__ cfd,
                          const float* __restrict__ q, const __half* __restrict__ ktv,
                          __nv_bfloat16* __restrict__ aggh, __nv_bfloat16* __restrict__ aggl) {
    int w = (blockIdx.x * blockDim.x + threadIdx.x) >> 5;
    if (w >= NT) return;
    int lane = threadIdx.x & 31;
    bool isF = w < NF;
    int wi = isF ? w : (w - NF);
    int dstRow = isF ? (ND + wi) : wi;
    const int* rp  = isF ? rpf : rpd;
    const int* col = isF ? cdf : cfd;
    int srcBase = isF ? 0 : ND;

    float4 q4 = *(const float4*)(q + (size_t)dstRow * 128 + lane * 4);
    float4 acc = make_float4(0.f, 0.f, 0.f, 0.f);
    float ssum = 0.f;
    int beg = rp[wi], end = rp[wi + 1];
    int n = end - beg;

    auto ldkv = [&](int i) {
        int s = col[beg + i];
        return __ldg((const uint4*)(ktv + (size_t)(srcBase + s) * 256 + lane * 8));
    };
    auto proc = [&](uint4 ld) {
        float2 k01 = __half22float2(*(__half2*)&ld.x);
        float2 k23 = __half22float2(*(__half2*)&ld.y);
        float p = q4.x * k01.x + q4.y * k01.y + q4.z * k23.x + q4.w * k23.y;
        p += __shfl_xor_sync(0xffffffffu, p, 1);
        p += __shfl_xor_sync(0xffffffffu, p, 2);
        float ex = __expf(fminf(p, 80.f));
        float2 v01 = __half22float2(*(__half2*)&ld.z);
        float2 v23 = __half22float2(*(__half2*)&ld.w);
        ssum += ex;
        acc.x += ex * v01.x; acc.y += ex * v01.y;
        acc.z += ex * v23.x; acc.w += ex * v23.y;
    };

    uint4 c0 = {}, c1 = {};
    if (n > 0) c0 = ldkv(0);
    if (n > 1) c1 = ldkv(1);
    for (int i = 0; i < n; i += 2) {
        uint4 p0 = {}, p1 = {};
        if (i + 2 < n) p0 = ldkv(i + 2);
        if (i + 3 < n) p1 = ldkv(i + 3);
        proc(c0);
        if (i + 1 < n) proc(c1);
        c0 = p0; c1 = p1;
    }

    float inv = __frcp_rn(ssum + 1e-16f);
    float g0 = gelu_exact(acc.x * inv);
    float g1 = gelu_exact(acc.y * inv);
    float g2 = gelu_exact(acc.z * inv);
    float g3 = gelu_exact(acc.w * inv);

    size_t base = (size_t)dstRow * 128 + lane * 4;
    unsigned h01, l01, h23, l23;
    split_pair(make_float2(g0, g1), h01, l01);
    split_pair(make_float2(g2, g3), h23, l23);
    *(unsigned*)(aggh + base)     = h01;
    *(unsigned*)(aggh + base + 2) = h23;
    *(unsigned*)(aggl + base)     = l01;
    *(unsigned*)(aggl + base + 2) = l23;
}

// ---------------------------------------------------------------------------
// Output head: out[ND,32] = X[0:ND,128] @ W[128,32] + b
// ---------------------------------------------------------------------------
__global__ void out_gemm(const float* __restrict__ x, const float* __restrict__ W,
                         const float* __restrict__ b, float* __restrict__ out) {
    size_t idx = (size_t)blockIdx.x * blockDim.x + threadIdx.x;
    if (idx >= (size_t)ND * OUTC) return;
    int n = (int)(idx >> 5), cc = (int)(idx & 31);
    const float* xr = x + (size_t)n * 128;
    float s = b[cc];
#pragma unroll 8
    for (int k = 0; k < 128; k++) s += xr[k] * W[k * OUTC + cc];
    out[idx] = s;
}

// ---------------------------------------------------------------------------
// Host orchestration. Fork/join: s2 = CSR build, s3 = weight prep.
// Streams/events are created ONCE, on the first (eager, uncaptured) call —
// the harness runs a correctness call before capture, so no resource creation
// happens during capture. Non-blocking streams avoid legacy-stream
// serialization so the forked branches genuinely overlap in the graph.
// ---------------------------------------------------------------------------
static inline int cdiv(long long a, long long b) { return (int)((a + b - 1) / b); }

extern "C" void kernel_launch(void* const* d_in, const int* in_sizes, int n_in,
                              void* d_out, int out_size) {
    (void)in_sizes; (void)n_in; (void)out_size;

    const float* x_device = (const float*)d_in[0];
    const float* x_feature = (const float*)d_in[1];
    const int* e_df_src = (const int*)d_in[2];
    const int* e_df_dst = (const int*)d_in[3];
    const int* e_fd_src = (const int*)d_in[4];
    const int* e_fd_dst = (const int*)d_in[5];
    const float* W_dev_in = (const float*)d_in[6];
    const float* b_dev_in = (const float*)d_in[7];
    const float* W_feat_in = (const float*)d_in[8];
    const float* b_feat_in = (const float*)d_in[9];
    const float* Wk = (const float*)d_in[10];
    const float* bk = (const float*)d_in[11];
    const float* Wq = (const float*)d_in[12];
    const float* bq = (const float*)d_in[13];
    const float* Wv = (const float*)d_in[14];
    const float* bv = (const float*)d_in[15];
    const float* a_rel = (const float*)d_in[16];
    const float* m_rel = (const float*)d_in[17];
    const float* p_rel = (const float*)d_in[18];
    const float* Wa = (const float*)d_in[19];
    const float* ba = (const float*)d_in[20];
    const float* skip = (const float*)d_in[21];
    const float* ln_g = (const float*)d_in[22];
    const float* ln_b = (const float*)d_in[23];
    const float* W_out = (const float*)d_in[24];
    const float* b_out = (const float*)d_in[25];
    float* out = (float*)d_out;

    float* pool = nullptr;
    cudaGetSymbolAddress((void**)&pool, g_pool);

    float* X   = pool + OFF_X;
    float* Q   = pool + OFF_Q;
    __half* KTV = (__half*)(pool + OFF_KTV);
    __nv_bfloat16* Xh  = (__nv_bfloat16*)(pool + OFF_XH);
    __nv_bfloat16* Xl  = (__nv_bfloat16*)(pool + OFF_XL);
    __nv_bfloat16* AGH = (__nv_bfloat16*)(pool + OFF_AGH);
    __nv_bfloat16* AGL = (__nv_bfloat16*)(pool + OFF_AGL);
    float* WkE = pool + OFF_WKE;  float* WvE = pool + OFF_WVE;
    float* bkE = pool + OFF_BKE;  float* bvE = pool + OFF_BVE;
    __nv_bfloat16* HQ = (__nv_bfloat16*)(pool + OFF_HQ);
    __nv_bfloat16* LQ = (__nv_bfloat16*)(pool + OFF_LQ);
    __nv_bfloat16* HK = (__nv_bfloat16*)(pool + OFF_HK);
    __nv_bfloat16* LK = (__nv_bfloat16*)(pool + OFF_LK);
    __nv_bfloat16* HV = (__nv_bfloat16*)(pool + OFF_HV);
    __nv_bfloat16* LV = (__nv_bfloat16*)(pool + OFF_LV);
    __nv_bfloat16* HA = (__nv_bfloat16*)(pool + OFF_HA);
    __nv_bfloat16* LA = (__nv_bfloat16*)(pool + OFF_LA);
    __nv_bfloat16* HDI = (__nv_bfloat16*)(pool + OFF_HDI);
    __nv_bfloat16* LDI = (__nv_bfloat16*)(pool + OFF_LDI);
    __nv_bfloat16* HFI = (__nv_bfloat16*)(pool + OFF_HFI);
    __nv_bfloat16* LFI = (__nv_bfloat16*)(pool + OFF_LFI);
    int* rpf = (int*)(pool + OFF_RPF);
    int* rpd = (int*)(pool + OFF_RPD);
    int* cdf = (int*)(pool + OFF_CDF);
    int* cfd = (int*)(pool + OFF_CFD);
    int* cnt = (int*)(pool + OFF_CNT);
    int* cur = (int*)(pool + OFF_CUR);
    int* bsum = (int*)(pool + OFF_BSUM);

    const int gBlkD = cdiv(ND, 128), gBlkF = cdiv(NF, 128);
    const int gBlk = gBlkD + gBlkF;

    // One-time resource creation (first call is eager per harness contract)
    static cudaStream_t s2 = nullptr, s3 = nullptr;
    static cudaEvent_t evRoot = nullptr, evCsr = nullptr, evW = nullptr;
    if (s2 == nullptr) {
        cudaStreamCreateWithFlags(&s2, cudaStreamNonBlocking);
        cudaStreamCreateWithFlags(&s3, cudaStreamNonBlocking);
        cudaEventCreateWithFlags(&evRoot, cudaEventDisableTiming);
        cudaEventCreateWithFlags(&evCsr, cudaEventDisableTiming);
        cudaEventCreateWithFlags(&evW, cudaEventDisableTiming);
    }

    cudaEventRecord(evRoot, 0);
    cudaStreamWaitEvent(s2, evRoot, 0);
    cudaStreamWaitEvent(s3, evRoot, 0);

    // ---- branch s2: CSR build (both edge types) ----
    cudaMemsetAsync(cnt, 0, NT * sizeof(int), s2);
    hist2<<<cdiv(2 * EE, 256), 256, 0, s2>>>(e_df_dst, e_fd_dst, cnt);
    bsum2<<<NBF + NBD, 512, 0, s2>>>(cnt, bsum);
    scan2<<<2, 128, 0, s2>>>(bsum);
    rowptr2<<<NBF + NBD, 512, 0, s2>>>(cnt, bsum, rpf, rpd, cur);
    fill2<<<cdiv(2 * EE, 256), 256, 0, s2>>>(e_df_src, e_df_dst, e_fd_src, e_fd_dst,
                                             rpf, rpd, cur, cdf, cfd);
    cudaEventRecord(evCsr, s2);

    // ---- branch s3: fold relation transforms + split the 16 layer matrices ----
    fold_weights<<<cdiv(4 * 129 * 128, 256), 256, 0, s3>>>(Wk, bk, Wv, bv,
                                                           a_rel, m_rel, p_rel,
                                                           WkE, bkE, WvE, bvE);
    bsplit_rest<<<cdiv(16 * 16384, 256), 256, 0, s3>>>(Wq, WkE, WvE, Wa,
                                                       HQ, LQ, HK, LK, HV, LV, HA, LA);
    cudaEventRecord(evW, s3);

    // ---- main: input-weight split + input projections + ReLU (merged D/F) ----
    bsplit_in<<<cdiv(2 * 16384, 256), 256>>>(W_dev_in, W_feat_in, HDI, LDI, HFI, LFI);
    {
        GArgs a = {};
        a.AfD = x_device; a.AfF = x_feature;
        a.H0 = HDI; a.L0 = LDI; a.H1 = HFI; a.L1 = LFI;
        a.b0 = b_dev_in; a.b1 = b_feat_in;
        a.X = X; a.Xh = Xh; a.Xl = Xl;
        a.layer = 0; a.blkD = gBlkD;
        gemm_tc<1, 0><<<gBlk, 256>>>(a);
    }

    cudaStreamWaitEvent(0, evW, 0);   // layer weights ready before qkv

    for (int l = 0; l < NLYR; l++) {
        // fused q / kt / vt projections (merged D/F, gridDim.y = 3, 2-term split)
        {
            GArgs a = {};
            a.Ah = Xh; a.Al = Xl;
            a.H0 = HQ; a.L0 = LQ; a.H1 = HK; a.L1 = LK; a.H2 = HV; a.L2 = LV;
            a.b0 = bq; a.b1 = bkE; a.b2 = bvE;
            a.Q = Q; a.KTV = KTV;
            a.layer = l; a.blkD = gBlkD;
            gemm_tc<0, 1><<<dim3(gBlk, 3), 256>>>(a);
        }
        if (l == 0) cudaStreamWaitEvent(0, evCsr, 0);  // CSR ready before first edge pass
        // edge aggregation (both edge types)
        edge_agg2<<<cdiv((long long)NT * 32, 256), 256>>>(rpf, cdf, rpd, cfd,
                                                          Q, KTV, AGH, AGL);
        // Wa GEMM + fused skip + residual + LayerNorm (merged D/F)
        {
            GArgs a = {};
            a.Ah = AGH; a.Al = AGL;
            a.H0 = HA; a.L0 = LA;
            a.b0 = ba;
            a.X = X; a.Xh = Xh; a.Xl = Xl;
            a.skipv = skip; a.lng = ln_g; a.lnb = ln_b;
            a.layer = l; a.blkD = gBlkD;
            gemm_tc<2, 1><<<gBlk, 256>>>(a);
        }
    }

    out_gemm<<<cdiv((long long)ND * OUTC, 256), 256>>>(X, W_out, b_out, out);
}